// round 1
// baseline (speedup 1.0000x reference)
#include <cuda_runtime.h>
#include <cuda_bf16.h>
#include <cstdint>

#define B_SZ 8192
#define D_SZ 512
#define MARGIN 0.1f

#define BM 128
#define BN 128
#define BK 32
#define PADW 20   // smem words per row: 16 data + 4 pad (conflict-free frag loads, 16B-aligned stores)

// ---------------- device scratch (no runtime allocation allowed) ----------------
static __device__ __nv_bfloat16 g_fbf[B_SZ * D_SZ];            // 8 MB bf16 copy of feats
static __device__ float        g_sim[(long long)B_SZ * B_SZ];  // 256 MB sim matrix
static __device__ unsigned     g_minpos[B_SZ];                 // order-encoded float min (pos pairs)
static __device__ unsigned     g_maxneg[B_SZ];                 // order-encoded float max (neg pairs)
static __device__ float        g_enorm_part[512];
static __device__ float        g_end_norm;
static __device__ float        g_rowloss[B_SZ];

// order-preserving float<->uint encoding (monotone: f1<f2 <=> enc(f1)<enc(f2))
__device__ __forceinline__ unsigned fenc(float f) {
    unsigned u = __float_as_uint(f);
    return (u & 0x80000000u) ? ~u : (u | 0x80000000u);
}
__device__ __forceinline__ float fdec(unsigned u) {
    return (u & 0x80000000u) ? __uint_as_float(u ^ 0x80000000u) : __uint_as_float(~u);
}

// exp(x) for tiny |x| (sims ~1e-4): degree-4 Taylor, __expf fallback (never taken here)
__device__ __forceinline__ float expx(float x) {
    float ax = fabsf(x);
    if (ax >= 0.25f) return __expf(x);
    return 1.f + x * (1.f + x * (0.5f + x * (0.16666667f + x * 0.041666667f)));
}

// ---------------- K1: sum of squares partials + fp32 -> bf16 convert ----------------
__global__ __launch_bounds__(256) void k_prep(const float* __restrict__ feats) {
    const int n4 = B_SZ * D_SZ / 4;
    const float4* f4 = reinterpret_cast<const float4*>(feats);
    float s = 0.f;
    for (int i = blockIdx.x * blockDim.x + threadIdx.x; i < n4; i += gridDim.x * blockDim.x) {
        float4 v = f4[i];
        s += v.x * v.x + v.y * v.y + v.z * v.z + v.w * v.w;
        __nv_bfloat162 lo = __floats2bfloat162_rn(v.x, v.y);
        __nv_bfloat162 hi = __floats2bfloat162_rn(v.z, v.w);
        uint2 o;
        o.x = *reinterpret_cast<unsigned*>(&lo);
        o.y = *reinterpret_cast<unsigned*>(&hi);
        reinterpret_cast<uint2*>(g_fbf)[i] = o;
    }
    __shared__ float red[256];
    red[threadIdx.x] = s;
    __syncthreads();
    for (int o = 128; o > 0; o >>= 1) {
        if (threadIdx.x < o) red[threadIdx.x] += red[threadIdx.x + o];
        __syncthreads();
    }
    if (threadIdx.x == 0) g_enorm_part[blockIdx.x] = red[0];
}

// ---------------- K1b: reduce end_norm + init min/max arrays ----------------
__global__ __launch_bounds__(512) void k_reduce_init() {
    __shared__ float red[512];
    red[threadIdx.x] = g_enorm_part[threadIdx.x];
    __syncthreads();
    for (int o = 256; o > 0; o >>= 1) {
        if (threadIdx.x < o) red[threadIdx.x] += red[threadIdx.x + o];
        __syncthreads();
    }
    if (threadIdx.x == 0) g_end_norm = red[0];
    for (int i = threadIdx.x; i < B_SZ; i += 512) {
        g_minpos[i] = 0xFF800000u;   // enc(+inf)
        g_maxneg[i] = 0x007FFFFFu;   // enc(-inf)
    }
}

// ---------------- K2: bf16 MMA GEMM (sim = F F^T / end_norm) + fused row min/max ----------------
__device__ __forceinline__ void mma16816(float* d, const uint32_t* a, const uint32_t* b) {
    asm volatile(
        "mma.sync.aligned.m16n8k16.row.col.f32.bf16.bf16.f32 "
        "{%0,%1,%2,%3}, {%4,%5,%6,%7}, {%8,%9}, {%0,%1,%2,%3};\n"
        : "+f"(d[0]), "+f"(d[1]), "+f"(d[2]), "+f"(d[3])
        : "r"(a[0]), "r"(a[1]), "r"(a[2]), "r"(a[3]), "r"(b[0]), "r"(b[1]));
}
__device__ __forceinline__ void cpa16(uint32_t saddr, const void* g) {
    asm volatile("cp.async.cg.shared.global [%0], [%1], 16;\n" :: "r"(saddr), "l"(g));
}

__global__ __launch_bounds__(256, 2) void k_gemm(const int* __restrict__ labels) {
    __shared__ uint32_t smA[2][BM * PADW];
    __shared__ uint32_t smB[2][BN * PADW];
    __shared__ int slabi[BM];
    __shared__ int slabj[BN];

    const int i0 = blockIdx.y * BM;
    const int j0 = blockIdx.x * BN;
    const int tid = threadIdx.x;
    const int lane = tid & 31;
    const int warp = tid >> 5;
    const int wm = warp >> 2;   // 0..1 : 64-row band
    const int wn = warp & 3;    // 0..3 : 32-col band
    const int r4 = lane >> 2;
    const int cq = lane & 3;

    float acc[4][4][4];
#pragma unroll
    for (int mt = 0; mt < 4; ++mt)
#pragma unroll
        for (int nt = 0; nt < 4; ++nt)
#pragma unroll
            for (int e = 0; e < 4; ++e) acc[mt][nt][e] = 0.f;

    const int NK = D_SZ / BK;  // 16 stages

    // prologue: stage 0
    {
#pragma unroll
        for (int h = 0; h < 2; ++h) {
            int id = tid + h * 256;
            int r = id >> 2, q = id & 3;
            cpa16((uint32_t)__cvta_generic_to_shared(&smA[0][r * PADW + q * 4]),
                  g_fbf + (i0 + r) * D_SZ + q * 8);
            cpa16((uint32_t)__cvta_generic_to_shared(&smB[0][r * PADW + q * 4]),
                  g_fbf + (j0 + r) * D_SZ + q * 8);
        }
        asm volatile("cp.async.commit_group;\n");
    }

    for (int kt = 0; kt < NK; ++kt) {
        const int s = kt & 1;
        if (kt + 1 < NK) {
            const int kbase = (kt + 1) * BK;
#pragma unroll
            for (int h = 0; h < 2; ++h) {
                int id = tid + h * 256;
                int r = id >> 2, q = id & 3;
                cpa16((uint32_t)__cvta_generic_to_shared(&smA[s ^ 1][r * PADW + q * 4]),
                      g_fbf + (i0 + r) * D_SZ + kbase + q * 8);
                cpa16((uint32_t)__cvta_generic_to_shared(&smB[s ^ 1][r * PADW + q * 4]),
                      g_fbf + (j0 + r) * D_SZ + kbase + q * 8);
            }
            asm volatile("cp.async.commit_group;\n");
            asm volatile("cp.async.wait_group 1;\n");
        } else {
            asm volatile("cp.async.wait_group 0;\n");
        }
        __syncthreads();

#pragma unroll
        for (int ks = 0; ks < 2; ++ks) {
            const int ko = ks * 8;
            uint32_t a[4][4], b[4][2];
#pragma unroll
            for (int mt = 0; mt < 4; ++mt) {
                const uint32_t* p = &smA[s][(wm * 64 + mt * 16 + r4) * PADW + ko + cq];
                a[mt][0] = p[0];
                a[mt][1] = p[8 * PADW];
                a[mt][2] = p[4];
                a[mt][3] = p[8 * PADW + 4];
            }
#pragma unroll
            for (int nt = 0; nt < 4; ++nt) {
                const uint32_t* p = &smB[s][(wn * 32 + nt * 8 + r4) * PADW + ko + cq];
                b[nt][0] = p[0];
                b[nt][1] = p[4];
            }
#pragma unroll
            for (int mt = 0; mt < 4; ++mt)
#pragma unroll
                for (int nt = 0; nt < 4; ++nt)
                    mma16816(acc[mt][nt], a[mt], b[nt]);
        }
        __syncthreads();
    }

    // -------- epilogue: scale, store sim, fused per-row min(pos)/max(neg) --------
    if (tid < BM) { slabi[tid] = labels[i0 + tid]; slabj[tid] = labels[j0 + tid]; }
    __syncthreads();

    const float inv = 1.0f / g_end_norm;
    const float ONE_EPS = 1.0f - 1e-5f;
    const float INF = __int_as_float(0x7f800000);

#pragma unroll
    for (int mt = 0; mt < 4; ++mt) {
        const int ri0 = wm * 64 + mt * 16 + r4;
        const int ri1 = ri0 + 8;
        const int gi0 = i0 + ri0, gi1 = i0 + ri1;
        const int li0 = slabi[ri0], li1 = slabi[ri1];
        float mn0 = INF, mn1 = INF, mx0 = -INF, mx1 = -INF;
#pragma unroll
        for (int nt = 0; nt < 4; ++nt) {
            const int rj = wn * 32 + nt * 8 + 2 * cq;
            const int gj = j0 + rj;
            const int lj0 = slabj[rj], lj1 = slabj[rj + 1];
            float s00 = acc[mt][nt][0] * inv, s01 = acc[mt][nt][1] * inv;
            float s10 = acc[mt][nt][2] * inv, s11 = acc[mt][nt][3] * inv;
            *reinterpret_cast<float2*>(&g_sim[(long long)gi0 * B_SZ + gj]) = make_float2(s00, s01);
            *reinterpret_cast<float2*>(&g_sim[(long long)gi1 * B_SZ + gj]) = make_float2(s10, s11);
            if (li0 == lj0) { if (s00 < ONE_EPS) mn0 = fminf(mn0, s00); } else mx0 = fmaxf(mx0, s00);
            if (li0 == lj1) { if (s01 < ONE_EPS) mn0 = fminf(mn0, s01); } else mx0 = fmaxf(mx0, s01);
            if (li1 == lj0) { if (s10 < ONE_EPS) mn1 = fminf(mn1, s10); } else mx1 = fmaxf(mx1, s10);
            if (li1 == lj1) { if (s11 < ONE_EPS) mn1 = fminf(mn1, s11); } else mx1 = fmaxf(mx1, s11);
        }
#pragma unroll
        for (int o = 1; o < 4; o <<= 1) {
            mn0 = fminf(mn0, __shfl_xor_sync(0xffffffffu, mn0, o));
            mn1 = fminf(mn1, __shfl_xor_sync(0xffffffffu, mn1, o));
            mx0 = fmaxf(mx0, __shfl_xor_sync(0xffffffffu, mx0, o));
            mx1 = fmaxf(mx1, __shfl_xor_sync(0xffffffffu, mx1, o));
        }
        if (cq == 0) {
            atomicMin(&g_minpos[gi0], fenc(mn0));
            atomicMin(&g_minpos[gi1], fenc(mn1));
            atomicMax(&g_maxneg[gi0], fenc(mx0));
            atomicMax(&g_maxneg[gi1], fenc(mx1));
        }
    }
}

// ---------------- K3: per-row masked exp-sums -> row loss ----------------
__global__ __launch_bounds__(256) void k_rows(const int* __restrict__ labels) {
    __shared__ int slab[B_SZ];  // all labels, 32 KB
    for (int i = threadIdx.x; i < B_SZ; i += 256) slab[i] = labels[i];
    __syncthreads();

    const int warp = threadIdx.x >> 5, lane = threadIdx.x & 31;
    const int row = blockIdx.x * 8 + warp;
    const int li = slab[row];
    const float minpos = fdec(g_minpos[row]);
    const float maxneg = fdec(g_maxneg[row]);
    const float4* srow = reinterpret_cast<const float4*>(&g_sim[(long long)row * B_SZ]);
    const int4* slab4 = reinterpret_cast<const int4*>(slab);
    const float ONE_EPS = 1.0f - 1e-5f;

    float sp = 0.f, sn = 0.f;
    int ap = 0, an = 0;
    for (int q = lane; q < B_SZ / 4; q += 32) {
        float4 v = srow[q];
        int4 l4 = slab4[q];
        float ss[4] = {v.x, v.y, v.z, v.w};
        int   ll[4] = {l4.x, l4.y, l4.z, l4.w};
#pragma unroll
        for (int e = 0; e < 4; ++e) {
            float s = ss[e];
            bool same = (ll[e] == li);
            bool psel = same && (s < ONE_EPS) && (s - MARGIN < maxneg);
            bool nsel = (!same) && (s + MARGIN > minpos);
            float x = 2.f * s;
            if (psel) { sp += expx(-x); ap = 1; }
            if (nsel) { sn += expx(x);  an = 1; }
        }
    }
#pragma unroll
    for (int o = 16; o > 0; o >>= 1) {
        sp += __shfl_xor_sync(0xffffffffu, sp, o);
        sn += __shfl_xor_sync(0xffffffffu, sn, o);
    }
    ap = __any_sync(0xffffffffu, ap);
    an = __any_sync(0xffffffffu, an);
    if (lane == 0) {
        float loss = 0.f;
        if (ap && an) {
            // exp(-2(s-0.5)) = e * exp(-2s);  exp(2(s-0.5)) = (1/e) * exp(2s)
            const float E = 2.718281828459045f;
            const float EINV = 0.36787944117144233f;
            loss = 0.5f * log1pf(E * sp) + 0.5f * log1pf(EINV * sn);
        }
        g_rowloss[row] = loss;
    }
}

// ---------------- K4: deterministic final reduction ----------------
__global__ __launch_bounds__(256) void k_final(float* __restrict__ out) {
    __shared__ float red[256];
    float s = 0.f;
    for (int i = threadIdx.x; i < B_SZ; i += 256) s += g_rowloss[i];
    red[threadIdx.x] = s;
    __syncthreads();
    for (int o = 128; o > 0; o >>= 1) {
        if (threadIdx.x < o) red[threadIdx.x] += red[threadIdx.x + o];
        __syncthreads();
    }
    if (threadIdx.x == 0) out[0] = red[0] * (1.0f / B_SZ);
}

// ---------------- launch ----------------
extern "C" void kernel_launch(void* const* d_in, const int* in_sizes, int n_in,
                              void* d_out, int out_size) {
    const float* feats = (const float*)d_in[0];
    const int* labels = (const int*)d_in[1];
    (void)in_sizes; (void)n_in; (void)out_size;

    k_prep<<<512, 256>>>(feats);
    k_reduce_init<<<1, 512>>>();
    dim3 grid(B_SZ / BN, B_SZ / BM);
    k_gemm<<<grid, 256>>>(labels);
    k_rows<<<B_SZ / 8, 256>>>(labels);
    k_final<<<1, 256>>>((float*)d_out);
}

// round 3
// speedup vs baseline: 1.7337x; 1.7337x over previous
#include <cuda_runtime.h>
#include <cuda_bf16.h>
#include <cstdint>
#include <cstddef>

#define B_SZ 8192
#define D_SZ 512
#define MARGIN 0.1f

#define BM 128
#define BN 128
#define BK 32
#define PADW 20          // words per smem row: 16 data + 4 pad (conflict-free LDSM)
#define NBLK 64          // 8192/128
#define NTRI 2080        // NBLK*(NBLK+1)/2

// dynamic smem layout (words): mainloop A[2]|B[2] = 10240 words (40KB),
// epilogue tiles (8 warps x 64x33) = 16896 words (67.6KB). Union -> 67584 bytes.
#define SM_A(s)  ((s) * 2560)
#define SM_B(s)  (5120 + (s) * 2560)
#define SMEM_BYTES 67584

// ---------------- device scratch ----------------
static __device__ __nv_bfloat16 g_fbf[B_SZ * D_SZ];          // 8 MB bf16 feats (L2-resident)
static __device__ unsigned     g_sim[(size_t)B_SZ * B_SZ];   // 256 MB sim, 2 LSBs = masks
static __device__ unsigned     g_minpos[B_SZ];
static __device__ unsigned     g_maxneg[B_SZ];
static __device__ float        g_enorm_part[512];
static __device__ float        g_end_norm;
static __device__ float        g_rowloss[B_SZ];

// order-preserving float<->uint encoding
__device__ __forceinline__ unsigned fenc(float f) {
    unsigned u = __float_as_uint(f);
    return (u & 0x80000000u) ? ~u : (u | 0x80000000u);
}
__device__ __forceinline__ float fdec(unsigned u) {
    return (u & 0x80000000u) ? __uint_as_float(u ^ 0x80000000u) : __uint_as_float(~u);
}
// exp for tiny |x| (|x|<=~1e-3 here): Taylor-4; guarded fallback never taken
__device__ __forceinline__ float expx(float x) {
    if (fabsf(x) >= 0.25f) return __expf(x);
    return 1.f + x * (1.f + x * (0.5f + x * (0.16666667f + x * 0.041666667f)));
}

// ---------------- K1: sumsq partials + fp32->bf16 ----------------
__global__ __launch_bounds__(256) void k_prep(const float* __restrict__ feats) {
    const int n4 = B_SZ * D_SZ / 4;
    const float4* f4 = reinterpret_cast<const float4*>(feats);
    float s = 0.f;
    for (int i = blockIdx.x * blockDim.x + threadIdx.x; i < n4; i += gridDim.x * blockDim.x) {
        float4 v = f4[i];
        s += v.x * v.x + v.y * v.y + v.z * v.z + v.w * v.w;
        __nv_bfloat162 lo = __floats2bfloat162_rn(v.x, v.y);
        __nv_bfloat162 hi = __floats2bfloat162_rn(v.z, v.w);
        uint2 o;
        o.x = *reinterpret_cast<unsigned*>(&lo);
        o.y = *reinterpret_cast<unsigned*>(&hi);
        reinterpret_cast<uint2*>(g_fbf)[i] = o;
    }
    __shared__ float red[256];
    red[threadIdx.x] = s;
    __syncthreads();
    for (int o = 128; o > 0; o >>= 1) {
        if (threadIdx.x < o) red[threadIdx.x] += red[threadIdx.x + o];
        __syncthreads();
    }
    if (threadIdx.x == 0) g_enorm_part[blockIdx.x] = red[0];
}

// ---------------- K1b: reduce end_norm + init min/max ----------------
__global__ __launch_bounds__(512) void k_reduce_init() {
    __shared__ float red[512];
    red[threadIdx.x] = g_enorm_part[threadIdx.x];
    __syncthreads();
    for (int o = 256; o > 0; o >>= 1) {
        if (threadIdx.x < o) red[threadIdx.x] += red[threadIdx.x + o];
        __syncthreads();
    }
    if (threadIdx.x == 0) g_end_norm = red[0];
    for (int i = threadIdx.x; i < B_SZ; i += 512) {
        g_minpos[i] = 0xFF800000u;   // enc(+inf)
        g_maxneg[i] = 0x007FFFFFu;   // enc(-inf)
    }
}

// ---------------- GEMM helpers ----------------
__device__ __forceinline__ void mma16816(float* d, const uint32_t* a, const uint32_t* b) {
    asm volatile(
        "mma.sync.aligned.m16n8k16.row.col.f32.bf16.bf16.f32 "
        "{%0,%1,%2,%3}, {%4,%5,%6,%7}, {%8,%9}, {%0,%1,%2,%3};\n"
        : "+f"(d[0]), "+f"(d[1]), "+f"(d[2]), "+f"(d[3])
        : "r"(a[0]), "r"(a[1]), "r"(a[2]), "r"(a[3]), "r"(b[0]), "r"(b[1]));
}
__device__ __forceinline__ void ldsm4(uint32_t* d, uint32_t saddr) {
    asm volatile("ldmatrix.sync.aligned.m8n8.x4.shared.b16 {%0,%1,%2,%3}, [%4];"
                 : "=r"(d[0]), "=r"(d[1]), "=r"(d[2]), "=r"(d[3]) : "r"(saddr));
}
__device__ __forceinline__ void cpa16(uint32_t saddr, const void* g) {
    asm volatile("cp.async.cg.shared.global [%0], [%1], 16;\n" :: "r"(saddr), "l"(g));
}
__device__ __forceinline__ void load_chunk(uint32_t sb, int stage, int kbase,
                                           int i0, int j0, int tid) {
    const int r = tid >> 2, q = tid & 3;
#pragma unroll
    for (int h = 0; h < 2; ++h) {
        int rr = r + h * 64;
        cpa16(sb + (SM_A(stage) + rr * PADW + q * 4) * 4,
              g_fbf + (size_t)(i0 + rr) * D_SZ + kbase + q * 8);
        cpa16(sb + (SM_B(stage) + rr * PADW + q * 4) * 4,
              g_fbf + (size_t)(j0 + rr) * D_SZ + kbase + q * 8);
    }
    asm volatile("cp.async.commit_group;\n" ::: "memory");
}

// ---------------- K2: triangular HMMA GEMM + fused epilogue ----------------
__global__ void __launch_bounds__(256, 2) k_gemm(const int* __restrict__ labels) {
    extern __shared__ uint32_t dsm[];
    const uint32_t sb = (uint32_t)__cvta_generic_to_shared(dsm);
    __shared__ int slabi[BM];
    __shared__ int slabj[BN];

    // ---- triangular block mapping ----
    const int kb = blockIdx.x;
    int bi = (int)(64.5f - sqrtf(64.5f * 64.5f - 2.0f * (float)kb));
    if (bi < 0) bi = 0;
    if (bi > 63) bi = 63;
    while (bi > 0 && bi * NBLK - bi * (bi - 1) / 2 > kb) --bi;
    while ((bi + 1) * NBLK - (bi + 1) * bi / 2 <= kb) ++bi;
    const int bj = bi + (kb - (bi * NBLK - bi * (bi - 1) / 2));
    const int i0 = bi * BM, j0 = bj * BN;
    const bool offdiag = (bi != bj);

    const int tid = threadIdx.x, lane = tid & 31, warp = tid >> 5;
    const int wm = warp >> 2;   // 0..1 : 64-row band
    const int wn = warp & 3;    // 0..3 : 32-col band
    const int r4 = lane >> 2;
    const int cq = lane & 3;

    if (tid < BM) slabi[tid] = labels[i0 + tid];
    else if (tid < BM + BN) slabj[tid - BM] = labels[j0 + tid - BM];

    float acc[4][4][4];
#pragma unroll
    for (int mt = 0; mt < 4; ++mt)
#pragma unroll
        for (int nt = 0; nt < 4; ++nt)
#pragma unroll
            for (int e = 0; e < 4; ++e) acc[mt][nt][e] = 0.f;

    // ldmatrix lane addressing (word offsets within a stage)
    const int arow = wm * 64 + (lane & 15);
    const int akw  = (lane >> 4) * 4;
    const int awoff = arow * PADW + akw;                       // + mt*16*PADW + ko
    const int brow = wn * 32 + (lane & 7) + ((lane >= 16) ? 8 : 0);
    const int bkw  = ((lane >> 3) & 1) * 4;
    const int bwoff = brow * PADW + bkw;                       // + p*16*PADW + ko

    const int NK = D_SZ / BK;  // 16
    load_chunk(sb, 0, 0, i0, j0, tid);

    for (int kt = 0; kt < NK; ++kt) {
        const int s = kt & 1;
        if (kt + 1 < NK) {
            load_chunk(sb, s ^ 1, (kt + 1) * BK, i0, j0, tid);
            asm volatile("cp.async.wait_group 1;\n" ::: "memory");
        } else {
            asm volatile("cp.async.wait_group 0;\n" ::: "memory");
        }
        __syncthreads();

#pragma unroll
        for (int ks = 0; ks < 2; ++ks) {
            const int ko = ks * 8;
            uint32_t a[4][4], b[2][4];
#pragma unroll
            for (int mt = 0; mt < 4; ++mt)
                ldsm4(a[mt], sb + (SM_A(s) + awoff + mt * 16 * PADW + ko) * 4);
#pragma unroll
            for (int p = 0; p < 2; ++p)
                ldsm4(b[p], sb + (SM_B(s) + bwoff + p * 16 * PADW + ko) * 4);
#pragma unroll
            for (int mt = 0; mt < 4; ++mt)
#pragma unroll
                for (int nt = 0; nt < 4; ++nt) {
                    uint32_t bb[2] = {b[nt >> 1][(nt & 1) * 2], b[nt >> 1][(nt & 1) * 2 + 1]};
                    mma16816(acc[mt][nt], a[mt], bb);
                }
        }
        __syncthreads();
    }

    // ---- epilogue ----
    const float inv = 1.0f / g_end_norm;
    const float ONE_EPS = 1.0f - 1e-5f;
    const float INF = __int_as_float(0x7f800000);
    uint32_t* tile = dsm + warp * 2112;   // [64][33] per warp (reuses mainloop smem)

    float cmn[4][2], cmx[4][2];           // column accumulators (for mirrored rows)
#pragma unroll
    for (int nt = 0; nt < 4; ++nt) {
        cmn[nt][0] = cmn[nt][1] = INF;
        cmx[nt][0] = cmx[nt][1] = -INF;
    }

#pragma unroll
    for (int mt = 0; mt < 4; ++mt) {
        const int lr0 = mt * 16 + r4, lr1 = lr0 + 8;
        const int li0 = slabi[wm * 64 + lr0], li1 = slabi[wm * 64 + lr1];
        float mn0 = INF, mn1 = INF, mx0 = -INF, mx1 = -INF;
#pragma unroll
        for (int nt = 0; nt < 4; ++nt) {
            const int lc = nt * 8 + 2 * cq;
            const int lj0 = slabj[wn * 32 + lc], lj1 = slabj[wn * 32 + lc + 1];
            float s00 = acc[mt][nt][0] * inv, s01 = acc[mt][nt][1] * inv;
            float s10 = acc[mt][nt][2] * inv, s11 = acc[mt][nt][3] * inv;

            bool sm00 = (li0 == lj0), sm01 = (li0 == lj1);
            bool sm10 = (li1 == lj0), sm11 = (li1 == lj1);
            bool p00 = sm00 && (s00 < ONE_EPS), p01 = sm01 && (s01 < ONE_EPS);
            bool p10 = sm10 && (s10 < ONE_EPS), p11 = sm11 && (s11 < ONE_EPS);

            if (p00) { mn0 = fminf(mn0, s00); cmn[nt][0] = fminf(cmn[nt][0], s00); }
            if (p01) { mn0 = fminf(mn0, s01); cmn[nt][1] = fminf(cmn[nt][1], s01); }
            if (p10) { mn1 = fminf(mn1, s10); cmn[nt][0] = fminf(cmn[nt][0], s10); }
            if (p11) { mn1 = fminf(mn1, s11); cmn[nt][1] = fminf(cmn[nt][1], s11); }
            if (!sm00) { mx0 = fmaxf(mx0, s00); cmx[nt][0] = fmaxf(cmx[nt][0], s00); }
            if (!sm01) { mx0 = fmaxf(mx0, s01); cmx[nt][1] = fmaxf(cmx[nt][1], s01); }
            if (!sm10) { mx1 = fmaxf(mx1, s10); cmx[nt][0] = fmaxf(cmx[nt][0], s10); }
            if (!sm11) { mx1 = fmaxf(mx1, s11); cmx[nt][1] = fmaxf(cmx[nt][1], s11); }

            unsigned f00 = p00 ? 1u : (sm00 ? 0u : 2u);
            unsigned f01 = p01 ? 1u : (sm01 ? 0u : 2u);
            unsigned f10 = p10 ? 1u : (sm10 ? 0u : 2u);
            unsigned f11 = p11 ? 1u : (sm11 ? 0u : 2u);
            tile[lr0 * 33 + lc]     = (__float_as_uint(s00) & ~3u) | f00;
            tile[lr0 * 33 + lc + 1] = (__float_as_uint(s01) & ~3u) | f01;
            tile[lr1 * 33 + lc]     = (__float_as_uint(s10) & ~3u) | f10;
            tile[lr1 * 33 + lc + 1] = (__float_as_uint(s11) & ~3u) | f11;
        }
        // row reductions across cq lanes
#pragma unroll
        for (int o = 1; o < 4; o <<= 1) {
            mn0 = fminf(mn0, __shfl_xor_sync(0xffffffffu, mn0, o));
            mn1 = fminf(mn1, __shfl_xor_sync(0xffffffffu, mn1, o));
            mx0 = fmaxf(mx0, __shfl_xor_sync(0xffffffffu, mx0, o));
            mx1 = fmaxf(mx1, __shfl_xor_sync(0xffffffffu, mx1, o));
        }
        if (cq == 0) {
            atomicMin(&g_minpos[i0 + wm * 64 + lr0], fenc(mn0));
            atomicMin(&g_minpos[i0 + wm * 64 + lr1], fenc(mn1));
            atomicMax(&g_maxneg[i0 + wm * 64 + lr0], fenc(mx0));
            atomicMax(&g_maxneg[i0 + wm * 64 + lr1], fenc(mx1));
        }
    }

    // column (mirrored-row) reductions across r4 lanes, then atomics
    if (offdiag) {
#pragma unroll
        for (int nt = 0; nt < 4; ++nt)
#pragma unroll
            for (int h = 0; h < 2; ++h) {
#pragma unroll
                for (int o = 4; o < 32; o <<= 1) {
                    cmn[nt][h] = fminf(cmn[nt][h], __shfl_xor_sync(0xffffffffu, cmn[nt][h], o));
                    cmx[nt][h] = fmaxf(cmx[nt][h], __shfl_xor_sync(0xffffffffu, cmx[nt][h], o));
                }
            }
        if (r4 == 0) {
#pragma unroll
            for (int nt = 0; nt < 4; ++nt) {
                const int gj = j0 + wn * 32 + nt * 8 + 2 * cq;
                atomicMin(&g_minpos[gj], fenc(cmn[nt][0]));
                atomicMin(&g_minpos[gj + 1], fenc(cmn[nt][1]));
                atomicMax(&g_maxneg[gj], fenc(cmx[nt][0]));
                atomicMax(&g_maxneg[gj + 1], fenc(cmx[nt][1]));
            }
        }
    }
    __syncwarp();

    // phase 1: direct store (coalesced 128B per row per warp)
#pragma unroll 8
    for (int r = 0; r < 64; ++r) {
        g_sim[(size_t)(i0 + wm * 64 + r) * B_SZ + (j0 + wn * 32 + lane)] = tile[r * 33 + lane];
    }
    // phase 2: transposed store for the mirrored block
    if (offdiag) {
#pragma unroll 8
        for (int c = 0; c < 32; ++c) {
            size_t base = (size_t)(j0 + wn * 32 + c) * B_SZ + (i0 + wm * 64);
            g_sim[base + lane]      = tile[lane * 33 + c];
            g_sim[base + 32 + lane] = tile[(lane + 32) * 33 + c];
        }
    }
}

// ---------------- K3: per-row masked exp-sums ----------------
__global__ __launch_bounds__(256) void k_rows() {
    const int warp = threadIdx.x >> 5, lane = threadIdx.x & 31;
    const int row = blockIdx.x * 8 + warp;
    const float thrP = fdec(g_maxneg[row]) + MARGIN;   // pos selected iff s < thrP
    const float thrN = fdec(g_minpos[row]) - MARGIN;   // neg selected iff s > thrN
    const uint4* srow = reinterpret_cast<const uint4*>(g_sim + (size_t)row * B_SZ);

    float sp = 0.f, sn = 0.f;
#pragma unroll 1
    for (int q = lane; q < B_SZ / 4; q += 128) {
        uint4 v0 = srow[q], v1 = srow[q + 32], v2 = srow[q + 64], v3 = srow[q + 96];
        unsigned u[16] = {v0.x, v0.y, v0.z, v0.w, v1.x, v1.y, v1.z, v1.w,
                          v2.x, v2.y, v2.z, v2.w, v3.x, v3.y, v3.z, v3.w};
#pragma unroll
        for (int e = 0; e < 16; ++e) {
            unsigned uu = u[e];
            float s = __uint_as_float(uu);
            bool pos = (uu & 1u) && (s < thrP);
            bool neg = (uu & 2u) && (s > thrN);
            float x = pos ? -2.f * s : 2.f * s;
            float ev = expx(x);
            if (pos) sp += ev;
            if (neg) sn += ev;
        }
    }
#pragma unroll
    for (int o = 16; o > 0; o >>= 1) {
        sp += __shfl_xor_sync(0xffffffffu, sp, o);
        sn += __shfl_xor_sync(0xffffffffu, sn, o);
    }
    if (lane == 0) {
        float loss = 0.f;
        if (sp > 0.f && sn > 0.f) {
            const float E = 2.718281828459045f;
            const float EINV = 0.36787944117144233f;
            loss = 0.5f * log1pf(E * sp) + 0.5f * log1pf(EINV * sn);
        }
        g_rowloss[row] = loss;
    }
}

// ---------------- K4: deterministic final reduction ----------------
__global__ __launch_bounds__(256) void k_final(float* __restrict__ out) {
    __shared__ float red[256];
    float s = 0.f;
    for (int i = threadIdx.x; i < B_SZ; i += 256) s += g_rowloss[i];
    red[threadIdx.x] = s;
    __syncthreads();
    for (int o = 128; o > 0; o >>= 1) {
        if (threadIdx.x < o) red[threadIdx.x] += red[threadIdx.x + o];
        __syncthreads();
    }
    if (threadIdx.x == 0) out[0] = red[0] * (1.0f / B_SZ);
}

// ---------------- launch ----------------
extern "C" void kernel_launch(void* const* d_in, const int* in_sizes, int n_in,
                              void* d_out, int out_size) {
    const float* feats = (const float*)d_in[0];
    const int* labels = (const int*)d_in[1];
    (void)in_sizes; (void)n_in; (void)out_size;

    static int once = 0;
    if (!once) {
        cudaFuncSetAttribute(k_gemm, cudaFuncAttributeMaxDynamicSharedMemorySize, SMEM_BYTES);
        once = 1;
    }

    k_prep<<<512, 256>>>(feats);
    k_reduce_init<<<1, 512>>>();
    k_gemm<<<NTRI, 256, SMEM_BYTES>>>(labels);
    k_rows<<<B_SZ / 8, 256>>>();
    k_final<<<1, 256>>>((float*)d_out);
}

// round 4
// speedup vs baseline: 1.9596x; 1.1303x over previous
#include <cuda_runtime.h>
#include <cuda_bf16.h>
#include <cstdint>
#include <cstddef>

#define B_SZ 8192
#define D_SZ 512
#define MARGIN 0.1f

#define BM 128
#define BN 128
#define BK 32
#define PADW 20          // words per smem row: 16 data + 4 pad (conflict-free LDSM)
#define NBLK 64          // 8192/128
#define NTRI 2080        // NBLK*(NBLK+1)/2

// dynamic smem (words): 3 stages x (A 2560 + B 2560) = 15360 words (61.4KB)
// epilogue tiles: 8 warps x 64x33 = 16896 words (67.6KB). Union -> 67584 bytes.
#define SM_A(s)  ((s) * 5120)
#define SM_B(s)  ((s) * 5120 + 2560)
#define SMEM_BYTES 67584

// ---------------- device scratch ----------------
static __device__ __nv_bfloat16 g_fbf[B_SZ * D_SZ];          // 8 MB bf16 feats (L2-resident)
static __device__ float        g_sim[(size_t)B_SZ * B_SZ];   // 256 MB encoded sims
static __device__ unsigned     g_minpos[B_SZ];
static __device__ unsigned     g_maxneg[B_SZ];
static __device__ float        g_enorm_part[512];
static __device__ float        g_end_norm;
static __device__ float        g_rowloss[B_SZ];

// order-preserving float<->uint encoding
__device__ __forceinline__ unsigned fenc(float f) {
    unsigned u = __float_as_uint(f);
    return (u & 0x80000000u) ? ~u : (u | 0x80000000u);
}
__device__ __forceinline__ float fdec(unsigned u) {
    return (u & 0x80000000u) ? __uint_as_float(u ^ 0x80000000u) : __uint_as_float(~u);
}

// ---------------- K1: sumsq partials + fp32->bf16 ----------------
__global__ __launch_bounds__(256) void k_prep(const float* __restrict__ feats) {
    const int n4 = B_SZ * D_SZ / 4;
    const float4* f4 = reinterpret_cast<const float4*>(feats);
    float s = 0.f;
    for (int i = blockIdx.x * blockDim.x + threadIdx.x; i < n4; i += gridDim.x * blockDim.x) {
        float4 v = f4[i];
        s += v.x * v.x + v.y * v.y + v.z * v.z + v.w * v.w;
        __nv_bfloat162 lo = __floats2bfloat162_rn(v.x, v.y);
        __nv_bfloat162 hi = __floats2bfloat162_rn(v.z, v.w);
        uint2 o;
        o.x = *reinterpret_cast<unsigned*>(&lo);
        o.y = *reinterpret_cast<unsigned*>(&hi);
        reinterpret_cast<uint2*>(g_fbf)[i] = o;
    }
    __shared__ float red[256];
    red[threadIdx.x] = s;
    __syncthreads();
    for (int o = 128; o > 0; o >>= 1) {
        if (threadIdx.x < o) red[threadIdx.x] += red[threadIdx.x + o];
        __syncthreads();
    }
    if (threadIdx.x == 0) g_enorm_part[blockIdx.x] = red[0];
}

// ---------------- K1b: reduce end_norm + init min/max ----------------
__global__ __launch_bounds__(512) void k_reduce_init() {
    __shared__ float red[512];
    red[threadIdx.x] = g_enorm_part[threadIdx.x];
    __syncthreads();
    for (int o = 256; o > 0; o >>= 1) {
        if (threadIdx.x < o) red[threadIdx.x] += red[threadIdx.x + o];
        __syncthreads();
    }
    if (threadIdx.x == 0) g_end_norm = red[0];
    for (int i = threadIdx.x; i < B_SZ; i += 512) {
        g_minpos[i] = 0xFF800000u;   // enc(+inf)
        g_maxneg[i] = 0x007FFFFFu;   // enc(-inf)
    }
}

// ---------------- GEMM helpers ----------------
__device__ __forceinline__ void mma16816(float* d, const uint32_t* a, const uint32_t* b) {
    asm volatile(
        "mma.sync.aligned.m16n8k16.row.col.f32.bf16.bf16.f32 "
        "{%0,%1,%2,%3}, {%4,%5,%6,%7}, {%8,%9}, {%0,%1,%2,%3};\n"
        : "+f"(d[0]), "+f"(d[1]), "+f"(d[2]), "+f"(d[3])
        : "r"(a[0]), "r"(a[1]), "r"(a[2]), "r"(a[3]), "r"(b[0]), "r"(b[1]));
}
__device__ __forceinline__ void ldsm4(uint32_t* d, uint32_t saddr) {
    asm volatile("ldmatrix.sync.aligned.m8n8.x4.shared.b16 {%0,%1,%2,%3}, [%4];"
                 : "=r"(d[0]), "=r"(d[1]), "=r"(d[2]), "=r"(d[3]) : "r"(saddr));
}
__device__ __forceinline__ void cpa16(uint32_t saddr, const void* g) {
    asm volatile("cp.async.cg.shared.global [%0], [%1], 16;\n" :: "r"(saddr), "l"(g));
}
__device__ __forceinline__ void load_chunk(uint32_t sb, int stage, int kbase,
                                           int i0, int j0, int tid) {
    const int r = tid >> 2, q = tid & 3;
#pragma unroll
    for (int h = 0; h < 2; ++h) {
        int rr = r + h * 64;
        cpa16(sb + (SM_A(stage) + rr * PADW + q * 4) * 4,
              g_fbf + (size_t)(i0 + rr) * D_SZ + kbase + q * 8);
        cpa16(sb + (SM_B(stage) + rr * PADW + q * 4) * 4,
              g_fbf + (size_t)(j0 + rr) * D_SZ + kbase + q * 8);
    }
    asm volatile("cp.async.commit_group;\n" ::: "memory");
}

// ---------------- K2: triangular HMMA GEMM + fused epilogue ----------------
__global__ void __launch_bounds__(256, 2) k_gemm(const int* __restrict__ labels) {
    extern __shared__ uint32_t dsm[];
    const uint32_t sb = (uint32_t)__cvta_generic_to_shared(dsm);
    __shared__ int slabi[BM];
    __shared__ int slabj[BN];

    // ---- triangular block mapping ----
    const int kb = blockIdx.x;
    int bi = (int)(64.5f - sqrtf(64.5f * 64.5f - 2.0f * (float)kb));
    if (bi < 0) bi = 0;
    if (bi > 63) bi = 63;
    while (bi > 0 && bi * NBLK - bi * (bi - 1) / 2 > kb) --bi;
    while ((bi + 1) * NBLK - (bi + 1) * bi / 2 <= kb) ++bi;
    const int bj = bi + (kb - (bi * NBLK - bi * (bi - 1) / 2));
    const int i0 = bi * BM, j0 = bj * BN;
    const bool offdiag = (bi != bj);

    const int tid = threadIdx.x, lane = tid & 31, warp = tid >> 5;
    const int wm = warp >> 2;   // 0..1 : 64-row band
    const int wn = warp & 3;    // 0..3 : 32-col band
    const int r4 = lane >> 2;
    const int cq = lane & 3;

    if (tid < BM) slabi[tid] = labels[i0 + tid];
    else if (tid < BM + BN) slabj[tid - BM] = labels[j0 + tid - BM];

    float acc[4][4][4];
#pragma unroll
    for (int mt = 0; mt < 4; ++mt)
#pragma unroll
        for (int nt = 0; nt < 4; ++nt)
#pragma unroll
            for (int e = 0; e < 4; ++e) acc[mt][nt][e] = 0.f;

    // ldmatrix lane addressing (word offsets within a stage)
    const int arow = wm * 64 + (lane & 15);
    const int akw  = (lane >> 4) * 4;
    const int awoff = arow * PADW + akw;
    const int brow = wn * 32 + (lane & 7) + ((lane >= 16) ? 8 : 0);
    const int bkw  = ((lane >> 3) & 1) * 4;
    const int bwoff = brow * PADW + bkw;

    const int NK = D_SZ / BK;  // 16
    load_chunk(sb, 0, 0, i0, j0, tid);
    load_chunk(sb, 1, BK, i0, j0, tid);

    for (int kt = 0; kt < NK; ++kt) {
        const int s = kt % 3;
        if (kt + 1 < NK) asm volatile("cp.async.wait_group 1;\n" ::: "memory");
        else             asm volatile("cp.async.wait_group 0;\n" ::: "memory");
        __syncthreads();
        if (kt + 2 < NK) load_chunk(sb, (kt + 2) % 3, (kt + 2) * BK, i0, j0, tid);

#pragma unroll
        for (int ks = 0; ks < 2; ++ks) {
            const int ko = ks * 8;
            uint32_t a[4][4], b[2][4];
#pragma unroll
            for (int mt = 0; mt < 4; ++mt)
                ldsm4(a[mt], sb + (SM_A(s) + awoff + mt * 16 * PADW + ko) * 4);
#pragma unroll
            for (int p = 0; p < 2; ++p)
                ldsm4(b[p], sb + (SM_B(s) + bwoff + p * 16 * PADW + ko) * 4);
#pragma unroll
            for (int mt = 0; mt < 4; ++mt)
#pragma unroll
                for (int nt = 0; nt < 4; ++nt) {
                    uint32_t bb[2] = {b[nt >> 1][(nt & 1) * 2], b[nt >> 1][(nt & 1) * 2 + 1]};
                    mma16816(acc[mt][nt], a[mt], bb);
                }
        }
    }
    __syncthreads();   // all compute done before smem reuse by epilogue tiles

    // ---- epilogue: scale, min/max, range-encode (pos: s | neg: s+2 | neither: NaN) ----
    const float inv = 1.0f / g_end_norm;
    const float ONE_EPS = 1.0f - 1e-5f;
    const float INF = __int_as_float(0x7f800000);
    const float QNAN = __int_as_float(0x7fc00000);
    uint32_t* tile = dsm + warp * 2112;   // [64][33] per warp

    float cmn[4][2], cmx[4][2];           // column accumulators (mirrored rows)
#pragma unroll
    for (int nt = 0; nt < 4; ++nt) {
        cmn[nt][0] = cmn[nt][1] = INF;
        cmx[nt][0] = cmx[nt][1] = -INF;
    }

#pragma unroll
    for (int mt = 0; mt < 4; ++mt) {
        const int lr0 = mt * 16 + r4, lr1 = lr0 + 8;
        const int li0 = slabi[wm * 64 + lr0], li1 = slabi[wm * 64 + lr1];
        float mn0 = INF, mn1 = INF, mx0 = -INF, mx1 = -INF;
#pragma unroll
        for (int nt = 0; nt < 4; ++nt) {
            const int lc = nt * 8 + 2 * cq;
            const int lj0 = slabj[wn * 32 + lc], lj1 = slabj[wn * 32 + lc + 1];
            float s00 = acc[mt][nt][0] * inv, s01 = acc[mt][nt][1] * inv;
            float s10 = acc[mt][nt][2] * inv, s11 = acc[mt][nt][3] * inv;

            bool sm00 = (li0 == lj0), sm01 = (li0 == lj1);
            bool sm10 = (li1 == lj0), sm11 = (li1 == lj1);
            bool p00 = sm00 && (s00 < ONE_EPS), p01 = sm01 && (s01 < ONE_EPS);
            bool p10 = sm10 && (s10 < ONE_EPS), p11 = sm11 && (s11 < ONE_EPS);

            if (p00) { mn0 = fminf(mn0, s00); cmn[nt][0] = fminf(cmn[nt][0], s00); }
            if (p01) { mn0 = fminf(mn0, s01); cmn[nt][1] = fminf(cmn[nt][1], s01); }
            if (p10) { mn1 = fminf(mn1, s10); cmn[nt][0] = fminf(cmn[nt][0], s10); }
            if (p11) { mn1 = fminf(mn1, s11); cmn[nt][1] = fminf(cmn[nt][1], s11); }
            if (!sm00) { mx0 = fmaxf(mx0, s00); cmx[nt][0] = fmaxf(cmx[nt][0], s00); }
            if (!sm01) { mx0 = fmaxf(mx0, s01); cmx[nt][1] = fmaxf(cmx[nt][1], s01); }
            if (!sm10) { mx1 = fmaxf(mx1, s10); cmx[nt][0] = fmaxf(cmx[nt][0], s10); }
            if (!sm11) { mx1 = fmaxf(mx1, s11); cmx[nt][1] = fmaxf(cmx[nt][1], s11); }

            float t00 = sm00 ? (p00 ? s00 : QNAN) : s00 + 2.f;
            float t01 = sm01 ? (p01 ? s01 : QNAN) : s01 + 2.f;
            float t10 = sm10 ? (p10 ? s10 : QNAN) : s10 + 2.f;
            float t11 = sm11 ? (p11 ? s11 : QNAN) : s11 + 2.f;
            tile[lr0 * 33 + lc]     = __float_as_uint(t00);
            tile[lr0 * 33 + lc + 1] = __float_as_uint(t01);
            tile[lr1 * 33 + lc]     = __float_as_uint(t10);
            tile[lr1 * 33 + lc + 1] = __float_as_uint(t11);
        }
#pragma unroll
        for (int o = 1; o < 4; o <<= 1) {
            mn0 = fminf(mn0, __shfl_xor_sync(0xffffffffu, mn0, o));
            mn1 = fminf(mn1, __shfl_xor_sync(0xffffffffu, mn1, o));
            mx0 = fmaxf(mx0, __shfl_xor_sync(0xffffffffu, mx0, o));
            mx1 = fmaxf(mx1, __shfl_xor_sync(0xffffffffu, mx1, o));
        }
        if (cq == 0) {
            atomicMin(&g_minpos[i0 + wm * 64 + lr0], fenc(mn0));
            atomicMin(&g_minpos[i0 + wm * 64 + lr1], fenc(mn1));
            atomicMax(&g_maxneg[i0 + wm * 64 + lr0], fenc(mx0));
            atomicMax(&g_maxneg[i0 + wm * 64 + lr1], fenc(mx1));
        }
    }

    if (offdiag) {
#pragma unroll
        for (int nt = 0; nt < 4; ++nt)
#pragma unroll
            for (int h = 0; h < 2; ++h) {
#pragma unroll
                for (int o = 4; o < 32; o <<= 1) {
                    cmn[nt][h] = fminf(cmn[nt][h], __shfl_xor_sync(0xffffffffu, cmn[nt][h], o));
                    cmx[nt][h] = fmaxf(cmx[nt][h], __shfl_xor_sync(0xffffffffu, cmx[nt][h], o));
                }
            }
        if (r4 == 0) {
#pragma unroll
            for (int nt = 0; nt < 4; ++nt) {
                const int gj = j0 + wn * 32 + nt * 8 + 2 * cq;
                atomicMin(&g_minpos[gj], fenc(cmn[nt][0]));
                atomicMin(&g_minpos[gj + 1], fenc(cmn[nt][1]));
                atomicMax(&g_maxneg[gj], fenc(cmx[nt][0]));
                atomicMax(&g_maxneg[gj + 1], fenc(cmx[nt][1]));
            }
        }
    }
    __syncwarp();

    unsigned* gsim = reinterpret_cast<unsigned*>(g_sim);
    // phase 1: direct store (coalesced 128B per row per warp)
#pragma unroll 8
    for (int r = 0; r < 64; ++r) {
        gsim[(size_t)(i0 + wm * 64 + r) * B_SZ + (j0 + wn * 32 + lane)] = tile[r * 33 + lane];
    }
    // phase 2: transposed store for the mirrored block
    if (offdiag) {
#pragma unroll 8
        for (int c = 0; c < 32; ++c) {
            size_t base = (size_t)(j0 + wn * 32 + c) * B_SZ + (i0 + wm * 64);
            gsim[base + lane]      = tile[lane * 33 + c];
            gsim[base + 32 + lane] = tile[(lane + 32) * 33 + c];
        }
    }
}

// ---------------- K3: per-row masked exp-sums (range-encoded, dual deg-3 polys) ----------------
__global__ __launch_bounds__(256) void k_rows() {
    const int warp = threadIdx.x >> 5, lane = threadIdx.x & 31;
    const int row = blockIdx.x * 8 + warp;
    const float thrP  = fdec(g_maxneg[row]) + MARGIN;          // pos-sel iff t < thrP
    const float thrN2 = fdec(g_minpos[row]) - MARGIN + 2.0f;   // neg-sel iff t > thrN2
    const float4* srow = reinterpret_cast<const float4*>(g_sim + (size_t)row * B_SZ);

    // e^{-2t} deg-3:            1 - 2t + 2t^2 - (4/3)t^3
    // e^{2(t-2)} deg-3 monomial: (4/3)t^3 - 6t^2 + 10t - 17/3
    float spA = 0.f, spB = 0.f, snA = 0.f, snB = 0.f;
#pragma unroll 1
    for (int q = lane; q < B_SZ / 4; q += 128) {
        float4 v0 = srow[q], v1 = srow[q + 32], v2 = srow[q + 64], v3 = srow[q + 96];
        float u[16] = {v0.x, v0.y, v0.z, v0.w, v1.x, v1.y, v1.z, v1.w,
                       v2.x, v2.y, v2.z, v2.w, v3.x, v3.y, v3.z, v3.w};
#pragma unroll
        for (int e = 0; e < 16; ++e) {
            float t = u[e];
            float evp = fmaf(t, fmaf(t, fmaf(t, -1.33333333f, 2.f), -2.f), 1.f);
            float evn = fmaf(t, fmaf(t, fmaf(t, 1.33333333f, -6.f), 10.f), -5.66666667f);
            if (t < thrP)  { if (e & 1) spA += evp; else spB += evp; }
            if (t > thrN2) { if (e & 1) snA += evn; else snB += evn; }
        }
    }
    float sp = spA + spB, sn = snA + snB;
#pragma unroll
    for (int o = 16; o > 0; o >>= 1) {
        sp += __shfl_xor_sync(0xffffffffu, sp, o);
        sn += __shfl_xor_sync(0xffffffffu, sn, o);
    }
    if (lane == 0) {
        float loss = 0.f;
        if (sp > 0.f && sn > 0.f) {
            const float E = 2.718281828459045f;
            const float EINV = 0.36787944117144233f;
            loss = 0.5f * log1pf(E * sp) + 0.5f * log1pf(EINV * sn);
        }
        g_rowloss[row] = loss;
    }
}

// ---------------- K4: deterministic final reduction ----------------
__global__ __launch_bounds__(256) void k_final(float* __restrict__ out) {
    __shared__ float red[256];
    float s = 0.f;
    for (int i = threadIdx.x; i < B_SZ; i += 256) s += g_rowloss[i];
    red[threadIdx.x] = s;
    __syncthreads();
    for (int o = 128; o > 0; o >>= 1) {
        if (threadIdx.x < o) red[threadIdx.x] += red[threadIdx.x + o];
        __syncthreads();
    }
    if (threadIdx.x == 0) out[0] = red[0] * (1.0f / B_SZ);
}

// ---------------- launch ----------------
extern "C" void kernel_launch(void* const* d_in, const int* in_sizes, int n_in,
                              void* d_out, int out_size) {
    const float* feats = (const float*)d_in[0];
    const int* labels = (const int*)d_in[1];
    (void)in_sizes; (void)n_in; (void)out_size;

    static int once = 0;
    if (!once) {
        cudaFuncSetAttribute(k_gemm, cudaFuncAttributeMaxDynamicSharedMemorySize, SMEM_BYTES);
        once = 1;
    }

    k_prep<<<512, 256>>>(feats);
    k_reduce_init<<<1, 512>>>();
    k_gemm<<<NTRI, 256, SMEM_BYTES>>>(labels);
    k_rows<<<B_SZ / 8, 256>>>();
    k_final<<<1, 256>>>((float*)d_out);
}

// round 5
// speedup vs baseline: 3.0930x; 1.5783x over previous
#include <cuda_runtime.h>
#include <cuda_bf16.h>
#include <cstdint>
#include <cstddef>

#define B_SZ 8192
#define D_SZ 512
#define MARGIN 0.1f

#define BM 128
#define BN 128
#define BK 32
#define PADW 20          // words per smem row: 16 data + 4 pad (conflict-free LDSM)
#define NBLK 64
#define NTRI 2080        // NBLK*(NBLK+1)/2

// dynamic smem (words): 3 stages x (A 2560 + B 2560) = 15360 words (61.4KB)
#define SM_A(s)  ((s) * 5120)
#define SM_B(s)  ((s) * 5120 + 2560)
#define SMEM_BYTES 61440

// ---------------- device scratch ----------------
static __device__ __nv_bfloat16 g_fbf[B_SZ * D_SZ];   // 8 MB bf16 feats (L2-resident)
static __device__ float    g_sp[B_SZ];                // per-row sum e^{-2s} over pos
static __device__ float    g_sn[B_SZ];                // per-row sum e^{+2s} over neg
static __device__ unsigned g_minpos[B_SZ];            // order-encoded min over pos
static __device__ unsigned g_maxneg[B_SZ];            // order-encoded max over neg
static __device__ unsigned g_gmaxpos;                 // global max over pos (encoded)
static __device__ unsigned g_gminneg;                 // global min over neg (encoded)
static __device__ float    g_enorm_part[512];
static __device__ float    g_end_norm;
static __device__ float    g_rowloss[B_SZ];
static __device__ int      g_fixlist[B_SZ];
static __device__ int      g_nfix;

// order-preserving float<->uint encoding
__device__ __forceinline__ unsigned fenc(float f) {
    unsigned u = __float_as_uint(f);
    return (u & 0x80000000u) ? ~u : (u | 0x80000000u);
}
__device__ __forceinline__ float fdec(unsigned u) {
    return (u & 0x80000000u) ? __uint_as_float(u ^ 0x80000000u) : __uint_as_float(~u);
}

// ---------------- K1: sumsq partials + fp32->bf16 ----------------
__global__ __launch_bounds__(256) void k_prep(const float* __restrict__ feats) {
    const int n4 = B_SZ * D_SZ / 4;
    const float4* f4 = reinterpret_cast<const float4*>(feats);
    float s = 0.f;
    for (int i = blockIdx.x * blockDim.x + threadIdx.x; i < n4; i += gridDim.x * blockDim.x) {
        float4 v = f4[i];
        s += v.x * v.x + v.y * v.y + v.z * v.z + v.w * v.w;
        __nv_bfloat162 lo = __floats2bfloat162_rn(v.x, v.y);
        __nv_bfloat162 hi = __floats2bfloat162_rn(v.z, v.w);
        uint2 o;
        o.x = *reinterpret_cast<unsigned*>(&lo);
        o.y = *reinterpret_cast<unsigned*>(&hi);
        reinterpret_cast<uint2*>(g_fbf)[i] = o;
    }
    __shared__ float red[256];
    red[threadIdx.x] = s;
    __syncthreads();
    for (int o = 128; o > 0; o >>= 1) {
        if (threadIdx.x < o) red[threadIdx.x] += red[threadIdx.x + o];
        __syncthreads();
    }
    if (threadIdx.x == 0) g_enorm_part[blockIdx.x] = red[0];
}

// ---------------- K1b: reduce end_norm + init accumulators ----------------
__global__ __launch_bounds__(512) void k_reduce_init() {
    __shared__ float red[512];
    red[threadIdx.x] = g_enorm_part[threadIdx.x];
    __syncthreads();
    for (int o = 256; o > 0; o >>= 1) {
        if (threadIdx.x < o) red[threadIdx.x] += red[threadIdx.x + o];
        __syncthreads();
    }
    if (threadIdx.x == 0) {
        g_end_norm = red[0];
        g_nfix = 0;
        g_gmaxpos = 0x007FFFFFu;   // enc(-inf)
        g_gminneg = 0xFF800000u;   // enc(+inf)
    }
    for (int i = threadIdx.x; i < B_SZ; i += 512) {
        g_sp[i] = 0.f;
        g_sn[i] = 0.f;
        g_minpos[i] = 0xFF800000u;   // enc(+inf)
        g_maxneg[i] = 0x007FFFFFu;   // enc(-inf)
    }
}

// ---------------- GEMM helpers ----------------
__device__ __forceinline__ void mma16816(float* d, const uint32_t* a, const uint32_t* b) {
    asm volatile(
        "mma.sync.aligned.m16n8k16.row.col.f32.bf16.bf16.f32 "
        "{%0,%1,%2,%3}, {%4,%5,%6,%7}, {%8,%9}, {%0,%1,%2,%3};\n"
        : "+f"(d[0]), "+f"(d[1]), "+f"(d[2]), "+f"(d[3])
        : "r"(a[0]), "r"(a[1]), "r"(a[2]), "r"(a[3]), "r"(b[0]), "r"(b[1]));
}
__device__ __forceinline__ void ldsm4(uint32_t* d, uint32_t saddr) {
    asm volatile("ldmatrix.sync.aligned.m8n8.x4.shared.b16 {%0,%1,%2,%3}, [%4];"
                 : "=r"(d[0]), "=r"(d[1]), "=r"(d[2]), "=r"(d[3]) : "r"(saddr));
}
__device__ __forceinline__ void cpa16(uint32_t saddr, const void* g) {
    asm volatile("cp.async.cg.shared.global [%0], [%1], 16;\n" :: "r"(saddr), "l"(g));
}
__device__ __forceinline__ void load_chunk(uint32_t sb, int stage, int kbase,
                                           int i0, int j0, int tid) {
    const int r = tid >> 2, q = tid & 3;
#pragma unroll
    for (int h = 0; h < 2; ++h) {
        int rr = r + h * 64;
        cpa16(sb + (SM_A(stage) + rr * PADW + q * 4) * 4,
              g_fbf + (size_t)(i0 + rr) * D_SZ + kbase + q * 8);
        cpa16(sb + (SM_B(stage) + rr * PADW + q * 4) * 4,
              g_fbf + (size_t)(j0 + rr) * D_SZ + kbase + q * 8);
    }
    asm volatile("cp.async.commit_group;\n" ::: "memory");
}

// element processor: classify, accumulate row/col stats
#define PROC(SRAW, LI, LJ, SP, SN, MN, MX, NT, H)                              \
    {                                                                          \
        float s_ = (SRAW) * inv;                                               \
        float s2_ = s_ * s_;                                                   \
        float even_ = fmaf(s2_, 2.f, 1.f);                                     \
        float odd_ = s_ * fmaf(s2_, 1.33333333f, 2.f);                         \
        if ((LI) == (LJ)) {                                                    \
            if (s_ < ONE_EPS) {                                                \
                float evp_ = even_ - odd_;                                     \
                SP += evp_; MN = fminf(MN, s_); gmx = fmaxf(gmx, s_);          \
                csp[NT][H] += evp_; cmnP[NT][H] = fminf(cmnP[NT][H], s_);      \
            }                                                                  \
        } else {                                                               \
            float evn_ = even_ + odd_;                                         \
            SN += evn_; MX = fmaxf(MX, s_); gmn = fminf(gmn, s_);              \
            csn[NT][H] += evn_; cmxN[NT][H] = fmaxf(cmxN[NT][H], s_);          \
        }                                                                      \
    }

// ---------------- K2: triangular HMMA GEMM + fully fused epilogue ----------------
__global__ void __launch_bounds__(256, 2) k_gemm(const int* __restrict__ labels) {
    extern __shared__ uint32_t dsm[];
    const uint32_t sb = (uint32_t)__cvta_generic_to_shared(dsm);
    __shared__ int slabi[BM];
    __shared__ int slabj[BN];
    __shared__ float sredA[8], sredB[8];

    // ---- triangular block mapping ----
    const int kb = blockIdx.x;
    int bi = (int)(64.5f - sqrtf(64.5f * 64.5f - 2.0f * (float)kb));
    if (bi < 0) bi = 0;
    if (bi > 63) bi = 63;
    while (bi > 0 && bi * NBLK - bi * (bi - 1) / 2 > kb) --bi;
    while ((bi + 1) * NBLK - (bi + 1) * bi / 2 <= kb) ++bi;
    const int bj = bi + (kb - (bi * NBLK - bi * (bi - 1) / 2));
    const int i0 = bi * BM, j0 = bj * BN;
    const bool offdiag = (bi != bj);

    const int tid = threadIdx.x, lane = tid & 31, warp = tid >> 5;
    const int wm = warp >> 2;
    const int wn = warp & 3;
    const int r4 = lane >> 2;
    const int cq = lane & 3;

    if (tid < BM) slabi[tid] = labels[i0 + tid];
    else if (tid < BM + BN) slabj[tid - BM] = labels[j0 + tid - BM];

    float acc[4][4][4];
#pragma unroll
    for (int mt = 0; mt < 4; ++mt)
#pragma unroll
        for (int nt = 0; nt < 4; ++nt)
#pragma unroll
            for (int e = 0; e < 4; ++e) acc[mt][nt][e] = 0.f;

    const int arow = wm * 64 + (lane & 15);
    const int akw  = (lane >> 4) * 4;
    const int awoff = arow * PADW + akw;
    const int brow = wn * 32 + (lane & 7) + ((lane >= 16) ? 8 : 0);
    const int bkw  = ((lane >> 3) & 1) * 4;
    const int bwoff = brow * PADW + bkw;

    const int NK = D_SZ / BK;  // 16
    load_chunk(sb, 0, 0, i0, j0, tid);
    load_chunk(sb, 1, BK, i0, j0, tid);

    for (int kt = 0; kt < NK; ++kt) {
        const int s = kt % 3;
        if (kt + 1 < NK) asm volatile("cp.async.wait_group 1;\n" ::: "memory");
        else             asm volatile("cp.async.wait_group 0;\n" ::: "memory");
        __syncthreads();
        if (kt + 2 < NK) load_chunk(sb, (kt + 2) % 3, (kt + 2) * BK, i0, j0, tid);

#pragma unroll
        for (int ks = 0; ks < 2; ++ks) {
            const int ko = ks * 8;
            uint32_t a[4][4], b[2][4];
#pragma unroll
            for (int mt = 0; mt < 4; ++mt)
                ldsm4(a[mt], sb + (SM_A(s) + awoff + mt * 16 * PADW + ko) * 4);
#pragma unroll
            for (int p = 0; p < 2; ++p)
                ldsm4(b[p], sb + (SM_B(s) + bwoff + p * 16 * PADW + ko) * 4);
#pragma unroll
            for (int mt = 0; mt < 4; ++mt)
#pragma unroll
                for (int nt = 0; nt < 4; ++nt) {
                    uint32_t bb[2] = {b[nt >> 1][(nt & 1) * 2], b[nt >> 1][(nt & 1) * 2 + 1]};
                    mma16816(acc[mt][nt], a[mt], bb);
                }
        }
    }

    // ---- epilogue: classify + accumulate sums/minmax, NO sim materialization ----
    const float inv = 1.0f / g_end_norm;
    const float ONE_EPS = 1.0f - 1e-5f;
    const float INF = __int_as_float(0x7f800000);

    float csp[4][2], csn[4][2], cmnP[4][2], cmxN[4][2];
#pragma unroll
    for (int nt = 0; nt < 4; ++nt)
#pragma unroll
        for (int h = 0; h < 2; ++h) {
            csp[nt][h] = 0.f; csn[nt][h] = 0.f;
            cmnP[nt][h] = INF; cmxN[nt][h] = -INF;
        }
    float gmx = -INF, gmn = INF;

#pragma unroll
    for (int mt = 0; mt < 4; ++mt) {
        const int lr0 = mt * 16 + r4, lr1 = lr0 + 8;
        const int li0 = slabi[wm * 64 + lr0], li1 = slabi[wm * 64 + lr1];
        const int gi0 = i0 + wm * 64 + lr0, gi1 = i0 + wm * 64 + lr1;
        float sp0 = 0.f, sn0 = 0.f, mn0 = INF, mx0 = -INF;
        float sp1 = 0.f, sn1 = 0.f, mn1 = INF, mx1 = -INF;
#pragma unroll
        for (int nt = 0; nt < 4; ++nt) {
            const int lc = nt * 8 + 2 * cq;
            const int lj0 = slabj[wn * 32 + lc], lj1 = slabj[wn * 32 + lc + 1];
            PROC(acc[mt][nt][0], li0, lj0, sp0, sn0, mn0, mx0, nt, 0);
            PROC(acc[mt][nt][1], li0, lj1, sp0, sn0, mn0, mx0, nt, 1);
            PROC(acc[mt][nt][2], li1, lj0, sp1, sn1, mn1, mx1, nt, 0);
            PROC(acc[mt][nt][3], li1, lj1, sp1, sn1, mn1, mx1, nt, 1);
        }
#pragma unroll
        for (int o = 1; o < 4; o <<= 1) {
            sp0 += __shfl_xor_sync(0xffffffffu, sp0, o);
            sn0 += __shfl_xor_sync(0xffffffffu, sn0, o);
            mn0 = fminf(mn0, __shfl_xor_sync(0xffffffffu, mn0, o));
            mx0 = fmaxf(mx0, __shfl_xor_sync(0xffffffffu, mx0, o));
            sp1 += __shfl_xor_sync(0xffffffffu, sp1, o);
            sn1 += __shfl_xor_sync(0xffffffffu, sn1, o);
            mn1 = fminf(mn1, __shfl_xor_sync(0xffffffffu, mn1, o));
            mx1 = fmaxf(mx1, __shfl_xor_sync(0xffffffffu, mx1, o));
        }
        if (cq == 0) {
            atomicAdd(&g_sp[gi0], sp0);
            atomicAdd(&g_sn[gi0], sn0);
            atomicMin(&g_minpos[gi0], fenc(mn0));
            atomicMax(&g_maxneg[gi0], fenc(mx0));
            atomicAdd(&g_sp[gi1], sp1);
            atomicAdd(&g_sn[gi1], sn1);
            atomicMin(&g_minpos[gi1], fenc(mn1));
            atomicMax(&g_maxneg[gi1], fenc(mx1));
        }
    }

    // mirrored (column) contributions for off-diagonal tiles
    if (offdiag) {
#pragma unroll
        for (int nt = 0; nt < 4; ++nt)
#pragma unroll
            for (int h = 0; h < 2; ++h) {
#pragma unroll
                for (int o = 4; o < 32; o <<= 1) {
                    csp[nt][h] += __shfl_xor_sync(0xffffffffu, csp[nt][h], o);
                    csn[nt][h] += __shfl_xor_sync(0xffffffffu, csn[nt][h], o);
                    cmnP[nt][h] = fminf(cmnP[nt][h], __shfl_xor_sync(0xffffffffu, cmnP[nt][h], o));
                    cmxN[nt][h] = fmaxf(cmxN[nt][h], __shfl_xor_sync(0xffffffffu, cmxN[nt][h], o));
                }
            }
        if (r4 == 0) {
#pragma unroll
            for (int nt = 0; nt < 4; ++nt) {
                const int gj = j0 + wn * 32 + nt * 8 + 2 * cq;
                atomicAdd(&g_sp[gj], csp[nt][0]);
                atomicAdd(&g_sn[gj], csn[nt][0]);
                atomicMin(&g_minpos[gj], fenc(cmnP[nt][0]));
                atomicMax(&g_maxneg[gj], fenc(cmxN[nt][0]));
                atomicAdd(&g_sp[gj + 1], csp[nt][1]);
                atomicAdd(&g_sn[gj + 1], csn[nt][1]);
                atomicMin(&g_minpos[gj + 1], fenc(cmnP[nt][1]));
                atomicMax(&g_maxneg[gj + 1], fenc(cmxN[nt][1]));
            }
        }
    }

    // block-reduce global max_pos / min_neg -> 2 atomics per CTA
#pragma unroll
    for (int o = 16; o > 0; o >>= 1) {
        gmx = fmaxf(gmx, __shfl_xor_sync(0xffffffffu, gmx, o));
        gmn = fminf(gmn, __shfl_xor_sync(0xffffffffu, gmn, o));
    }
    if (lane == 0) { sredA[warp] = gmx; sredB[warp] = gmn; }
    __syncthreads();
    if (tid == 0) {
        float a = sredA[0], b = sredB[0];
#pragma unroll
        for (int w = 1; w < 8; ++w) { a = fmaxf(a, sredA[w]); b = fminf(b, sredB[w]); }
        atomicMax(&g_gmaxpos, fenc(a));
        atomicMin(&g_gminneg, fenc(b));
    }
}

// ---------------- K3: per-row check + loss (fast path) ----------------
__global__ __launch_bounds__(256) void k_check() {
    const int r = blockIdx.x * 256 + threadIdx.x;
    const float minpos = fdec(g_minpos[r]);
    const float maxneg = fdec(g_maxneg[r]);
    const float gmaxP = fdec(g_gmaxpos);
    const float gminN = fdec(g_gminneg);
    // all pos of row selected if even the global max pos passes; same for neg
    const bool okP = (gmaxP - MARGIN < maxneg) || (gmaxP == -__int_as_float(0x7f800000) * -1.f && false);
    const bool okN = (gminN + MARGIN > minpos);
    if (okP && okN) {
        float loss = 0.f;
        float sp = g_sp[r], sn = g_sn[r];
        if (sp > 0.f && sn > 0.f) {
            const float E = 2.718281828459045f;
            const float EINV = 0.36787944117144233f;
            loss = 0.5f * log1pf(E * sp) + 0.5f * log1pf(EINV * sn);
        }
        g_rowloss[r] = loss;
    } else {
        g_rowloss[r] = 0.f;   // placeholder; k_fixup overwrites
        int idx = atomicAdd(&g_nfix, 1);
        g_fixlist[idx] = r;
    }
}

// ---------------- K3b: exact fallback for flagged rows (cold path) ----------------
__global__ __launch_bounds__(256) void k_fixup(const int* __restrict__ labels) {
    __shared__ float fr[D_SZ];
    __shared__ float redp[256], redn[256];
    const int n = g_nfix;
    for (int w = blockIdx.x; w < n; w += gridDim.x) {
        const int r = g_fixlist[w];
        for (int k = threadIdx.x; k < D_SZ; k += 256)
            fr[k] = __bfloat162float(g_fbf[(size_t)r * D_SZ + k]);
        __syncthreads();
        const float inv = 1.0f / g_end_norm;
        const float minpos = fdec(g_minpos[r]);
        const float maxneg = fdec(g_maxneg[r]);
        const int lr = labels[r];
        const float ONE_EPS = 1.0f - 1e-5f;
        float sp = 0.f, sn = 0.f;
        for (int j = threadIdx.x; j < B_SZ; j += 256) {
            const __nv_bfloat162* fj =
                reinterpret_cast<const __nv_bfloat162*>(g_fbf + (size_t)j * D_SZ);
            float d = 0.f;
            for (int k = 0; k < D_SZ / 2; ++k) {
                float2 v = __bfloat1622float2(fj[k]);
                d = fmaf(fr[2 * k], v.x, d);
                d = fmaf(fr[2 * k + 1], v.y, d);
            }
            float s = d * inv;
            if (labels[j] == lr) {
                if (s < ONE_EPS && (s - MARGIN < maxneg)) sp += __expf(-2.f * (s - 0.5f));
            } else if (s + MARGIN > minpos) {
                sn += __expf(2.f * (s - 0.5f));
            }
        }
        redp[threadIdx.x] = sp;
        redn[threadIdx.x] = sn;
        __syncthreads();
        for (int o = 128; o > 0; o >>= 1) {
            if (threadIdx.x < o) {
                redp[threadIdx.x] += redp[threadIdx.x + o];
                redn[threadIdx.x] += redn[threadIdx.x + o];
            }
            __syncthreads();
        }
        if (threadIdx.x == 0) {
            float loss = 0.f;
            if (redp[0] > 0.f && redn[0] > 0.f)
                loss = 0.5f * log1pf(redp[0]) + 0.5f * log1pf(redn[0]);
            g_rowloss[r] = loss;
        }
        __syncthreads();
    }
}

// ---------------- K4: deterministic final reduction ----------------
__global__ __launch_bounds__(256) void k_final(float* __restrict__ out) {
    __shared__ float red[256];
    float s = 0.f;
    for (int i = threadIdx.x; i < B_SZ; i += 256) s += g_rowloss[i];
    red[threadIdx.x] = s;
    __syncthreads();
    for (int o = 128; o > 0; o >>= 1) {
        if (threadIdx.x < o) red[threadIdx.x] += red[threadIdx.x + o];
        __syncthreads();
    }
    if (threadIdx.x == 0) out[0] = red[0] * (1.0f / B_SZ);
}

// ---------------- launch ----------------
extern "C" void kernel_launch(void* const* d_in, const int* in_sizes, int n_in,
                              void* d_out, int out_size) {
    const float* feats = (const float*)d_in[0];
    const int* labels = (const int*)d_in[1];
    (void)in_sizes; (void)n_in; (void)out_size;

    static int once = 0;
    if (!once) {
        cudaFuncSetAttribute(k_gemm, cudaFuncAttributeMaxDynamicSharedMemorySize, SMEM_BYTES);
        once = 1;
    }

    k_prep<<<512, 256>>>(feats);
    k_reduce_init<<<1, 512>>>();
    k_gemm<<<NTRI, 256, SMEM_BYTES>>>(labels);
    k_check<<<B_SZ / 256, 256>>>();
    k_fixup<<<64, 256>>>(labels);
    k_final<<<1, 256>>>((float*)d_out);
}

// round 6
// speedup vs baseline: 3.8063x; 1.2306x over previous
#include <cuda_runtime.h>
#include <cuda_bf16.h>
#include <cstdint>
#include <cstddef>

#define B_SZ 8192
#define D_SZ 512
#define MARGIN 0.1f

#define BM 128
#define BN 128
#define BK 32
#define PADW 20
#define NBLK 64
#define NTRI 2080

#define SM_A(s)  ((s) * 5120)
#define SM_B(s)  ((s) * 5120 + 2560)
#define SMEM_BYTES 61440

// ---------------- device scratch ----------------
static __device__ __nv_bfloat16 g_fbf[B_SZ * D_SZ];   // bf16 feats (fallback GEMM)
static __device__ float    g_sp[B_SZ];                // fallback accumulators
static __device__ float    g_sn[B_SZ];
static __device__ unsigned g_minpos[B_SZ];
static __device__ unsigned g_maxneg[B_SZ];
static __device__ unsigned g_gmaxpos;
static __device__ unsigned g_gminneg;
static __device__ float    g_enorm_part[256];
static __device__ float    g_end_norm;
static __device__ float    g_invE;
static __device__ float    g_rowloss[B_SZ];
static __device__ int      g_fixlist[B_SZ];
static __device__ int      g_nfix;
// fast-path state
static __device__ float    g_cpart[512 * 256];        // [dim][cta] partial sums of C
static __device__ float    g_C[512];                  // global feature sum
static __device__ float    g_cent[100 * 512];         // class centroids
static __device__ int      g_perm[B_SZ];
static __device__ int      g_off[101];
static __device__ int      g_cntg[100];
static __device__ unsigned g_maxn;                    // fenc(max row norm^2), idempotent
static __device__ int      g_fast;
static __device__ int      g_zero;

// order-preserving float<->uint encoding
__device__ __forceinline__ unsigned fenc(float f) {
    unsigned u = __float_as_uint(f);
    return (u & 0x80000000u) ? ~u : (u | 0x80000000u);
}
__device__ __forceinline__ float fdec(unsigned u) {
    return (u & 0x80000000u) ? __uint_as_float(u ^ 0x80000000u) : __uint_as_float(~u);
}

// ================= K1: norms + bf16 convert + C partials =================
__global__ __launch_bounds__(256) void k_prep(const float* __restrict__ feats) {
    __shared__ float sC[512];
    __shared__ float eW[8], mW[8];
    const int tid = threadIdx.x, lane = tid & 31, warp = tid >> 5;
    sC[tid] = 0.f; sC[tid + 256] = 0.f;
    __syncthreads();

    const float4* f4 = reinterpret_cast<const float4*>(feats);
    const int row0 = blockIdx.x * 32 + warp * 4;
    float cacc[16];
#pragma unroll
    for (int e = 0; e < 16; ++e) cacc[e] = 0.f;
    float esum = 0.f, mmax = 0.f;

#pragma unroll
    for (int rr = 0; rr < 4; ++rr) {
        const int row = row0 + rr;
        float rsq = 0.f;
#pragma unroll
        for (int it = 0; it < 4; ++it) {
            float4 v = f4[(size_t)row * 128 + it * 32 + lane];
            rsq += v.x * v.x + v.y * v.y + v.z * v.z + v.w * v.w;
            cacc[it * 4 + 0] += v.x; cacc[it * 4 + 1] += v.y;
            cacc[it * 4 + 2] += v.z; cacc[it * 4 + 3] += v.w;
            __nv_bfloat162 lo = __floats2bfloat162_rn(v.x, v.y);
            __nv_bfloat162 hi = __floats2bfloat162_rn(v.z, v.w);
            uint2 o;
            o.x = *reinterpret_cast<unsigned*>(&lo);
            o.y = *reinterpret_cast<unsigned*>(&hi);
            reinterpret_cast<uint2*>(g_fbf)[(size_t)row * 128 + it * 32 + lane] = o;
        }
#pragma unroll
        for (int o = 16; o > 0; o >>= 1) rsq += __shfl_xor_sync(0xffffffffu, rsq, o);
        if (lane == 0) esum += rsq;
        mmax = fmaxf(mmax, rsq);
    }
#pragma unroll
    for (int it = 0; it < 4; ++it)
#pragma unroll
        for (int e = 0; e < 4; ++e)
            atomicAdd(&sC[it * 128 + lane * 4 + e], cacc[it * 4 + e]);
    if (lane == 0) { eW[warp] = esum; mW[warp] = mmax; }
    __syncthreads();
    if (tid == 0) {
        float E = 0.f, m = 0.f;
#pragma unroll
        for (int w = 0; w < 8; ++w) { E += eW[w]; m = fmaxf(m, mW[w]); }
        g_enorm_part[blockIdx.x] = E;
        atomicMax(&g_maxn, fenc(m));
    }
    __syncthreads();
    g_cpart[(size_t)tid * 256 + blockIdx.x] = sC[tid];
    g_cpart[(size_t)(tid + 256) * 256 + blockIdx.x] = sC[tid + 256];
}

// ================= K2: verify + histogram + perm + C reduce =================
__global__ __launch_bounds__(512) void k_verify(const int* __restrict__ labels) {
    __shared__ float red[256];
    __shared__ int cnt[100], off[101];
    __shared__ unsigned offa[100];
    const int t = threadIdx.x;

    if (t < 256) red[t] = g_enorm_part[t];
    if (t < 100) cnt[t] = 0;
    __syncthreads();
    for (int o = 128; o > 0; o >>= 1) {
        if (t < o) red[t] += red[t + o];
        __syncthreads();
    }
    for (int i = t; i < B_SZ; i += 512) atomicAdd(&cnt[labels[i]], 1);
    __syncthreads();
    if (t == 0) {
        int acc = 0;
        for (int l = 0; l < 100; ++l) { off[l] = acc; acc += cnt[l]; }
        off[100] = acc;
    }
    __syncthreads();
    if (t < 100) { offa[t] = (unsigned)off[t]; g_cntg[t] = cnt[t]; g_off[t] = off[t]; }
    if (t == 100) g_off[100] = B_SZ;
    __syncthreads();
    for (int i = t; i < B_SZ; i += 512) {
        int l = labels[i];
        unsigned p = atomicAdd(&offa[l], 1u);
        g_perm[p] = i;
    }
    // reduce global feature sum C
    {
        const float* p = g_cpart + (size_t)t * 256;
        float s = 0.f;
#pragma unroll 8
        for (int c = 0; c < 256; ++c) s += p[c];
        g_C[t] = s;
    }
    if (t == 0) {
        float E = red[0];
        float M2 = __uint_as_float(g_maxn & 0x7fffffffu);   // decode fenc of positive
        float Mp = (E > 0.f) ? M2 / E : 1.f;                // rigorous bound on |sim|
        int mxc = 0;
        for (int l = 0; l < 100; ++l) mxc = max(mxc, cnt[l]);
        int zero = (mxc == B_SZ) ? 1 : 0;
        int fast = (E > 0.f) && (2.f * Mp < MARGIN * 0.9f) &&
                   (2.1f * (float)B_SZ * Mp * Mp < 1e-3f) && !zero;
        g_zero = zero;
        g_fast = fast ? 1 : 0;
        g_end_norm = E;
        g_invE = (E > 0.f) ? 1.f / E : 0.f;
        g_nfix = 0;
        g_gmaxpos = 0x007FFFFFu;
        g_gminneg = 0xFF800000u;
    }
    __syncthreads();
    if (!g_fast && !g_zero) {   // init fallback accumulators
        for (int i = t; i < B_SZ; i += 512) {
            g_sp[i] = 0.f; g_sn[i] = 0.f;
            g_minpos[i] = 0xFF800000u;
            g_maxneg[i] = 0x007FFFFFu;
        }
    }
}

// ================= K3: class centroids =================
__global__ __launch_bounds__(256) void k_cent(const float* __restrict__ feats) {
    if (!g_fast) return;
    const int l = blockIdx.x;
    const int start = g_off[l], n = g_cntg[l];
    const float2* f2 = reinterpret_cast<const float2*>(feats);
    const int d = threadIdx.x;
    float ax = 0.f, ay = 0.f;
#pragma unroll 4
    for (int k = 0; k < n; ++k) {
        int row = __ldg(&g_perm[start + k]);
        float2 v = f2[(size_t)row * 256 + d];
        ax += v.x; ay += v.y;
    }
    reinterpret_cast<float2*>(g_cent)[l * 256 + d] = make_float2(ax, ay);
}

// ================= K4: per-row analytic loss =================
__global__ __launch_bounds__(256) void k_row(const float* __restrict__ feats,
                                             const int* __restrict__ labels) {
    const int warp = threadIdx.x >> 5, lane = threadIdx.x & 31;
    const int row = blockIdx.x * 8 + warp;
    if (g_zero) { if (lane == 0) g_rowloss[row] = 0.f; return; }
    if (!g_fast) return;

    const int lab = labels[row];
    const float4* fr = reinterpret_cast<const float4*>(feats) + (size_t)row * 128;
    const float4* cl = reinterpret_cast<const float4*>(g_cent) + lab * 128;
    const float4* CC = reinterpret_cast<const float4*>(g_C);
    float dp = 0.f, da = 0.f;
#pragma unroll
    for (int it = 0; it < 4; ++it) {
        float4 a = fr[it * 32 + lane];
        float4 b = cl[it * 32 + lane];
        float4 c = CC[it * 32 + lane];
        dp = fmaf(a.x, b.x, fmaf(a.y, b.y, fmaf(a.z, b.z, fmaf(a.w, b.w, dp))));
        da = fmaf(a.x, c.x, fmaf(a.y, c.y, fmaf(a.z, c.z, fmaf(a.w, c.w, da))));
    }
#pragma unroll
    for (int o = 16; o > 0; o >>= 1) {
        dp += __shfl_xor_sync(0xffffffffu, dp, o);
        da += __shfl_xor_sync(0xffffffffu, da, o);
    }
    if (lane == 0) {
        const float invE = g_invE;
        const float cntf = (float)g_cntg[lab];
        // sp = sum_{pos} e^{-2s} ~= n - 2*sum_pos s ;  sn = sum_{neg} e^{2s} ~= (B-n) + 2*sum_neg s
        float sp = cntf - 2.f * dp * invE;
        float sn = ((float)B_SZ - cntf) + 2.f * (da - dp) * invE;
        const float E1 = 2.718281828459045f;
        const float EINV = 0.36787944117144233f;
        float loss = 0.5f * log1pf(E1 * sp) + 0.5f * log1pf(EINV * sn);
        g_rowloss[row] = loss;
    }
}

// ================= fallback GEMM path (round-5, flag-guarded) =================
__device__ __forceinline__ void mma16816(float* d, const uint32_t* a, const uint32_t* b) {
    asm volatile(
        "mma.sync.aligned.m16n8k16.row.col.f32.bf16.bf16.f32 "
        "{%0,%1,%2,%3}, {%4,%5,%6,%7}, {%8,%9}, {%0,%1,%2,%3};\n"
        : "+f"(d[0]), "+f"(d[1]), "+f"(d[2]), "+f"(d[3])
        : "r"(a[0]), "r"(a[1]), "r"(a[2]), "r"(a[3]), "r"(b[0]), "r"(b[1]));
}
__device__ __forceinline__ void ldsm4(uint32_t* d, uint32_t saddr) {
    asm volatile("ldmatrix.sync.aligned.m8n8.x4.shared.b16 {%0,%1,%2,%3}, [%4];"
                 : "=r"(d[0]), "=r"(d[1]), "=r"(d[2]), "=r"(d[3]) : "r"(saddr));
}
__device__ __forceinline__ void cpa16(uint32_t saddr, const void* g) {
    asm volatile("cp.async.cg.shared.global [%0], [%1], 16;\n" :: "r"(saddr), "l"(g));
}
__device__ __forceinline__ void load_chunk(uint32_t sb, int stage, int kbase,
                                           int i0, int j0, int tid) {
    const int r = tid >> 2, q = tid & 3;
#pragma unroll
    for (int h = 0; h < 2; ++h) {
        int rr = r + h * 64;
        cpa16(sb + (SM_A(stage) + rr * PADW + q * 4) * 4,
              g_fbf + (size_t)(i0 + rr) * D_SZ + kbase + q * 8);
        cpa16(sb + (SM_B(stage) + rr * PADW + q * 4) * 4,
              g_fbf + (size_t)(j0 + rr) * D_SZ + kbase + q * 8);
    }
    asm volatile("cp.async.commit_group;\n" ::: "memory");
}
#define PROC(SRAW, LI, LJ, SP, SN, MN, MX, NT, H)                              \
    {                                                                          \
        float s_ = (SRAW) * inv;                                               \
        float s2_ = s_ * s_;                                                   \
        float even_ = fmaf(s2_, 2.f, 1.f);                                     \
        float odd_ = s_ * fmaf(s2_, 1.33333333f, 2.f);                         \
        if ((LI) == (LJ)) {                                                    \
            if (s_ < ONE_EPS) {                                                \
                float evp_ = even_ - odd_;                                     \
                SP += evp_; MN = fminf(MN, s_); gmx = fmaxf(gmx, s_);          \
                csp[NT][H] += evp_; cmnP[NT][H] = fminf(cmnP[NT][H], s_);      \
            }                                                                  \
        } else {                                                               \
            float evn_ = even_ + odd_;                                         \
            SN += evn_; MX = fmaxf(MX, s_); gmn = fminf(gmn, s_);              \
            csn[NT][H] += evn_; cmxN[NT][H] = fmaxf(cmxN[NT][H], s_);          \
        }                                                                      \
    }

__global__ void __launch_bounds__(256, 2) k_gemm_fb(const int* __restrict__ labels) {
    if (g_fast | g_zero) return;
    extern __shared__ uint32_t dsm[];
    const uint32_t sb = (uint32_t)__cvta_generic_to_shared(dsm);
    __shared__ int slabi[BM];
    __shared__ int slabj[BN];
    __shared__ float sredA[8], sredB[8];

    const int kb = blockIdx.x;
    int bi = (int)(64.5f - sqrtf(64.5f * 64.5f - 2.0f * (float)kb));
    if (bi < 0) bi = 0;
    if (bi > 63) bi = 63;
    while (bi > 0 && bi * NBLK - bi * (bi - 1) / 2 > kb) --bi;
    while ((bi + 1) * NBLK - (bi + 1) * bi / 2 <= kb) ++bi;
    const int bj = bi + (kb - (bi * NBLK - bi * (bi - 1) / 2));
    const int i0 = bi * BM, j0 = bj * BN;
    const bool offdiag = (bi != bj);

    const int tid = threadIdx.x, lane = tid & 31, warp = tid >> 5;
    const int wm = warp >> 2, wn = warp & 3;
    const int r4 = lane >> 2, cq = lane & 3;

    if (tid < BM) slabi[tid] = labels[i0 + tid];
    else if (tid < BM + BN) slabj[tid - BM] = labels[j0 + tid - BM];

    float acc[4][4][4];
#pragma unroll
    for (int mt = 0; mt < 4; ++mt)
#pragma unroll
        for (int nt = 0; nt < 4; ++nt)
#pragma unroll
            for (int e = 0; e < 4; ++e) acc[mt][nt][e] = 0.f;

    const int arow = wm * 64 + (lane & 15);
    const int akw  = (lane >> 4) * 4;
    const int awoff = arow * PADW + akw;
    const int brow = wn * 32 + (lane & 7) + ((lane >= 16) ? 8 : 0);
    const int bkw  = ((lane >> 3) & 1) * 4;
    const int bwoff = brow * PADW + bkw;

    const int NK = D_SZ / BK;
    load_chunk(sb, 0, 0, i0, j0, tid);
    load_chunk(sb, 1, BK, i0, j0, tid);

    for (int kt = 0; kt < NK; ++kt) {
        const int s = kt % 3;
        if (kt + 1 < NK) asm volatile("cp.async.wait_group 1;\n" ::: "memory");
        else             asm volatile("cp.async.wait_group 0;\n" ::: "memory");
        __syncthreads();
        if (kt + 2 < NK) load_chunk(sb, (kt + 2) % 3, (kt + 2) * BK, i0, j0, tid);
#pragma unroll
        for (int ks = 0; ks < 2; ++ks) {
            const int ko = ks * 8;
            uint32_t a[4][4], b[2][4];
#pragma unroll
            for (int mt = 0; mt < 4; ++mt)
                ldsm4(a[mt], sb + (SM_A(s) + awoff + mt * 16 * PADW + ko) * 4);
#pragma unroll
            for (int p = 0; p < 2; ++p)
                ldsm4(b[p], sb + (SM_B(s) + bwoff + p * 16 * PADW + ko) * 4);
#pragma unroll
            for (int mt = 0; mt < 4; ++mt)
#pragma unroll
                for (int nt = 0; nt < 4; ++nt) {
                    uint32_t bb[2] = {b[nt >> 1][(nt & 1) * 2], b[nt >> 1][(nt & 1) * 2 + 1]};
                    mma16816(acc[mt][nt], a[mt], bb);
                }
        }
    }

    const float inv = 1.0f / g_end_norm;
    const float ONE_EPS = 1.0f - 1e-5f;
    const float INF = __int_as_float(0x7f800000);
    float csp[4][2], csn[4][2], cmnP[4][2], cmxN[4][2];
#pragma unroll
    for (int nt = 0; nt < 4; ++nt)
#pragma unroll
        for (int h = 0; h < 2; ++h) {
            csp[nt][h] = 0.f; csn[nt][h] = 0.f;
            cmnP[nt][h] = INF; cmxN[nt][h] = -INF;
        }
    float gmx = -INF, gmn = INF;

#pragma unroll
    for (int mt = 0; mt < 4; ++mt) {
        const int lr0 = mt * 16 + r4, lr1 = lr0 + 8;
        const int li0 = slabi[wm * 64 + lr0], li1 = slabi[wm * 64 + lr1];
        const int gi0 = i0 + wm * 64 + lr0, gi1 = i0 + wm * 64 + lr1;
        float sp0 = 0.f, sn0 = 0.f, mn0 = INF, mx0 = -INF;
        float sp1 = 0.f, sn1 = 0.f, mn1 = INF, mx1 = -INF;
#pragma unroll
        for (int nt = 0; nt < 4; ++nt) {
            const int lc = nt * 8 + 2 * cq;
            const int lj0 = slabj[wn * 32 + lc], lj1 = slabj[wn * 32 + lc + 1];
            PROC(acc[mt][nt][0], li0, lj0, sp0, sn0, mn0, mx0, nt, 0);
            PROC(acc[mt][nt][1], li0, lj1, sp0, sn0, mn0, mx0, nt, 1);
            PROC(acc[mt][nt][2], li1, lj0, sp1, sn1, mn1, mx1, nt, 0);
            PROC(acc[mt][nt][3], li1, lj1, sp1, sn1, mn1, mx1, nt, 1);
        }
#pragma unroll
        for (int o = 1; o < 4; o <<= 1) {
            sp0 += __shfl_xor_sync(0xffffffffu, sp0, o);
            sn0 += __shfl_xor_sync(0xffffffffu, sn0, o);
            mn0 = fminf(mn0, __shfl_xor_sync(0xffffffffu, mn0, o));
            mx0 = fmaxf(mx0, __shfl_xor_sync(0xffffffffu, mx0, o));
            sp1 += __shfl_xor_sync(0xffffffffu, sp1, o);
            sn1 += __shfl_xor_sync(0xffffffffu, sn1, o);
            mn1 = fminf(mn1, __shfl_xor_sync(0xffffffffu, mn1, o));
            mx1 = fmaxf(mx1, __shfl_xor_sync(0xffffffffu, mx1, o));
        }
        if (cq == 0) {
            atomicAdd(&g_sp[gi0], sp0);
            atomicAdd(&g_sn[gi0], sn0);
            atomicMin(&g_minpos[gi0], fenc(mn0));
            atomicMax(&g_maxneg[gi0], fenc(mx0));
            atomicAdd(&g_sp[gi1], sp1);
            atomicAdd(&g_sn[gi1], sn1);
            atomicMin(&g_minpos[gi1], fenc(mn1));
            atomicMax(&g_maxneg[gi1], fenc(mx1));
        }
    }
    if (offdiag) {
#pragma unroll
        for (int nt = 0; nt < 4; ++nt)
#pragma unroll
            for (int h = 0; h < 2; ++h) {
#pragma unroll
                for (int o = 4; o < 32; o <<= 1) {
                    csp[nt][h] += __shfl_xor_sync(0xffffffffu, csp[nt][h], o);
                    csn[nt][h] += __shfl_xor_sync(0xffffffffu, csn[nt][h], o);
                    cmnP[nt][h] = fminf(cmnP[nt][h], __shfl_xor_sync(0xffffffffu, cmnP[nt][h], o));
                    cmxN[nt][h] = fmaxf(cmxN[nt][h], __shfl_xor_sync(0xffffffffu, cmxN[nt][h], o));
                }
            }
        if (r4 == 0) {
#pragma unroll
            for (int nt = 0; nt < 4; ++nt) {
                const int gj = j0 + wn * 32 + nt * 8 + 2 * cq;
                atomicAdd(&g_sp[gj], csp[nt][0]);
                atomicAdd(&g_sn[gj], csn[nt][0]);
                atomicMin(&g_minpos[gj], fenc(cmnP[nt][0]));
                atomicMax(&g_maxneg[gj], fenc(cmxN[nt][0]));
                atomicAdd(&g_sp[gj + 1], csp[nt][1]);
                atomicAdd(&g_sn[gj + 1], csn[nt][1]);
                atomicMin(&g_minpos[gj + 1], fenc(cmnP[nt][1]));
                atomicMax(&g_maxneg[gj + 1], fenc(cmxN[nt][1]));
            }
        }
    }
#pragma unroll
    for (int o = 16; o > 0; o >>= 1) {
        gmx = fmaxf(gmx, __shfl_xor_sync(0xffffffffu, gmx, o));
        gmn = fminf(gmn, __shfl_xor_sync(0xffffffffu, gmn, o));
    }
    if (lane == 0) { sredA[warp] = gmx; sredB[warp] = gmn; }
    __syncthreads();
    if (tid == 0) {
        float a = sredA[0], b = sredB[0];
#pragma unroll
        for (int w = 1; w < 8; ++w) { a = fmaxf(a, sredA[w]); b = fminf(b, sredB[w]); }
        atomicMax(&g_gmaxpos, fenc(a));
        atomicMin(&g_gminneg, fenc(b));
    }
}

__global__ __launch_bounds__(256) void k_check_fb() {
    if (g_fast | g_zero) return;
    const int r = blockIdx.x * 256 + threadIdx.x;
    const float minpos = fdec(g_minpos[r]);
    const float maxneg = fdec(g_maxneg[r]);
    const float gmaxP = fdec(g_gmaxpos);
    const float gminN = fdec(g_gminneg);
    const bool okP = (gmaxP - MARGIN < maxneg);
    const bool okN = (gminN + MARGIN > minpos);
    if (okP && okN) {
        float loss = 0.f;
        float sp = g_sp[r], sn = g_sn[r];
        if (sp > 0.f && sn > 0.f) {
            const float E1 = 2.718281828459045f;
            const float EINV = 0.36787944117144233f;
            loss = 0.5f * log1pf(E1 * sp) + 0.5f * log1pf(EINV * sn);
        }
        g_rowloss[r] = loss;
    } else {
        g_rowloss[r] = 0.f;
        int idx = atomicAdd(&g_nfix, 1);
        g_fixlist[idx] = r;
    }
}

__global__ __launch_bounds__(256) void k_fixup_fb(const int* __restrict__ labels) {
    if (g_fast | g_zero) return;
    __shared__ float fr[D_SZ];
    __shared__ float redp[256], redn[256];
    const int n = g_nfix;
    for (int w = blockIdx.x; w < n; w += gridDim.x) {
        const int r = g_fixlist[w];
        for (int k = threadIdx.x; k < D_SZ; k += 256)
            fr[k] = __bfloat162float(g_fbf[(size_t)r * D_SZ + k]);
        __syncthreads();
        const float inv = 1.0f / g_end_norm;
        const float minpos = fdec(g_minpos[r]);
        const float maxneg = fdec(g_maxneg[r]);
        const int lr = labels[r];
        const float ONE_EPS = 1.0f - 1e-5f;
        float sp = 0.f, sn = 0.f;
        for (int j = threadIdx.x; j < B_SZ; j += 256) {
            const __nv_bfloat162* fj =
                reinterpret_cast<const __nv_bfloat162*>(g_fbf + (size_t)j * D_SZ);
            float d = 0.f;
            for (int k = 0; k < D_SZ / 2; ++k) {
                float2 v = __bfloat1622float2(fj[k]);
                d = fmaf(fr[2 * k], v.x, d);
                d = fmaf(fr[2 * k + 1], v.y, d);
            }
            float s = d * inv;
            if (labels[j] == lr) {
                if (s < ONE_EPS && (s - MARGIN < maxneg)) sp += __expf(-2.f * (s - 0.5f));
            } else if (s + MARGIN > minpos) {
                sn += __expf(2.f * (s - 0.5f));
            }
        }
        redp[threadIdx.x] = sp;
        redn[threadIdx.x] = sn;
        __syncthreads();
        for (int o = 128; o > 0; o >>= 1) {
            if (threadIdx.x < o) {
                redp[threadIdx.x] += redp[threadIdx.x + o];
                redn[threadIdx.x] += redn[threadIdx.x + o];
            }
            __syncthreads();
        }
        if (threadIdx.x == 0) {
            float loss = 0.f;
            if (redp[0] > 0.f && redn[0] > 0.f)
                loss = 0.5f * log1pf(redp[0]) + 0.5f * log1pf(redn[0]);
            g_rowloss[r] = loss;
        }
        __syncthreads();
    }
}

// ================= final reduction =================
__global__ __launch_bounds__(256) void k_final(float* __restrict__ out) {
    __shared__ float red[256];
    float s = 0.f;
    for (int i = threadIdx.x; i < B_SZ; i += 256) s += g_rowloss[i];
    red[threadIdx.x] = s;
    __syncthreads();
    for (int o = 128; o > 0; o >>= 1) {
        if (threadIdx.x < o) red[threadIdx.x] += red[threadIdx.x + o];
        __syncthreads();
    }
    if (threadIdx.x == 0) out[0] = red[0] * (1.0f / B_SZ);
}

// ================= launch =================
extern "C" void kernel_launch(void* const* d_in, const int* in_sizes, int n_in,
                              void* d_out, int out_size) {
    const float* feats = (const float*)d_in[0];
    const int* labels = (const int*)d_in[1];
    (void)in_sizes; (void)n_in; (void)out_size;

    static int once = 0;
    if (!once) {
        cudaFuncSetAttribute(k_gemm_fb, cudaFuncAttributeMaxDynamicSharedMemorySize, SMEM_BYTES);
        once = 1;
    }

    k_prep<<<256, 256>>>(feats);
    k_verify<<<1, 512>>>(labels);
    k_cent<<<100, 256>>>(feats);
    k_row<<<B_SZ / 8, 256>>>(feats, labels);
    k_gemm_fb<<<NTRI, 256, SMEM_BYTES>>>(labels);
    k_check_fb<<<B_SZ / 256, 256>>>();
    k_fixup_fb<<<64, 256>>>(labels);
    k_final<<<1, 256>>>((float*)d_out);
}

// round 8
// speedup vs baseline: 10.2300x; 2.6877x over previous
#include <cuda_runtime.h>
#include <cuda_bf16.h>
#include <cstdint>
#include <cstddef>

#define B_SZ 8192
#define D_SZ 512
#define MARGIN 0.1f

#define BM 128
#define BN 128
#define BK 32
#define PADW 20
#define NBLK 64
#define NTRI 2080

#define SM_A(s)  ((s) * 5120)
#define SM_B(s)  ((s) * 5120 + 2560)
#define SMEM_BYTES 61440

// ---------------- device scratch ----------------
static __device__ __nv_bfloat16 g_fbf[B_SZ * D_SZ];   // bf16 feats (fallback only)
static __device__ float    g_sp[B_SZ];
static __device__ float    g_sn[B_SZ];
static __device__ unsigned g_minpos[B_SZ];
static __device__ unsigned g_maxneg[B_SZ];
static __device__ unsigned g_gmaxpos;
static __device__ unsigned g_gminneg;
static __device__ float    g_enorm_part[256];
static __device__ float    g_end_norm;
static __device__ float    g_invE;
static __device__ float    g_rowloss[B_SZ];
static __device__ int      g_fixlist[B_SZ];
static __device__ int      g_nfix;
// fast-path state
static __device__ float    g_cpart[256 * 512];        // [cta][dim] partial sums of C
static __device__ float    g_C[512];
static __device__ float    g_cent[100 * 512];
static __device__ int      g_perm[B_SZ];
static __device__ int      g_off[101];
static __device__ int      g_cntg[100];
static __device__ unsigned g_maxn;                    // idempotent across replays
static __device__ int      g_fast;
static __device__ int      g_zero;

__device__ __forceinline__ unsigned fenc(float f) {
    unsigned u = __float_as_uint(f);
    return (u & 0x80000000u) ? ~u : (u | 0x80000000u);
}
__device__ __forceinline__ float fdec(unsigned u) {
    return (u & 0x80000000u) ? __uint_as_float(u ^ 0x80000000u) : __uint_as_float(~u);
}

// ================= K1: norms + max norm + C partials =================
__global__ __launch_bounds__(256) void k_prep(const float* __restrict__ feats) {
    __shared__ float sC[512];
    __shared__ float eW[8], mW[8];
    const int tid = threadIdx.x, lane = tid & 31, warp = tid >> 5;
    sC[tid] = 0.f; sC[tid + 256] = 0.f;
    __syncthreads();

    const float4* f4 = reinterpret_cast<const float4*>(feats);
    const int row0 = blockIdx.x * 32 + warp * 4;
    float cacc[16];
#pragma unroll
    for (int e = 0; e < 16; ++e) cacc[e] = 0.f;
    float esum = 0.f, mmax = 0.f;

#pragma unroll
    for (int rr = 0; rr < 4; ++rr) {
        const int row = row0 + rr;
        float rsq = 0.f;
#pragma unroll
        for (int it = 0; it < 4; ++it) {
            float4 v = f4[(size_t)row * 128 + it * 32 + lane];
            rsq += v.x * v.x + v.y * v.y + v.z * v.z + v.w * v.w;
            cacc[it * 4 + 0] += v.x; cacc[it * 4 + 1] += v.y;
            cacc[it * 4 + 2] += v.z; cacc[it * 4 + 3] += v.w;
        }
#pragma unroll
        for (int o = 16; o > 0; o >>= 1) rsq += __shfl_xor_sync(0xffffffffu, rsq, o);
        if (lane == 0) esum += rsq;
        mmax = fmaxf(mmax, rsq);
    }
#pragma unroll
    for (int it = 0; it < 4; ++it)
#pragma unroll
        for (int e = 0; e < 4; ++e)
            atomicAdd(&sC[it * 128 + lane * 4 + e], cacc[it * 4 + e]);
    if (lane == 0) { eW[warp] = esum; mW[warp] = mmax; }
    __syncthreads();
    if (tid == 0) {
        float E = 0.f, m = 0.f;
#pragma unroll
        for (int w = 0; w < 8; ++w) { E += eW[w]; m = fmaxf(m, mW[w]); }
        g_enorm_part[blockIdx.x] = E;
        atomicMax(&g_maxn, fenc(m));
    }
    __syncthreads();
    g_cpart[(size_t)blockIdx.x * 512 + tid] = sC[tid];
    g_cpart[(size_t)blockIdx.x * 512 + tid + 256] = sC[tid + 256];
}

// ================= K2: verify + histogram + perm =================
__global__ __launch_bounds__(512) void k_verify(const int* __restrict__ labels) {
    __shared__ float red[256];
    __shared__ int cnt[100], off[101];
    __shared__ unsigned offa[100];
    const int t = threadIdx.x;

    if (t < 256) red[t] = g_enorm_part[t];
    if (t < 100) cnt[t] = 0;
    __syncthreads();
    for (int o = 128; o > 0; o >>= 1) {
        if (t < o) red[t] += red[t + o];
        __syncthreads();
    }
    for (int i = t; i < B_SZ; i += 512) atomicAdd(&cnt[labels[i]], 1);
    __syncthreads();
    if (t == 0) {
        int acc = 0;
        for (int l = 0; l < 100; ++l) { off[l] = acc; acc += cnt[l]; }
        off[100] = acc;
    }
    __syncthreads();
    if (t < 100) { offa[t] = (unsigned)off[t]; g_cntg[t] = cnt[t]; g_off[t] = off[t]; }
    if (t == 100) g_off[100] = B_SZ;
    __syncthreads();
    for (int i = t; i < B_SZ; i += 512) {
        int l = labels[i];
        unsigned p = atomicAdd(&offa[l], 1u);
        g_perm[p] = i;
    }
    if (t == 0) {
        float E = red[0];
        float M2 = __uint_as_float(g_maxn & 0x7fffffffu);
        float Mp = (E > 0.f) ? M2 / E : 1.f;            // rigorous |sim| bound
        int mxc = 0;
        for (int l = 0; l < 100; ++l) mxc = max(mxc, cnt[l]);
        int zero = (mxc == B_SZ) ? 1 : 0;
        int fast = (E > 0.f) && (2.f * Mp < MARGIN * 0.9f) &&
                   (2.1f * (float)B_SZ * Mp * Mp < 1e-3f) && !zero;
        g_zero = zero;
        g_fast = fast ? 1 : 0;
        g_end_norm = E;
        g_invE = (E > 0.f) ? 1.f / E : 0.f;
        g_nfix = 0;
        g_gmaxpos = 0x007FFFFFu;
        g_gminneg = 0xFF800000u;
    }
    __syncthreads();
    if (!g_fast && !g_zero) {
        for (int i = t; i < B_SZ; i += 512) {
            g_sp[i] = 0.f; g_sn[i] = 0.f;
            g_minpos[i] = 0xFF800000u;
            g_maxneg[i] = 0x007FFFFFu;
        }
    }
}

// ================= K3: class centroids (blocks 0..99) + C reduce (blocks 100..103) =================
__global__ __launch_bounds__(256) void k_cent(const float* __restrict__ feats) {
    if (!g_fast) return;
    const int b = blockIdx.x, t = threadIdx.x;
    if (b < 100) {
        __shared__ int sperm[256];
        const int start = g_off[b], n = g_cntg[b];
        const float2* f2 = reinterpret_cast<const float2*>(feats);
        float ax = 0.f, ay = 0.f;
        for (int base = 0; base < n; base += 256) {
            const int m = min(256, n - base);
            if (t < m) sperm[t] = g_perm[start + base + t];
            __syncthreads();
#pragma unroll 4
            for (int k = 0; k < m; ++k) {
                int row = sperm[k];
                float2 v = f2[(size_t)row * 256 + t];
                ax += v.x; ay += v.y;
            }
            __syncthreads();
        }
        reinterpret_cast<float2*>(g_cent)[b * 256 + t] = make_float2(ax, ay);
    } else {
        __shared__ float sr[256];
        const int d = (b - 100) * 128 + (t & 127);
        const int half = t >> 7;
        float s = 0.f;
#pragma unroll 8
        for (int c = half * 128; c < half * 128 + 128; ++c)
            s += g_cpart[(size_t)c * 512 + d];
        sr[t] = s;
        __syncthreads();
        if (t < 128) g_C[d] = sr[t] + sr[t + 128];
    }
}

// ================= K4: per-row analytic loss (2 rows/warp, C in smem) =================
__global__ __launch_bounds__(256) void k_row(const float* __restrict__ feats,
                                             const int* __restrict__ labels) {
    __shared__ float Cs[512];
    const int t = threadIdx.x, warp = t >> 5, lane = t & 31;
    const int r0 = blockIdx.x * 16 + warp * 2, r1 = r0 + 1;
    if (g_zero) {
        if (lane == 0) { g_rowloss[r0] = 0.f; g_rowloss[r1] = 0.f; }
        return;
    }
    if (!g_fast) return;
    Cs[t] = g_C[t]; Cs[t + 256] = g_C[t + 256];
    __syncthreads();

    const int lab0 = __ldg(&labels[r0]), lab1 = __ldg(&labels[r1]);
    const float4* f0 = reinterpret_cast<const float4*>(feats) + (size_t)r0 * 128;
    const float4* f1 = reinterpret_cast<const float4*>(feats) + (size_t)r1 * 128;
    const float4* c0 = reinterpret_cast<const float4*>(g_cent) + lab0 * 128;
    const float4* c1 = reinterpret_cast<const float4*>(g_cent) + lab1 * 128;
    const float4* C4 = reinterpret_cast<const float4*>(Cs);

    float dp0 = 0.f, da0 = 0.f, dp1 = 0.f, da1 = 0.f;
#pragma unroll
    for (int it = 0; it < 4; ++it) {
        float4 a0 = f0[it * 32 + lane];
        float4 a1 = f1[it * 32 + lane];
        float4 b0 = c0[it * 32 + lane];
        float4 b1 = c1[it * 32 + lane];
        float4 cc = C4[it * 32 + lane];
        dp0 = fmaf(a0.x, b0.x, fmaf(a0.y, b0.y, fmaf(a0.z, b0.z, fmaf(a0.w, b0.w, dp0))));
        da0 = fmaf(a0.x, cc.x, fmaf(a0.y, cc.y, fmaf(a0.z, cc.z, fmaf(a0.w, cc.w, da0))));
        dp1 = fmaf(a1.x, b1.x, fmaf(a1.y, b1.y, fmaf(a1.z, b1.z, fmaf(a1.w, b1.w, dp1))));
        da1 = fmaf(a1.x, cc.x, fmaf(a1.y, cc.y, fmaf(a1.z, cc.z, fmaf(a1.w, cc.w, da1))));
    }
#pragma unroll
    for (int o = 16; o > 0; o >>= 1) {
        dp0 += __shfl_xor_sync(0xffffffffu, dp0, o);
        da0 += __shfl_xor_sync(0xffffffffu, da0, o);
        dp1 += __shfl_xor_sync(0xffffffffu, dp1, o);
        da1 += __shfl_xor_sync(0xffffffffu, da1, o);
    }
    if (lane == 0) {
        const float invE = g_invE;
        const float E1 = 2.718281828459045f;
        const float EINV = 0.36787944117144233f;
        float n0 = (float)g_cntg[lab0];
        float sp0 = n0 - 2.f * dp0 * invE;
        float sn0 = ((float)B_SZ - n0) + 2.f * (da0 - dp0) * invE;
        g_rowloss[r0] = 0.5f * log1pf(E1 * sp0) + 0.5f * log1pf(EINV * sn0);
        float n1 = (float)g_cntg[lab1];
        float sp1 = n1 - 2.f * dp1 * invE;
        float sn1 = ((float)B_SZ - n1) + 2.f * (da1 - dp1) * invE;
        g_rowloss[r1] = 0.5f * log1pf(E1 * sp1) + 0.5f * log1pf(EINV * sn1);
    }
}

// ================= K5: fp32->bf16 convert (fallback only) =================
__global__ __launch_bounds__(256) void k_conv(const float* __restrict__ feats) {
    if (g_fast | g_zero) return;
    const int n4 = B_SZ * D_SZ / 4;
    const float4* f4 = reinterpret_cast<const float4*>(feats);
    for (int i = blockIdx.x * blockDim.x + threadIdx.x; i < n4; i += gridDim.x * blockDim.x) {
        float4 v = f4[i];
        __nv_bfloat162 lo = __floats2bfloat162_rn(v.x, v.y);
        __nv_bfloat162 hi = __floats2bfloat162_rn(v.z, v.w);
        uint2 o;
        o.x = *reinterpret_cast<unsigned*>(&lo);
        o.y = *reinterpret_cast<unsigned*>(&hi);
        reinterpret_cast<uint2*>(g_fbf)[i] = o;
    }
}

// ================= fallback GEMM (persistent, flag-guarded) =================
__device__ __forceinline__ void mma16816(float* d, const uint32_t* a, const uint32_t* b) {
    asm volatile(
        "mma.sync.aligned.m16n8k16.row.col.f32.bf16.bf16.f32 "
        "{%0,%1,%2,%3}, {%4,%5,%6,%7}, {%8,%9}, {%0,%1,%2,%3};\n"
        : "+f"(d[0]), "+f"(d[1]), "+f"(d[2]), "+f"(d[3])
        : "r"(a[0]), "r"(a[1]), "r"(a[2]), "r"(a[3]), "r"(b[0]), "r"(b[1]));
}
__device__ __forceinline__ void ldsm4(uint32_t* d, uint32_t saddr) {
    asm volatile("ldmatrix.sync.aligned.m8n8.x4.shared.b16 {%0,%1,%2,%3}, [%4];"
                 : "=r"(d[0]), "=r"(d[1]), "=r"(d[2]), "=r"(d[3]) : "r"(saddr));
}
__device__ __forceinline__ void cpa16(uint32_t saddr, const void* g) {
    asm volatile("cp.async.cg.shared.global [%0], [%1], 16;\n" :: "r"(saddr), "l"(g));
}
__device__ __forceinline__ void load_chunk(uint32_t sb, int stage, int kbase,
                                           int i0, int j0, int tid) {
    const int r = tid >> 2, q = tid & 3;
#pragma unroll
    for (int h = 0; h < 2; ++h) {
        int rr = r + h * 64;
        cpa16(sb + (SM_A(stage) + rr * PADW + q * 4) * 4,
              g_fbf + (size_t)(i0 + rr) * D_SZ + kbase + q * 8);
        cpa16(sb + (SM_B(stage) + rr * PADW + q * 4) * 4,
              g_fbf + (size_t)(j0 + rr) * D_SZ + kbase + q * 8);
    }
    asm volatile("cp.async.commit_group;\n" ::: "memory");
}
#define PROC(SRAW, LI, LJ, SP, SN, MN, MX, NT, H)                              \
    {                                                                          \
        float s_ = (SRAW) * inv;                                               \
        float s2_ = s_ * s_;                                                   \
        float even_ = fmaf(s2_, 2.f, 1.f);                                     \
        float odd_ = s_ * fmaf(s2_, 1.33333333f, 2.f);                         \
        if ((LI) == (LJ)) {                                                    \
            if (s_ < ONE_EPS) {                                                \
                float evp_ = even_ - odd_;                                     \
                SP += evp_; MN = fminf(MN, s_); gmx = fmaxf(gmx, s_);          \
                csp[NT][H] += evp_; cmnP[NT][H] = fminf(cmnP[NT][H], s_);      \
            }                                                                  \
        } else {                                                               \
            float evn_ = even_ + odd_;                                         \
            SN += evn_; MX = fmaxf(MX, s_); gmn = fminf(gmn, s_);              \
            csn[NT][H] += evn_; cmxN[NT][H] = fmaxf(cmxN[NT][H], s_);          \
        }                                                                      \
    }

__global__ void __launch_bounds__(256, 2) k_gemm_fb(const int* __restrict__ labels) {
    if (g_fast | g_zero) return;
    extern __shared__ uint32_t dsm[];
    const uint32_t sb = (uint32_t)__cvta_generic_to_shared(dsm);
    __shared__ int slabi[BM];
    __shared__ int slabj[BN];
    __shared__ float sredA[8], sredB[8];

    const int tid = threadIdx.x, lane = tid & 31, warp = tid >> 5;
    const int wm = warp >> 2, wn = warp & 3;
    const int r4 = lane >> 2, cq = lane & 3;
    const int arow = wm * 64 + (lane & 15);
    const int akw  = (lane >> 4) * 4;
    const int awoff = arow * PADW + akw;
    const int brow = wn * 32 + (lane & 7) + ((lane >= 16) ? 8 : 0);
    const int bkw  = ((lane >> 3) & 1) * 4;
    const int bwoff = brow * PADW + bkw;

    for (int kb = blockIdx.x; kb < NTRI; kb += gridDim.x) {
        __syncthreads();   // protect slab/smem reuse across tiles
        int bi = (int)(64.5f - sqrtf(64.5f * 64.5f - 2.0f * (float)kb));
        if (bi < 0) bi = 0;
        if (bi > 63) bi = 63;
        while (bi > 0 && bi * NBLK - bi * (bi - 1) / 2 > kb) --bi;
        while ((bi + 1) * NBLK - (bi + 1) * bi / 2 <= kb) ++bi;
        const int bj = bi + (kb - (bi * NBLK - bi * (bi - 1) / 2));
        const int i0 = bi * BM, j0 = bj * BN;
        const bool offdiag = (bi != bj);

        if (tid < BM) slabi[tid] = labels[i0 + tid];
        else if (tid < BM + BN) slabj[tid - BM] = labels[j0 + tid - BM];

        float acc[4][4][4];
#pragma unroll
        for (int mt = 0; mt < 4; ++mt)
#pragma unroll
            for (int nt = 0; nt < 4; ++nt)
#pragma unroll
                for (int e = 0; e < 4; ++e) acc[mt][nt][e] = 0.f;

        const int NK = D_SZ / BK;
        load_chunk(sb, 0, 0, i0, j0, tid);
        load_chunk(sb, 1, BK, i0, j0, tid);

        for (int kt = 0; kt < NK; ++kt) {
            const int s = kt % 3;
            if (kt + 1 < NK) asm volatile("cp.async.wait_group 1;\n" ::: "memory");
            else             asm volatile("cp.async.wait_group 0;\n" ::: "memory");
            __syncthreads();
            if (kt + 2 < NK) load_chunk(sb, (kt + 2) % 3, (kt + 2) * BK, i0, j0, tid);
#pragma unroll
            for (int ks = 0; ks < 2; ++ks) {
                const int ko = ks * 8;
                uint32_t a[4][4], b[2][4];
#pragma unroll
                for (int mt = 0; mt < 4; ++mt)
                    ldsm4(a[mt], sb + (SM_A(s) + awoff + mt * 16 * PADW + ko) * 4);
#pragma unroll
                for (int p = 0; p < 2; ++p)
                    ldsm4(b[p], sb + (SM_B(s) + bwoff + p * 16 * PADW + ko) * 4);
#pragma unroll
                for (int mt = 0; mt < 4; ++mt)
#pragma unroll
                    for (int nt = 0; nt < 4; ++nt) {
                        uint32_t bb[2] = {b[nt >> 1][(nt & 1) * 2], b[nt >> 1][(nt & 1) * 2 + 1]};
                        mma16816(acc[mt][nt], a[mt], bb);
                    }
            }
        }

        const float inv = 1.0f / g_end_norm;
        const float ONE_EPS = 1.0f - 1e-5f;
        const float INF = __int_as_float(0x7f800000);
        float csp[4][2], csn[4][2], cmnP[4][2], cmxN[4][2];
#pragma unroll
        for (int nt = 0; nt < 4; ++nt)
#pragma unroll
            for (int h = 0; h < 2; ++h) {
                csp[nt][h] = 0.f; csn[nt][h] = 0.f;
                cmnP[nt][h] = INF; cmxN[nt][h] = -INF;
            }
        float gmx = -INF, gmn = INF;

#pragma unroll
        for (int mt = 0; mt < 4; ++mt) {
            const int lr0 = mt * 16 + r4, lr1 = lr0 + 8;
            const int li0 = slabi[wm * 64 + lr0], li1 = slabi[wm * 64 + lr1];
            const int gi0 = i0 + wm * 64 + lr0, gi1 = i0 + wm * 64 + lr1;
            float sp0 = 0.f, sn0 = 0.f, mn0 = INF, mx0 = -INF;
            float sp1 = 0.f, sn1 = 0.f, mn1 = INF, mx1 = -INF;
#pragma unroll
            for (int nt = 0; nt < 4; ++nt) {
                const int lc = nt * 8 + 2 * cq;
                const int lj0 = slabj[wn * 32 + lc], lj1 = slabj[wn * 32 + lc + 1];
                PROC(acc[mt][nt][0], li0, lj0, sp0, sn0, mn0, mx0, nt, 0);
                PROC(acc[mt][nt][1], li0, lj1, sp0, sn0, mn0, mx0, nt, 1);
                PROC(acc[mt][nt][2], li1, lj0, sp1, sn1, mn1, mx1, nt, 0);
                PROC(acc[mt][nt][3], li1, lj1, sp1, sn1, mn1, mx1, nt, 1);
            }
#pragma unroll
            for (int o = 1; o < 4; o <<= 1) {
                sp0 += __shfl_xor_sync(0xffffffffu, sp0, o);
                sn0 += __shfl_xor_sync(0xffffffffu, sn0, o);
                mn0 = fminf(mn0, __shfl_xor_sync(0xffffffffu, mn0, o));
                mx0 = fmaxf(mx0, __shfl_xor_sync(0xffffffffu, mx0, o));
                sp1 += __shfl_xor_sync(0xffffffffu, sp1, o);
                sn1 += __shfl_xor_sync(0xffffffffu, sn1, o);
                mn1 = fminf(mn1, __shfl_xor_sync(0xffffffffu, mn1, o));
                mx1 = fmaxf(mx1, __shfl_xor_sync(0xffffffffu, mx1, o));
            }
            if (cq == 0) {
                atomicAdd(&g_sp[gi0], sp0);
                atomicAdd(&g_sn[gi0], sn0);
                atomicMin(&g_minpos[gi0], fenc(mn0));
                atomicMax(&g_maxneg[gi0], fenc(mx0));
                atomicAdd(&g_sp[gi1], sp1);
                atomicAdd(&g_sn[gi1], sn1);
                atomicMin(&g_minpos[gi1], fenc(mn1));
                atomicMax(&g_maxneg[gi1], fenc(mx1));
            }
        }
        if (offdiag) {
#pragma unroll
            for (int nt = 0; nt < 4; ++nt)
#pragma unroll
                for (int h = 0; h < 2; ++h) {
#pragma unroll
                    for (int o = 4; o < 32; o <<= 1) {
                        csp[nt][h] += __shfl_xor_sync(0xffffffffu, csp[nt][h], o);
                        csn[nt][h] += __shfl_xor_sync(0xffffffffu, csn[nt][h], o);
                        cmnP[nt][h] = fminf(cmnP[nt][h], __shfl_xor_sync(0xffffffffu, cmnP[nt][h], o));
                        cmxN[nt][h] = fmaxf(cmxN[nt][h], __shfl_xor_sync(0xffffffffu, cmxN[nt][h], o));
                    }
                }
            if (r4 == 0) {
#pragma unroll
                for (int nt = 0; nt < 4; ++nt) {
                    const int gj = j0 + wn * 32 + nt * 8 + 2 * cq;
                    atomicAdd(&g_sp[gj], csp[nt][0]);
                    atomicAdd(&g_sn[gj], csn[nt][0]);
                    atomicMin(&g_minpos[gj], fenc(cmnP[nt][0]));
                    atomicMax(&g_maxneg[gj], fenc(cmxN[nt][0]));
                    atomicAdd(&g_sp[gj + 1], csp[nt][1]);
                    atomicAdd(&g_sn[gj + 1], csn[nt][1]);
                    atomicMin(&g_minpos[gj + 1], fenc(cmnP[nt][1]));
                    atomicMax(&g_maxneg[gj + 1], fenc(cmxN[nt][1]));
                }
            }
        }
#pragma unroll
        for (int o = 16; o > 0; o >>= 1) {
            gmx = fmaxf(gmx, __shfl_xor_sync(0xffffffffu, gmx, o));
            gmn = fminf(gmn, __shfl_xor_sync(0xffffffffu, gmn, o));
        }
        if (lane == 0) { sredA[warp] = gmx; sredB[warp] = gmn; }
        __syncthreads();
        if (tid == 0) {
            float a = sredA[0], b = sredB[0];
#pragma unroll
            for (int w = 1; w < 8; ++w) { a = fmaxf(a, sredA[w]); b = fminf(b, sredB[w]); }
            atomicMax(&g_gmaxpos, fenc(a));
            atomicMin(&g_gminneg, fenc(b));
        }
    }
}

__global__ __launch_bounds__(256) void k_check_fb() {
    if (g_fast | g_zero) return;
    const int r = blockIdx.x * 256 + threadIdx.x;
    const float minpos = fdec(g_minpos[r]);
    const float maxneg = fdec(g_maxneg[r]);
    const float gmaxP = fdec(g_gmaxpos);
    const float gminN = fdec(g_gminneg);
    const bool okP = (gmaxP - MARGIN < maxneg);
    const bool okN = (gminN + MARGIN > minpos);
    if (okP && okN) {
        float loss = 0.f;
        float sp = g_sp[r], sn = g_sn[r];
        if (sp > 0.f && sn > 0.f) {
            const float E1 = 2.718281828459045f;
            const float EINV = 0.36787944117144233f;
            loss = 0.5f * log1pf(E1 * sp) + 0.5f * log1pf(EINV * sn);
        }
        g_rowloss[r] = loss;
    } else {
        g_rowloss[r] = 0.f;
        int idx = atomicAdd(&g_nfix, 1);
        g_fixlist[idx] = r;
    }
}

__global__ __launch_bounds__(256) void k_fixup_fb(const int* __restrict__ labels) {
    if (g_fast | g_zero) return;
    __shared__ float fr[D_SZ];
    __shared__ float redp[256], redn[256];
    const int n = g_nfix;
    for (int w = blockIdx.x; w < n; w += gridDim.x) {
        const int r = g_fixlist[w];
        for (int k = threadIdx.x; k < D_SZ; k += 256)
            fr[k] = __bfloat162float(g_fbf[(size_t)r * D_SZ + k]);
        __syncthreads();
        const float inv = 1.0f / g_end_norm;
        const float minpos = fdec(g_minpos[r]);
        const float maxneg = fdec(g_maxneg[r]);
        const int lr = labels[r];
        const float ONE_EPS = 1.0f - 1e-5f;
        float sp = 0.f, sn = 0.f;
        for (int j = threadIdx.x; j < B_SZ; j += 256) {
            const __nv_bfloat162* fj =
                reinterpret_cast<const __nv_bfloat162*>(g_fbf + (size_t)j * D_SZ);
            float d = 0.f;
            for (int k = 0; k < D_SZ / 2; ++k) {
                float2 v = __bfloat1622float2(fj[k]);
                d = fmaf(fr[2 * k], v.x, d);
                d = fmaf(fr[2 * k + 1], v.y, d);
            }
            float s = d * inv;
            if (labels[j] == lr) {
                if (s < ONE_EPS && (s - MARGIN < maxneg)) sp += __expf(-2.f * (s - 0.5f));
            } else if (s + MARGIN > minpos) {
                sn += __expf(2.f * (s - 0.5f));
            }
        }
        redp[threadIdx.x] = sp;
        redn[threadIdx.x] = sn;
        __syncthreads();
        for (int o = 128; o > 0; o >>= 1) {
            if (threadIdx.x < o) {
                redp[threadIdx.x] += redp[threadIdx.x + o];
                redn[threadIdx.x] += redn[threadIdx.x + o];
            }
            __syncthreads();
        }
        if (threadIdx.x == 0) {
            float loss = 0.f;
            if (redp[0] > 0.f && redn[0] > 0.f)
                loss = 0.5f * log1pf(redp[0]) + 0.5f * log1pf(redn[0]);
            g_rowloss[r] = loss;
        }
        __syncthreads();
    }
}

// ================= final reduction =================
__global__ __launch_bounds__(256) void k_final(float* __restrict__ out) {
    __shared__ float red[256];
    float s = 0.f;
    for (int i = threadIdx.x; i < B_SZ; i += 256) s += g_rowloss[i];
    red[threadIdx.x] = s;
    __syncthreads();
    for (int o = 128; o > 0; o >>= 1) {
        if (threadIdx.x < o) red[threadIdx.x] += red[threadIdx.x + o];
        __syncthreads();
    }
    if (threadIdx.x == 0) out[0] = red[0] * (1.0f / B_SZ);
}

// ================= launch =================
extern "C" void kernel_launch(void* const* d_in, const int* in_sizes, int n_in,
                              void* d_out, int out_size) {
    const float* feats = (const float*)d_in[0];
    const int* labels = (const int*)d_in[1];
    (void)in_sizes; (void)n_in; (void)out_size;

    static int once = 0;
    if (!once) {
        cudaFuncSetAttribute(k_gemm_fb, cudaFuncAttributeMaxDynamicSharedMemorySize, SMEM_BYTES);
        once = 1;
    }

    k_prep<<<256, 256>>>(feats);
    k_verify<<<1, 512>>>(labels);
    k_cent<<<104, 256>>>(feats);
    k_row<<<512, 256>>>(feats, labels);
    k_conv<<<256, 256>>>(feats);
    k_gemm_fb<<<296, 256, SMEM_BYTES>>>(labels);
    k_check_fb<<<32, 256>>>();
    k_fixup_fb<<<64, 256>>>(labels);
    k_final<<<1, 256>>>((float*)d_out);
}

// round 10
// speedup vs baseline: 10.7872x; 1.0545x over previous
#include <cuda_runtime.h>
#include <cuda_bf16.h>
#include <cstdint>
#include <cstddef>

#define B_SZ 8192
#define D_SZ 512
#define MARGIN 0.1f

#define BM 128
#define BN 128
#define BK 32
#define PADW 20
#define NBLK 64
#define NTRI 2080

#define SM_A(s)  ((s) * 5120)
#define SM_B(s)  ((s) * 5120 + 2560)
#define SMEM_BYTES 61440

// ---------------- device scratch ----------------
static __device__ __nv_bfloat16 g_fbf[B_SZ * D_SZ];   // bf16 feats (fallback only)
static __device__ float    g_sp[B_SZ];
static __device__ float    g_sn[B_SZ];
static __device__ unsigned g_minpos[B_SZ];
static __device__ unsigned g_maxneg[B_SZ];
static __device__ unsigned g_gmaxpos;
static __device__ unsigned g_gminneg;
static __device__ float    g_enorm_part[256];
static __device__ float    g_end_norm;
static __device__ float    g_invE;
static __device__ float    g_rowloss[B_SZ];
static __device__ int      g_fixlist[B_SZ];
static __device__ int      g_nfix;
// fast-path state
static __device__ float    g_cpart[256 * 512];        // [cta][dim] partial sums of C
static __device__ float    g_C[512];
static __device__ float    g_cent[100 * 512];
static __device__ int      g_perm[B_SZ];
static __device__ int      g_off[101];
static __device__ int      g_cntg[100];
static __device__ int      g_cnth[100];               // histogram; self-resetting per replay
static __device__ unsigned g_maxn;                    // idempotent across replays
static __device__ int      g_fast;
static __device__ int      g_zero;
static __device__ int      g_done;                    // last-block ticket; self-resetting

__device__ __forceinline__ unsigned fenc(float f) {
    unsigned u = __float_as_uint(f);
    return (u & 0x80000000u) ? ~u : (u | 0x80000000u);
}
__device__ __forceinline__ float fdec(unsigned u) {
    return (u & 0x80000000u) ? __uint_as_float(u ^ 0x80000000u) : __uint_as_float(~u);
}

// ================= K1: norms + max norm + C partials + label histogram =================
__global__ __launch_bounds__(256) void k_prep(const float* __restrict__ feats,
                                              const int* __restrict__ labels) {
    __shared__ float sC[8 * 512];   // warp-private slices, 16KB
    __shared__ float eW[8], mW[8];
    const int tid = threadIdx.x, lane = tid & 31, warp = tid >> 5;

    // histogram contribution (32 rows per block)
    if (tid < 32) atomicAdd(&g_cnth[labels[blockIdx.x * 32 + tid]], 1);

    const float4* f4 = reinterpret_cast<const float4*>(feats);
    const int row0 = blockIdx.x * 32 + warp * 4;
    float cacc[16];
#pragma unroll
    for (int e = 0; e < 16; ++e) cacc[e] = 0.f;
    float esum = 0.f, mmax = 0.f;

#pragma unroll
    for (int rr = 0; rr < 4; ++rr) {
        const int row = row0 + rr;
        float rsq = 0.f;
#pragma unroll
        for (int it = 0; it < 4; ++it) {
            float4 v = f4[(size_t)row * 128 + it * 32 + lane];
            rsq += v.x * v.x + v.y * v.y + v.z * v.z + v.w * v.w;
            cacc[it * 4 + 0] += v.x; cacc[it * 4 + 1] += v.y;
            cacc[it * 4 + 2] += v.z; cacc[it * 4 + 3] += v.w;
        }
#pragma unroll
        for (int o = 16; o > 0; o >>= 1) rsq += __shfl_xor_sync(0xffffffffu, rsq, o);
        if (lane == 0) esum += rsq;
        mmax = fmaxf(mmax, rsq);
    }
    // warp-private slice write (vectorized, conflict-free)
#pragma unroll
    for (int it = 0; it < 4; ++it) {
        float4 v = make_float4(cacc[it * 4], cacc[it * 4 + 1], cacc[it * 4 + 2], cacc[it * 4 + 3]);
        *reinterpret_cast<float4*>(&sC[warp * 512 + it * 128 + lane * 4]) = v;
    }
    if (lane == 0) { eW[warp] = esum; mW[warp] = mmax; }
    __syncthreads();
    if (tid == 0) {
        float E = 0.f, m = 0.f;
#pragma unroll
        for (int w = 0; w < 8; ++w) { E += eW[w]; m = fmaxf(m, mW[w]); }
        g_enorm_part[blockIdx.x] = E;
        atomicMax(&g_maxn, fenc(m));
    }
    // cross-warp reduce: each thread owns 2 dims
    float s0 = 0.f, s1 = 0.f;
#pragma unroll
    for (int w = 0; w < 8; ++w) {
        s0 += sC[w * 512 + tid];
        s1 += sC[w * 512 + tid + 256];
    }
    g_cpart[(size_t)blockIdx.x * 512 + tid] = s0;
    g_cpart[(size_t)blockIdx.x * 512 + tid + 256] = s1;
}

// ================= K2: verify + prefix + perm =================
__global__ __launch_bounds__(512) void k_verify(const int* __restrict__ labels) {
    __shared__ float red[256];
    __shared__ int cnt[100], off[101];
    __shared__ unsigned offa[100];
    const int t = threadIdx.x;

    if (t < 256) red[t] = g_enorm_part[t];
    if (t < 100) { int c = g_cnth[t]; cnt[t] = c; g_cnth[t] = 0; }   // consume + reset
    __syncthreads();
    for (int o = 128; o > 0; o >>= 1) {
        if (t < o) red[t] += red[t + o];
        __syncthreads();
    }
    if (t == 0) {
        int acc = 0;
        for (int l = 0; l < 100; ++l) { off[l] = acc; acc += cnt[l]; }
        off[100] = acc;
    }
    __syncthreads();
    if (t < 100) { offa[t] = (unsigned)off[t]; g_cntg[t] = cnt[t]; g_off[t] = off[t]; }
    if (t == 100) g_off[100] = B_SZ;
    __syncthreads();
    for (int i = t; i < B_SZ; i += 512) {
        int l = labels[i];
        unsigned p = atomicAdd(&offa[l], 1u);
        g_perm[p] = i;
    }
    if (t == 0) {
        float E = red[0];
        float M2 = __uint_as_float(g_maxn & 0x7fffffffu);
        float Mp = (E > 0.f) ? M2 / E : 1.f;            // rigorous |sim| bound
        int mxc = 0;
        for (int l = 0; l < 100; ++l) mxc = max(mxc, cnt[l]);
        int zero = (mxc == B_SZ) ? 1 : 0;
        int fast = (E > 0.f) && (2.f * Mp < MARGIN * 0.9f) &&
                   (2.1f * (float)B_SZ * Mp * Mp < 1e-3f) && !zero;
        g_zero = zero;
        g_fast = fast ? 1 : 0;
        g_end_norm = E;
        g_invE = (E > 0.f) ? 1.f / E : 0.f;
        g_nfix = 0;
        g_gmaxpos = 0x007FFFFFu;
        g_gminneg = 0xFF800000u;
    }
    __syncthreads();
    if (!g_fast && !g_zero) {
        for (int i = t; i < B_SZ; i += 512) {
            g_sp[i] = 0.f; g_sn[i] = 0.f;
            g_minpos[i] = 0xFF800000u;
            g_maxneg[i] = 0x007FFFFFu;
        }
    }
}

// ================= K3: centroids (0..99) + C reduce (100..103) =================
__global__ __launch_bounds__(256) void k_cent(const float* __restrict__ feats) {
    if (!g_fast) return;
    const int b = blockIdx.x, t = threadIdx.x;
    if (b < 100) {
        __shared__ int sperm[256];
        const int start = g_off[b], n = g_cntg[b];
        const float2* f2 = reinterpret_cast<const float2*>(feats);
        float ax = 0.f, ay = 0.f;
        for (int base = 0; base < n; base += 256) {
            const int m = min(256, n - base);
            if (t < m) sperm[t] = g_perm[start + base + t];
            __syncthreads();
#pragma unroll 8
            for (int k = 0; k < m; ++k) {
                int row = sperm[k];
                float2 v = f2[(size_t)row * 256 + t];
                ax += v.x; ay += v.y;
            }
            __syncthreads();
        }
        reinterpret_cast<float2*>(g_cent)[b * 256 + t] = make_float2(ax, ay);
    } else {
        __shared__ float sr[256];
        const int d = (b - 100) * 128 + (t & 127);
        const int half = t >> 7;
        float s = 0.f;
#pragma unroll 8
        for (int c = half * 128; c < half * 128 + 128; ++c)
            s += g_cpart[(size_t)c * 512 + d];
        sr[t] = s;
        __syncthreads();
        if (t < 128) g_C[d] = sr[t] + sr[t + 128];
    }
}

// ================= K4: per-row analytic loss (4 rows/warp) + fused final =================
__global__ __launch_bounds__(256) void k_row(const float* __restrict__ feats,
                                             const int* __restrict__ labels,
                                             float* __restrict__ out) {
    const int fast = g_fast, zero = g_zero;
    if (!fast && !zero) return;   // uniform across grid

    __shared__ float Cs[512];
    __shared__ int isLast;
    const int t = threadIdx.x, warp = t >> 5, lane = t & 31;
    const int r0 = (blockIdx.x * 8 + warp) * 4;

    if (fast) { Cs[t] = g_C[t]; Cs[t + 256] = g_C[t + 256]; }
    __syncthreads();

    if (zero) {
        if (lane == 0) {
#pragma unroll
            for (int i = 0; i < 4; ++i) g_rowloss[r0 + i] = 0.f;
        }
    } else {
        int lab[4];
#pragma unroll
        for (int i = 0; i < 4; ++i) lab[i] = __ldg(&labels[r0 + i]);
        const float4* f4 = reinterpret_cast<const float4*>(feats);
        const float4* c4 = reinterpret_cast<const float4*>(g_cent);
        const float4* C4 = reinterpret_cast<const float4*>(Cs);

        float dp[4] = {0.f, 0.f, 0.f, 0.f}, da[4] = {0.f, 0.f, 0.f, 0.f};
#pragma unroll
        for (int it = 0; it < 4; ++it) {
            // issue all 9 loads before any FMA chain
            float4 a[4], b[4], cc;
#pragma unroll
            for (int i = 0; i < 4; ++i) a[i] = f4[(size_t)(r0 + i) * 128 + it * 32 + lane];
#pragma unroll
            for (int i = 0; i < 4; ++i) b[i] = c4[(size_t)lab[i] * 128 + it * 32 + lane];
            cc = C4[it * 32 + lane];
#pragma unroll
            for (int i = 0; i < 4; ++i) {
                dp[i] = fmaf(a[i].x, b[i].x, fmaf(a[i].y, b[i].y,
                         fmaf(a[i].z, b[i].z, fmaf(a[i].w, b[i].w, dp[i]))));
                da[i] = fmaf(a[i].x, cc.x, fmaf(a[i].y, cc.y,
                         fmaf(a[i].z, cc.z, fmaf(a[i].w, cc.w, da[i]))));
            }
        }
#pragma unroll
        for (int o = 16; o > 0; o >>= 1) {
#pragma unroll
            for (int i = 0; i < 4; ++i) {
                dp[i] += __shfl_xor_sync(0xffffffffu, dp[i], o);
                da[i] += __shfl_xor_sync(0xffffffffu, da[i], o);
            }
        }
        if (lane == 0) {
            const float invE = g_invE;
            const float E1 = 2.718281828459045f;
            const float EINV = 0.36787944117144233f;
#pragma unroll
            for (int i = 0; i < 4; ++i) {
                float n = (float)g_cntg[lab[i]];
                float sp = n - 2.f * dp[i] * invE;
                float sn = ((float)B_SZ - n) + 2.f * (da[i] - dp[i]) * invE;
                g_rowloss[r0 + i] = 0.5f * log1pf(E1 * sp) + 0.5f * log1pf(EINV * sn);
            }
        }
    }

    // ---- fused deterministic final reduction (last block) ----
    __threadfence();
    if (t == 0) isLast = (atomicAdd(&g_done, 1) == (int)gridDim.x - 1);
    __syncthreads();
    if (isLast) {
        __threadfence();
        __shared__ float red[256];
        float s = 0.f;
        for (int i = t; i < B_SZ; i += 256) s += g_rowloss[i];
        red[t] = s;
        __syncthreads();
        for (int o = 128; o > 0; o >>= 1) {
            if (t < o) red[t] += red[t + o];
            __syncthreads();
        }
        if (t == 0) { out[0] = red[0] * (1.0f / B_SZ); g_done = 0; }
    }
}

// ================= K5: fp32->bf16 convert (fallback only) =================
__global__ __launch_bounds__(256) void k_conv(const float* __restrict__ feats) {
    if (g_fast | g_zero) return;
    const int n4 = B_SZ * D_SZ / 4;
    const float4* f4 = reinterpret_cast<const float4*>(feats);
    for (int i = blockIdx.x * blockDim.x + threadIdx.x; i < n4; i += gridDim.x * blockDim.x) {
        float4 v = f4[i];
        __nv_bfloat162 lo = __floats2bfloat162_rn(v.x, v.y);
        __nv_bfloat162 hi = __floats2bfloat162_rn(v.z, v.w);
        uint2 o;
        o.x = *reinterpret_cast<unsigned*>(&lo);
        o.y = *reinterpret_cast<unsigned*>(&hi);
        reinterpret_cast<uint2*>(g_fbf)[i] = o;
    }
}

// ================= fallback GEMM (persistent, flag-guarded) =================
__device__ __forceinline__ void mma16816(float* d, const uint32_t* a, const uint32_t* b) {
    asm volatile(
        "mma.sync.aligned.m16n8k16.row.col.f32.bf16.bf16.f32 "
        "{%0,%1,%2,%3}, {%4,%5,%6,%7}, {%8,%9}, {%0,%1,%2,%3};\n"
        : "+f"(d[0]), "+f"(d[1]), "+f"(d[2]), "+f"(d[3])
        : "r"(a[0]), "r"(a[1]), "r"(a[2]), "r"(a[3]), "r"(b[0]), "r"(b[1]));
}
__device__ __forceinline__ void ldsm4(uint32_t* d, uint32_t saddr) {
    asm volatile("ldmatrix.sync.aligned.m8n8.x4.shared.b16 {%0,%1,%2,%3}, [%4];"
                 : "=r"(d[0]), "=r"(d[1]), "=r"(d[2]), "=r"(d[3]) : "r"(saddr));
}
__device__ __forceinline__ void cpa16(uint32_t saddr, const void* g) {
    asm volatile("cp.async.cg.shared.global [%0], [%1], 16;\n" :: "r"(saddr), "l"(g));
}
__device__ __forceinline__ void load_chunk(uint32_t sb, int stage, int kbase,
                                           int i0, int j0, int tid) {
    const int r = tid >> 2, q = tid & 3;
#pragma unroll
    for (int h = 0; h < 2; ++h) {
        int rr = r + h * 64;
        cpa16(sb + (SM_A(stage) + rr * PADW + q * 4) * 4,
              g_fbf + (size_t)(i0 + rr) * D_SZ + kbase + q * 8);
        cpa16(sb + (SM_B(stage) + rr * PADW + q * 4) * 4,
              g_fbf + (size_t)(j0 + rr) * D_SZ + kbase + q * 8);
    }
    asm volatile("cp.async.commit_group;\n" ::: "memory");
}
#define PROC(SRAW, LI, LJ, SP, SN, MN, MX, NT, H)                              \
    {                                                                          \
        float s_ = (SRAW) * inv;                                               \
        float s2_ = s_ * s_;                                                   \
        float even_ = fmaf(s2_, 2.f, 1.f);                                     \
        float odd_ = s_ * fmaf(s2_, 1.33333333f, 2.f);                         \
        if ((LI) == (LJ)) {                                                    \
            if (s_ < ONE_EPS) {                                                \
                float evp_ = even_ - odd_;                                     \
                SP += evp_; MN = fminf(MN, s_); gmx = fmaxf(gmx, s_);          \
                csp[NT][H] += evp_; cmnP[NT][H] = fminf(cmnP[NT][H], s_);      \
            }                                                                  \
        } else {                                                               \
            float evn_ = even_ + odd_;                                         \
            SN += evn_; MX = fmaxf(MX, s_); gmn = fminf(gmn, s_);              \
            csn[NT][H] += evn_; cmxN[NT][H] = fmaxf(cmxN[NT][H], s_);          \
        }                                                                      \
    }

__global__ void __launch_bounds__(256, 2) k_gemm_fb(const int* __restrict__ labels) {
    if (g_fast | g_zero) return;
    extern __shared__ uint32_t dsm[];
    const uint32_t sb = (uint32_t)__cvta_generic_to_shared(dsm);
    __shared__ int slabi[BM];
    __shared__ int slabj[BN];
    __shared__ float sredA[8], sredB[8];

    const int tid = threadIdx.x, lane = tid & 31, warp = tid >> 5;
    const int wm = warp >> 2, wn = warp & 3;
    const int r4 = lane >> 2, cq = lane & 3;
    const int arow = wm * 64 + (lane & 15);
    const int akw  = (lane >> 4) * 4;
    const int awoff = arow * PADW + akw;
    const int brow = wn * 32 + (lane & 7) + ((lane >= 16) ? 8 : 0);
    const int bkw  = ((lane >> 3) & 1) * 4;
    const int bwoff = brow * PADW + bkw;

    for (int kb = blockIdx.x; kb < NTRI; kb += gridDim.x) {
        __syncthreads();
        int bi = (int)(64.5f - sqrtf(64.5f * 64.5f - 2.0f * (float)kb));
        if (bi < 0) bi = 0;
        if (bi > 63) bi = 63;
        while (bi > 0 && bi * NBLK - bi * (bi - 1) / 2 > kb) --bi;
        while ((bi + 1) * NBLK - (bi + 1) * bi / 2 <= kb) ++bi;
        const int bj = bi + (kb - (bi * NBLK - bi * (bi - 1) / 2));
        const int i0 = bi * BM, j0 = bj * BN;
        const bool offdiag = (bi != bj);

        if (tid < BM) slabi[tid] = labels[i0 + tid];
        else if (tid < BM + BN) slabj[tid - BM] = labels[j0 + tid - BM];

        float acc[4][4][4];
#pragma unroll
        for (int mt = 0; mt < 4; ++mt)
#pragma unroll
            for (int nt = 0; nt < 4; ++nt)
#pragma unroll
                for (int e = 0; e < 4; ++e) acc[mt][nt][e] = 0.f;

        const int NK = D_SZ / BK;
        load_chunk(sb, 0, 0, i0, j0, tid);
        load_chunk(sb, 1, BK, i0, j0, tid);

        for (int kt = 0; kt < NK; ++kt) {
            const int s = kt % 3;
            if (kt + 1 < NK) asm volatile("cp.async.wait_group 1;\n" ::: "memory");
            else             asm volatile("cp.async.wait_group 0;\n" ::: "memory");
            __syncthreads();
            if (kt + 2 < NK) load_chunk(sb, (kt + 2) % 3, (kt + 2) * BK, i0, j0, tid);
#pragma unroll
            for (int ks = 0; ks < 2; ++ks) {
                const int ko = ks * 8;
                uint32_t a[4][4], b[2][4];
#pragma unroll
                for (int mt = 0; mt < 4; ++mt)
                    ldsm4(a[mt], sb + (SM_A(s) + awoff + mt * 16 * PADW + ko) * 4);
#pragma unroll
                for (int p = 0; p < 2; ++p)
                    ldsm4(b[p], sb + (SM_B(s) + bwoff + p * 16 * PADW + ko) * 4);
#pragma unroll
                for (int mt = 0; mt < 4; ++mt)
#pragma unroll
                    for (int nt = 0; nt < 4; ++nt) {
                        uint32_t bb[2] = {b[nt >> 1][(nt & 1) * 2], b[nt >> 1][(nt & 1) * 2 + 1]};
                        mma16816(acc[mt][nt], a[mt], bb);
                    }
            }
        }

        const float inv = 1.0f / g_end_norm;
        const float ONE_EPS = 1.0f - 1e-5f;
        const float INF = __int_as_float(0x7f800000);
        float csp[4][2], csn[4][2], cmnP[4][2], cmxN[4][2];
#pragma unroll
        for (int nt = 0; nt < 4; ++nt)
#pragma unroll
            for (int h = 0; h < 2; ++h) {
                csp[nt][h] = 0.f; csn[nt][h] = 0.f;
                cmnP[nt][h] = INF; cmxN[nt][h] = -INF;
            }
        float gmx = -INF, gmn = INF;

#pragma unroll
        for (int mt = 0; mt < 4; ++mt) {
            const int lr0 = mt * 16 + r4, lr1 = lr0 + 8;
            const int li0 = slabi[wm * 64 + lr0], li1 = slabi[wm * 64 + lr1];
            const int gi0 = i0 + wm * 64 + lr0, gi1 = i0 + wm * 64 + lr1;
            float sp0 = 0.f, sn0 = 0.f, mn0 = INF, mx0 = -INF;
            float sp1 = 0.f, sn1 = 0.f, mn1 = INF, mx1 = -INF;
#pragma unroll
            for (int nt = 0; nt < 4; ++nt) {
                const int lc = nt * 8 + 2 * cq;
                const int lj0 = slabj[wn * 32 + lc], lj1 = slabj[wn * 32 + lc + 1];
                PROC(acc[mt][nt][0], li0, lj0, sp0, sn0, mn0, mx0, nt, 0);
                PROC(acc[mt][nt][1], li0, lj1, sp0, sn0, mn0, mx0, nt, 1);
                PROC(acc[mt][nt][2], li1, lj0, sp1, sn1, mn1, mx1, nt, 0);
                PROC(acc[mt][nt][3], li1, lj1, sp1, sn1, mn1, mx1, nt, 1);
            }
#pragma unroll
            for (int o = 1; o < 4; o <<= 1) {
                sp0 += __shfl_xor_sync(0xffffffffu, sp0, o);
                sn0 += __shfl_xor_sync(0xffffffffu, sn0, o);
                mn0 = fminf(mn0, __shfl_xor_sync(0xffffffffu, mn0, o));
                mx0 = fmaxf(mx0, __shfl_xor_sync(0xffffffffu, mx0, o));
                sp1 += __shfl_xor_sync(0xffffffffu, sp1, o);
                sn1 += __shfl_xor_sync(0xffffffffu, sn1, o);
                mn1 = fminf(mn1, __shfl_xor_sync(0xffffffffu, mn1, o));
                mx1 = fmaxf(mx1, __shfl_xor_sync(0xffffffffu, mx1, o));
            }
            if (cq == 0) {
                atomicAdd(&g_sp[gi0], sp0);
                atomicAdd(&g_sn[gi0], sn0);
                atomicMin(&g_minpos[gi0], fenc(mn0));
                atomicMax(&g_maxneg[gi0], fenc(mx0));
                atomicAdd(&g_sp[gi1], sp1);
                atomicAdd(&g_sn[gi1], sn1);
                atomicMin(&g_minpos[gi1], fenc(mn1));
                atomicMax(&g_maxneg[gi1], fenc(mx1));
            }
        }
        if (offdiag) {
#pragma unroll
            for (int nt = 0; nt < 4; ++nt)
#pragma unroll
                for (int h = 0; h < 2; ++h) {
#pragma unroll
                    for (int o = 4; o < 32; o <<= 1) {
                        csp[nt][h] += __shfl_xor_sync(0xffffffffu, csp[nt][h], o);
                        csn[nt][h] += __shfl_xor_sync(0xffffffffu, csn[nt][h], o);
                        cmnP[nt][h] = fminf(cmnP[nt][h], __shfl_xor_sync(0xffffffffu, cmnP[nt][h], o));
                        cmxN[nt][h] = fmaxf(cmxN[nt][h], __shfl_xor_sync(0xffffffffu, cmxN[nt][h], o));
                    }
                }
            if (r4 == 0) {
#pragma unroll
                for (int nt = 0; nt < 4; ++nt) {
                    const int gj = j0 + wn * 32 + nt * 8 + 2 * cq;
                    atomicAdd(&g_sp[gj], csp[nt][0]);
                    atomicAdd(&g_sn[gj], csn[nt][0]);
                    atomicMin(&g_minpos[gj], fenc(cmnP[nt][0]));
                    atomicMax(&g_maxneg[gj], fenc(cmxN[nt][0]));
                    atomicAdd(&g_sp[gj + 1], csp[nt][1]);
                    atomicAdd(&g_sn[gj + 1], csn[nt][1]);
                    atomicMin(&g_minpos[gj + 1], fenc(cmnP[nt][1]));
                    atomicMax(&g_maxneg[gj + 1], fenc(cmxN[nt][1]));
                }
            }
        }
#pragma unroll
        for (int o = 16; o > 0; o >>= 1) {
            gmx = fmaxf(gmx, __shfl_xor_sync(0xffffffffu, gmx, o));
            gmn = fminf(gmn, __shfl_xor_sync(0xffffffffu, gmn, o));
        }
        if (lane == 0) { sredA[warp] = gmx; sredB[warp] = gmn; }
        __syncthreads();
        if (tid == 0) {
            float a = sredA[0], b = sredB[0];
#pragma unroll
            for (int w = 1; w < 8; ++w) { a = fmaxf(a, sredA[w]); b = fminf(b, sredB[w]); }
            atomicMax(&g_gmaxpos, fenc(a));
            atomicMin(&g_gminneg, fenc(b));
        }
    }
}

__global__ __launch_bounds__(256) void k_check_fb() {
    if (g_fast | g_zero) return;
    const int r = blockIdx.x * 256 + threadIdx.x;
    const float minpos = fdec(g_minpos[r]);
    const float maxneg = fdec(g_maxneg[r]);
    const float gmaxP = fdec(g_gmaxpos);
    const float gminN = fdec(g_gminneg);
    const bool okP = (gmaxP - MARGIN < maxneg);
    const bool okN = (gminN + MARGIN > minpos);
    if (okP && okN) {
        float loss = 0.f;
        float sp = g_sp[r], sn = g_sn[r];
        if (sp > 0.f && sn > 0.f) {
            const float E1 = 2.718281828459045f;
            const float EINV = 0.36787944117144233f;
            loss = 0.5f * log1pf(E1 * sp) + 0.5f * log1pf(EINV * sn);
        }
        g_rowloss[r] = loss;
    } else {
        g_rowloss[r] = 0.f;
        int idx = atomicAdd(&g_nfix, 1);
        g_fixlist[idx] = r;
    }
}

__global__ __launch_bounds__(256) void k_fixup_fb(const int* __restrict__ labels) {
    if (g_fast | g_zero) return;
    __shared__ float fr[D_SZ];
    __shared__ float redp[256], redn[256];
    const int n = g_nfix;
    for (int w = blockIdx.x; w < n; w += gridDim.x) {
        const int r = g_fixlist[w];
        for (int k = threadIdx.x; k < D_SZ; k += 256)
            fr[k] = __bfloat162float(g_fbf[(size_t)r * D_SZ + k]);
        __syncthreads();
        const float inv = 1.0f / g_end_norm;
        const float minpos = fdec(g_minpos[r]);
        const float maxneg = fdec(g_maxneg[r]);
        const int lr = labels[r];
        const float ONE_EPS = 1.0f - 1e-5f;
        float sp = 0.f, sn = 0.f;
        for (int j = threadIdx.x; j < B_SZ; j += 256) {
            const __nv_bfloat162* fj =
                reinterpret_cast<const __nv_bfloat162*>(g_fbf + (size_t)j * D_SZ);
            float d = 0.f;
            for (int k = 0; k < D_SZ / 2; ++k) {
                float2 v = __bfloat1622float2(fj[k]);
                d = fmaf(fr[2 * k], v.x, d);
                d = fmaf(fr[2 * k + 1], v.y, d);
            }
            float s = d * inv;
            if (labels[j] == lr) {
                if (s < ONE_EPS && (s - MARGIN < maxneg)) sp += __expf(-2.f * (s - 0.5f));
            } else if (s + MARGIN > minpos) {
                sn += __expf(2.f * (s - 0.5f));
            }
        }
        redp[threadIdx.x] = sp;
        redn[threadIdx.x] = sn;
        __syncthreads();
        for (int o = 128; o > 0; o >>= 1) {
            if (threadIdx.x < o) {
                redp[threadIdx.x] += redp[threadIdx.x + o];
                redn[threadIdx.x] += redn[threadIdx.x + o];
            }
            __syncthreads();
        }
        if (threadIdx.x == 0) {
            float loss = 0.f;
            if (redp[0] > 0.f && redn[0] > 0.f)
                loss = 0.5f * log1pf(redp[0]) + 0.5f * log1pf(redn[0]);
            g_rowloss[r] = loss;
        }
        __syncthreads();
    }
}

// ================= K8: final reduction (fallback only; fast path fused into k_row) =================
__global__ __launch_bounds__(256) void k_final_fb(float* __restrict__ out) {
    if (g_fast | g_zero) return;
    __shared__ float red[256];
    float s = 0.f;
    for (int i = threadIdx.x; i < B_SZ; i += 256) s += g_rowloss[i];
    red[threadIdx.x] = s;
    __syncthreads();
    for (int o = 128; o > 0; o >>= 1) {
        if (threadIdx.x < o) red[threadIdx.x] += red[threadIdx.x + o];
        __syncthreads();
    }
    if (threadIdx.x == 0) out[0] = red[0] * (1.0f / B_SZ);
}

// ================= launch =================
extern "C" void kernel_launch(void* const* d_in, const int* in_sizes, int n_in,
                              void* d_out, int out_size) {
    const float* feats = (const float*)d_in[0];
    const int* labels = (const int*)d_in[1];
    (void)in_sizes; (void)n_in; (void)out_size;

    static int once = 0;
    if (!once) {
        cudaFuncSetAttribute(k_gemm_fb, cudaFuncAttributeMaxDynamicSharedMemorySize, SMEM_BYTES);
        once = 1;
    }

    k_prep<<<256, 256>>>(feats, labels);
    k_verify<<<1, 512>>>(labels);
    k_cent<<<104, 256>>>(feats);
    k_row<<<256, 256>>>(feats, labels, (float*)d_out);
    k_conv<<<256, 256>>>(feats);
    k_gemm_fb<<<148, 256, SMEM_BYTES>>>(labels);
    k_check_fb<<<32, 256>>>();
    k_fixup_fb<<<64, 256>>>(labels);
    k_final_fb<<<1, 256>>>((float*)d_out);
}

// round 11
// speedup vs baseline: 12.3538x; 1.1452x over previous
#include <cuda_runtime.h>
#include <cuda_bf16.h>
#include <cstdint>
#include <cstddef>

#define B_SZ 8192
#define D_SZ 512
#define MARGIN 0.1f

#define BM 128
#define BN 128
#define BK 32
#define PADW 20
#define NBLK 64
#define NTRI 2080
#define FB_GRID 148

#define SM_A(s)  ((s) * 5120)
#define SM_B(s)  ((s) * 5120 + 2560)
#define SMEM_BYTES 61440

// ---------------- device scratch ----------------
static __device__ __nv_bfloat16 g_fbf[B_SZ * D_SZ];   // bf16 feats (fallback only)
static __device__ float    g_sp[B_SZ];
static __device__ float    g_sn[B_SZ];
static __device__ unsigned g_minpos[B_SZ];
static __device__ unsigned g_maxneg[B_SZ];
static __device__ unsigned g_gmaxpos;
static __device__ unsigned g_gminneg;
static __device__ float    g_enorm_part[256];
static __device__ float    g_end_norm;
static __device__ float    g_invE;
static __device__ float    g_rowloss[B_SZ];
static __device__ int      g_fixlist[B_SZ];
static __device__ int      g_nfix;
// fast-path state
static __device__ float    g_cpart[256 * 512];        // [cta][dim] partial sums of C
static __device__ float    g_C[512];
static __device__ float    g_cent[100 * 512];
static __device__ int      g_perm[B_SZ];
static __device__ int      g_off[101];
static __device__ int      g_cntg[100];
static __device__ int      g_cnth[100];               // histogram; self-resetting per replay
static __device__ unsigned g_maxn;                    // idempotent across replays
static __device__ int      g_fast;
static __device__ int      g_zero;
static __device__ int      g_done;                    // k_row ticket; self-resetting
static __device__ int      g_pdone;                   // k_prep ticket; self-resetting
static __device__ unsigned g_fbar;                    // fallback grid barrier; self-resetting

__device__ __forceinline__ unsigned fenc(float f) {
    unsigned u = __float_as_uint(f);
    return (u & 0x80000000u) ? ~u : (u | 0x80000000u);
}
__device__ __forceinline__ float fdec(unsigned u) {
    return (u & 0x80000000u) ? __uint_as_float(u ^ 0x80000000u) : __uint_as_float(~u);
}

// ================= K1: norms + C partials + histogram + fused verify (last block) =================
__global__ __launch_bounds__(256) void k_prep(const float* __restrict__ feats,
                                              const int* __restrict__ labels) {
    __shared__ float sC[8 * 512];   // warp-private slices, 16KB
    __shared__ float eW[8], mW[8];
    __shared__ int isLast;
    const int tid = threadIdx.x, lane = tid & 31, warp = tid >> 5;

    if (tid < 32) atomicAdd(&g_cnth[labels[blockIdx.x * 32 + tid]], 1);

    const float4* f4 = reinterpret_cast<const float4*>(feats);
    const int row0 = blockIdx.x * 32 + warp * 4;
    float cacc[16];
#pragma unroll
    for (int e = 0; e < 16; ++e) cacc[e] = 0.f;
    float esum = 0.f, mmax = 0.f;

#pragma unroll
    for (int rr = 0; rr < 4; ++rr) {
        const int row = row0 + rr;
        float rsq = 0.f;
#pragma unroll
        for (int it = 0; it < 4; ++it) {
            float4 v = f4[(size_t)row * 128 + it * 32 + lane];
            rsq += v.x * v.x + v.y * v.y + v.z * v.z + v.w * v.w;
            cacc[it * 4 + 0] += v.x; cacc[it * 4 + 1] += v.y;
            cacc[it * 4 + 2] += v.z; cacc[it * 4 + 3] += v.w;
        }
#pragma unroll
        for (int o = 16; o > 0; o >>= 1) rsq += __shfl_xor_sync(0xffffffffu, rsq, o);
        if (lane == 0) esum += rsq;
        mmax = fmaxf(mmax, rsq);
    }
#pragma unroll
    for (int it = 0; it < 4; ++it) {
        float4 v = make_float4(cacc[it * 4], cacc[it * 4 + 1], cacc[it * 4 + 2], cacc[it * 4 + 3]);
        *reinterpret_cast<float4*>(&sC[warp * 512 + it * 128 + lane * 4]) = v;
    }
    if (lane == 0) { eW[warp] = esum; mW[warp] = mmax; }
    __syncthreads();
    if (tid == 0) {
        float E = 0.f, m = 0.f;
#pragma unroll
        for (int w = 0; w < 8; ++w) { E += eW[w]; m = fmaxf(m, mW[w]); }
        g_enorm_part[blockIdx.x] = E;
        atomicMax(&g_maxn, fenc(m));
    }
    float s0 = 0.f, s1 = 0.f;
#pragma unroll
    for (int w = 0; w < 8; ++w) {
        s0 += sC[w * 512 + tid];
        s1 += sC[w * 512 + tid + 256];
    }
    g_cpart[(size_t)blockIdx.x * 512 + tid] = s0;
    g_cpart[(size_t)blockIdx.x * 512 + tid + 256] = s1;

    // ---- fused verify: last block ----
    __threadfence();
    if (tid == 0) isLast = (atomicAdd(&g_pdone, 1) == (int)gridDim.x - 1);
    __syncthreads();
    if (!isLast) return;
    __threadfence();

    __shared__ float red[256];
    __shared__ int cnt[100], off[101];
    __shared__ unsigned offa[100];
    red[tid] = g_enorm_part[tid];
    if (tid < 100) { int c = g_cnth[tid]; cnt[tid] = c; g_cnth[tid] = 0; }
    __syncthreads();
    for (int o = 128; o > 0; o >>= 1) {
        if (tid < o) red[tid] += red[tid + o];
        __syncthreads();
    }
    if (tid == 0) {
        int acc = 0;
        for (int l = 0; l < 100; ++l) { off[l] = acc; acc += cnt[l]; }
        off[100] = acc;
    }
    __syncthreads();
    if (tid < 100) { offa[tid] = (unsigned)off[tid]; g_cntg[tid] = cnt[tid]; g_off[tid] = off[tid]; }
    if (tid == 100) g_off[100] = B_SZ;
    __syncthreads();
    for (int i = tid; i < B_SZ; i += 256) {
        int l = labels[i];
        unsigned p = atomicAdd(&offa[l], 1u);
        g_perm[p] = i;
    }
    if (tid == 0) {
        float E = red[0];
        float M2 = __uint_as_float(g_maxn & 0x7fffffffu);
        float Mp = (E > 0.f) ? M2 / E : 1.f;            // rigorous |sim| bound
        int mxc = 0;
        for (int l = 0; l < 100; ++l) mxc = max(mxc, cnt[l]);
        int zero = (mxc == B_SZ) ? 1 : 0;
        int fast = (E > 0.f) && (2.f * Mp < MARGIN * 0.9f) &&
                   (2.1f * (float)B_SZ * Mp * Mp < 1e-3f) && !zero;
        g_zero = zero;
        g_fast = fast ? 1 : 0;
        g_end_norm = E;
        g_invE = (E > 0.f) ? 1.f / E : 0.f;
        g_nfix = 0;
        g_gmaxpos = 0x007FFFFFu;
        g_gminneg = 0xFF800000u;
        g_pdone = 0;
    }
    __syncthreads();
    if (!g_fast && !g_zero) {
        for (int i = tid; i < B_SZ; i += 256) {
            g_sp[i] = 0.f; g_sn[i] = 0.f;
            g_minpos[i] = 0xFF800000u;
            g_maxneg[i] = 0x007FFFFFu;
        }
    }
    __threadfence();
}

// ================= K2: centroids (0..99) + C reduce (100..103) =================
__global__ __launch_bounds__(256) void k_cent(const float* __restrict__ feats) {
    if (!g_fast) return;
    const int b = blockIdx.x, t = threadIdx.x;
    if (b < 100) {
        __shared__ int sperm[256];
        const int start = g_off[b], n = g_cntg[b];
        const float2* f2 = reinterpret_cast<const float2*>(feats);
        float ax = 0.f, ay = 0.f;
        for (int base = 0; base < n; base += 256) {
            const int m = min(256, n - base);
            if (t < m) sperm[t] = g_perm[start + base + t];
            __syncthreads();
#pragma unroll 8
            for (int k = 0; k < m; ++k) {
                int row = sperm[k];
                float2 v = f2[(size_t)row * 256 + t];
                ax += v.x; ay += v.y;
            }
            __syncthreads();
        }
        reinterpret_cast<float2*>(g_cent)[b * 256 + t] = make_float2(ax, ay);
    } else {
        __shared__ float sr[256];
        const int d = (b - 100) * 128 + (t & 127);
        const int half = t >> 7;
        float s = 0.f;
#pragma unroll 8
        for (int c = half * 128; c < half * 128 + 128; ++c)
            s += g_cpart[(size_t)c * 512 + d];
        sr[t] = s;
        __syncthreads();
        if (t < 128) g_C[d] = sr[t] + sr[t + 128];
    }
}

// ================= K3: per-row analytic loss (2 rows/warp, grid 512) + fused final =================
__global__ __launch_bounds__(256) void k_row(const float* __restrict__ feats,
                                             const int* __restrict__ labels,
                                             float* __restrict__ out) {
    const int fast = g_fast, zero = g_zero;
    if (!fast && !zero) return;   // uniform across grid

    __shared__ float Cs[512];
    __shared__ int isLast;
    const int t = threadIdx.x, warp = t >> 5, lane = t & 31;
    const int r0 = blockIdx.x * 16 + warp * 2, r1 = r0 + 1;

    if (fast) { Cs[t] = g_C[t]; Cs[t + 256] = g_C[t + 256]; }
    __syncthreads();

    if (zero) {
        if (lane == 0) { g_rowloss[r0] = 0.f; g_rowloss[r1] = 0.f; }
    } else {
        const int lab0 = __ldg(&labels[r0]), lab1 = __ldg(&labels[r1]);
        const float4* f0 = reinterpret_cast<const float4*>(feats) + (size_t)r0 * 128;
        const float4* f1 = reinterpret_cast<const float4*>(feats) + (size_t)r1 * 128;
        const float4* c0 = reinterpret_cast<const float4*>(g_cent) + (size_t)lab0 * 128;
        const float4* c1 = reinterpret_cast<const float4*>(g_cent) + (size_t)lab1 * 128;
        const float4* C4 = reinterpret_cast<const float4*>(Cs);

        float dp0 = 0.f, da0 = 0.f, dp1 = 0.f, da1 = 0.f;
#pragma unroll
        for (int it = 0; it < 4; ++it) {
            float4 a0 = f0[it * 32 + lane];
            float4 a1 = f1[it * 32 + lane];
            float4 b0 = c0[it * 32 + lane];
            float4 b1 = c1[it * 32 + lane];
            float4 cc = C4[it * 32 + lane];
            dp0 = fmaf(a0.x, b0.x, fmaf(a0.y, b0.y, fmaf(a0.z, b0.z, fmaf(a0.w, b0.w, dp0))));
            da0 = fmaf(a0.x, cc.x, fmaf(a0.y, cc.y, fmaf(a0.z, cc.z, fmaf(a0.w, cc.w, da0))));
            dp1 = fmaf(a1.x, b1.x, fmaf(a1.y, b1.y, fmaf(a1.z, b1.z, fmaf(a1.w, b1.w, dp1))));
            da1 = fmaf(a1.x, cc.x, fmaf(a1.y, cc.y, fmaf(a1.z, cc.z, fmaf(a1.w, cc.w, da1))));
        }
#pragma unroll
        for (int o = 16; o > 0; o >>= 1) {
            dp0 += __shfl_xor_sync(0xffffffffu, dp0, o);
            da0 += __shfl_xor_sync(0xffffffffu, da0, o);
            dp1 += __shfl_xor_sync(0xffffffffu, dp1, o);
            da1 += __shfl_xor_sync(0xffffffffu, da1, o);
        }
        if (lane == 0) {
            const float invE = g_invE;
            const float E1 = 2.718281828459045f;
            const float EINV = 0.36787944117144233f;
            float n0 = (float)g_cntg[lab0];
            float sp0 = n0 - 2.f * dp0 * invE;
            float sn0 = ((float)B_SZ - n0) + 2.f * (da0 - dp0) * invE;
            g_rowloss[r0] = 0.5f * log1pf(E1 * sp0) + 0.5f * log1pf(EINV * sn0);
            float n1 = (float)g_cntg[lab1];
            float sp1 = n1 - 2.f * dp1 * invE;
            float sn1 = ((float)B_SZ - n1) + 2.f * (da1 - dp1) * invE;
            g_rowloss[r1] = 0.5f * log1pf(E1 * sp1) + 0.5f * log1pf(EINV * sn1);
        }
    }

    // ---- fused deterministic final reduction (last block) ----
    __threadfence();
    if (t == 0) isLast = (atomicAdd(&g_done, 1) == (int)gridDim.x - 1);
    __syncthreads();
    if (isLast) {
        __threadfence();
        __shared__ float red[256];
        float s = 0.f;
        for (int i = t; i < B_SZ; i += 256) s += g_rowloss[i];
        red[t] = s;
        __syncthreads();
        for (int o = 128; o > 0; o >>= 1) {
            if (t < o) red[t] += red[t + o];
            __syncthreads();
        }
        if (t == 0) { out[0] = red[0] * (1.0f / B_SZ); g_done = 0; }
    }
}

// ================= fallback: conv + GEMM + check + fixup + final in ONE kernel =================
__device__ __forceinline__ void mma16816(float* d, const uint32_t* a, const uint32_t* b) {
    asm volatile(
        "mma.sync.aligned.m16n8k16.row.col.f32.bf16.bf16.f32 "
        "{%0,%1,%2,%3}, {%4,%5,%6,%7}, {%8,%9}, {%0,%1,%2,%3};\n"
        : "+f"(d[0]), "+f"(d[1]), "+f"(d[2]), "+f"(d[3])
        : "r"(a[0]), "r"(a[1]), "r"(a[2]), "r"(a[3]), "r"(b[0]), "r"(b[1]));
}
__device__ __forceinline__ void ldsm4(uint32_t* d, uint32_t saddr) {
    asm volatile("ldmatrix.sync.aligned.m8n8.x4.shared.b16 {%0,%1,%2,%3}, [%4];"
                 : "=r"(d[0]), "=r"(d[1]), "=r"(d[2]), "=r"(d[3]) : "r"(saddr));
}
__device__ __forceinline__ void cpa16(uint32_t saddr, const void* g) {
    asm volatile("cp.async.cg.shared.global [%0], [%1], 16;\n" :: "r"(saddr), "l"(g));
}
__device__ __forceinline__ void load_chunk(uint32_t sb, int stage, int kbase,
                                           int i0, int j0, int tid) {
    const int r = tid >> 2, q = tid & 3;
#pragma unroll
    for (int h = 0; h < 2; ++h) {
        int rr = r + h * 64;
        cpa16(sb + (SM_A(stage) + rr * PADW + q * 4) * 4,
              g_fbf + (size_t)(i0 + rr) * D_SZ + kbase + q * 8);
        cpa16(sb + (SM_B(stage) + rr * PADW + q * 4) * 4,
              g_fbf + (size_t)(j0 + rr) * D_SZ + kbase + q * 8);
    }
    asm volatile("cp.async.commit_group;\n" ::: "memory");
}
// grid barrier: all FB_GRID blocks co-resident (grid == SM count, 2 CTAs/SM allowed)
__device__ __forceinline__ void gsync(unsigned target) {
    __syncthreads();
    if (threadIdx.x == 0) {
        __threadfence();
        atomicAdd(&g_fbar, 1u);
        while (*(volatile unsigned*)&g_fbar < target) { }
    }
    __syncthreads();
    __threadfence();
}
#define PROC(SRAW, LI, LJ, SP, SN, MN, MX, NT, H)                              \
    {                                                                          \
        float s_ = (SRAW) * inv;                                               \
        float s2_ = s_ * s_;                                                   \
        float even_ = fmaf(s2_, 2.f, 1.f);                                     \
        float odd_ = s_ * fmaf(s2_, 1.33333333f, 2.f);                         \
        if ((LI) == (LJ)) {                                                    \
            if (s_ < ONE_EPS) {                                                \
                float evp_ = even_ - odd_;                                     \
                SP += evp_; MN = fminf(MN, s_); gmx = fmaxf(gmx, s_);          \
                csp[NT][H] += evp_; cmnP[NT][H] = fminf(cmnP[NT][H], s_);      \
            }                                                                  \
        } else {                                                               \
            float evn_ = even_ + odd_;                                         \
            SN += evn_; MX = fmaxf(MX, s_); gmn = fminf(gmn, s_);              \
            csn[NT][H] += evn_; cmxN[NT][H] = fmaxf(cmxN[NT][H], s_);          \
        }                                                                      \
    }

__global__ void __launch_bounds__(256, 2) k_fallback(const float* __restrict__ feats,
                                                     const int* __restrict__ labels,
                                                     float* __restrict__ out) {
    if (g_fast | g_zero) return;
    extern __shared__ uint32_t dsm[];
    const uint32_t sb = (uint32_t)__cvta_generic_to_shared(dsm);
    __shared__ int slabi[BM];
    __shared__ int slabj[BN];
    __shared__ float sredA[8], sredB[8];

    const int tid = threadIdx.x, lane = tid & 31, warp = tid >> 5;

    // ---- phase A: fp32 -> bf16 convert ----
    {
        const int n4 = B_SZ * D_SZ / 4;
        const float4* f4 = reinterpret_cast<const float4*>(feats);
        for (int i = blockIdx.x * 256 + tid; i < n4; i += FB_GRID * 256) {
            float4 v = f4[i];
            __nv_bfloat162 lo = __floats2bfloat162_rn(v.x, v.y);
            __nv_bfloat162 hi = __floats2bfloat162_rn(v.z, v.w);
            uint2 o;
            o.x = *reinterpret_cast<unsigned*>(&lo);
            o.y = *reinterpret_cast<unsigned*>(&hi);
            reinterpret_cast<uint2*>(g_fbf)[i] = o;
        }
    }
    gsync(1 * FB_GRID);

    // ---- phase B: triangular HMMA GEMM + epilogue stats ----
    const int wm = warp >> 2, wn = warp & 3;
    const int r4 = lane >> 2, cq = lane & 3;
    const int arow = wm * 64 + (lane & 15);
    const int akw  = (lane >> 4) * 4;
    const int awoff = arow * PADW + akw;
    const int brow = wn * 32 + (lane & 7) + ((lane >= 16) ? 8 : 0);
    const int bkw  = ((lane >> 3) & 1) * 4;
    const int bwoff = brow * PADW + bkw;

    for (int kb = blockIdx.x; kb < NTRI; kb += FB_GRID) {
        __syncthreads();
        int bi = (int)(64.5f - sqrtf(64.5f * 64.5f - 2.0f * (float)kb));
        if (bi < 0) bi = 0;
        if (bi > 63) bi = 63;
        while (bi > 0 && bi * NBLK - bi * (bi - 1) / 2 > kb) --bi;
        while ((bi + 1) * NBLK - (bi + 1) * bi / 2 <= kb) ++bi;
        const int bj = bi + (kb - (bi * NBLK - bi * (bi - 1) / 2));
        const int i0 = bi * BM, j0 = bj * BN;
        const bool offdiag = (bi != bj);

        if (tid < BM) slabi[tid] = labels[i0 + tid];
        else if (tid < BM + BN) slabj[tid - BM] = labels[j0 + tid - BM];

        float acc[4][4][4];
#pragma unroll
        for (int mt = 0; mt < 4; ++mt)
#pragma unroll
            for (int nt = 0; nt < 4; ++nt)
#pragma unroll
                for (int e = 0; e < 4; ++e) acc[mt][nt][e] = 0.f;

        const int NK = D_SZ / BK;
        load_chunk(sb, 0, 0, i0, j0, tid);
        load_chunk(sb, 1, BK, i0, j0, tid);

        for (int kt = 0; kt < NK; ++kt) {
            const int s = kt % 3;
            if (kt + 1 < NK) asm volatile("cp.async.wait_group 1;\n" ::: "memory");
            else             asm volatile("cp.async.wait_group 0;\n" ::: "memory");
            __syncthreads();
            if (kt + 2 < NK) load_chunk(sb, (kt + 2) % 3, (kt + 2) * BK, i0, j0, tid);
#pragma unroll
            for (int ks = 0; ks < 2; ++ks) {
                const int ko = ks * 8;
                uint32_t a[4][4], b[2][4];
#pragma unroll
                for (int mt = 0; mt < 4; ++mt)
                    ldsm4(a[mt], sb + (SM_A(s) + awoff + mt * 16 * PADW + ko) * 4);
#pragma unroll
                for (int p = 0; p < 2; ++p)
                    ldsm4(b[p], sb + (SM_B(s) + bwoff + p * 16 * PADW + ko) * 4);
#pragma unroll
                for (int mt = 0; mt < 4; ++mt)
#pragma unroll
                    for (int nt = 0; nt < 4; ++nt) {
                        uint32_t bb[2] = {b[nt >> 1][(nt & 1) * 2], b[nt >> 1][(nt & 1) * 2 + 1]};
                        mma16816(acc[mt][nt], a[mt], bb);
                    }
            }
        }

        const float inv = 1.0f / g_end_norm;
        const float ONE_EPS = 1.0f - 1e-5f;
        const float INF = __int_as_float(0x7f800000);
        float csp[4][2], csn[4][2], cmnP[4][2], cmxN[4][2];
#pragma unroll
        for (int nt = 0; nt < 4; ++nt)
#pragma unroll
            for (int h = 0; h < 2; ++h) {
                csp[nt][h] = 0.f; csn[nt][h] = 0.f;
                cmnP[nt][h] = INF; cmxN[nt][h] = -INF;
            }
        float gmx = -INF, gmn = INF;

#pragma unroll
        for (int mt = 0; mt < 4; ++mt) {
            const int lr0 = mt * 16 + r4, lr1 = lr0 + 8;
            const int li0 = slabi[wm * 64 + lr0], li1 = slabi[wm * 64 + lr1];
            const int gi0 = i0 + wm * 64 + lr0, gi1 = i0 + wm * 64 + lr1;
            float sp0 = 0.f, sn0 = 0.f, mn0 = INF, mx0 = -INF;
            float sp1 = 0.f, sn1 = 0.f, mn1 = INF, mx1 = -INF;
#pragma unroll
            for (int nt = 0; nt < 4; ++nt) {
                const int lc = nt * 8 + 2 * cq;
                const int lj0 = slabj[wn * 32 + lc], lj1 = slabj[wn * 32 + lc + 1];
                PROC(acc[mt][nt][0], li0, lj0, sp0, sn0, mn0, mx0, nt, 0);
                PROC(acc[mt][nt][1], li0, lj1, sp0, sn0, mn0, mx0, nt, 1);
                PROC(acc[mt][nt][2], li1, lj0, sp1, sn1, mn1, mx1, nt, 0);
                PROC(acc[mt][nt][3], li1, lj1, sp1, sn1, mn1, mx1, nt, 1);
            }
#pragma unroll
            for (int o = 1; o < 4; o <<= 1) {
                sp0 += __shfl_xor_sync(0xffffffffu, sp0, o);
                sn0 += __shfl_xor_sync(0xffffffffu, sn0, o);
                mn0 = fminf(mn0, __shfl_xor_sync(0xffffffffu, mn0, o));
                mx0 = fmaxf(mx0, __shfl_xor_sync(0xffffffffu, mx0, o));
                sp1 += __shfl_xor_sync(0xffffffffu, sp1, o);
                sn1 += __shfl_xor_sync(0xffffffffu, sn1, o);
                mn1 = fminf(mn1, __shfl_xor_sync(0xffffffffu, mn1, o));
                mx1 = fmaxf(mx1, __shfl_xor_sync(0xffffffffu, mx1, o));
            }
            if (cq == 0) {
                atomicAdd(&g_sp[gi0], sp0);
                atomicAdd(&g_sn[gi0], sn0);
                atomicMin(&g_minpos[gi0], fenc(mn0));
                atomicMax(&g_maxneg[gi0], fenc(mx0));
                atomicAdd(&g_sp[gi1], sp1);
                atomicAdd(&g_sn[gi1], sn1);
                atomicMin(&g_minpos[gi1], fenc(mn1));
                atomicMax(&g_maxneg[gi1], fenc(mx1));
            }
        }
        if (offdiag) {
#pragma unroll
            for (int nt = 0; nt < 4; ++nt)
#pragma unroll
                for (int h = 0; h < 2; ++h) {
#pragma unroll
                    for (int o = 4; o < 32; o <<= 1) {
                        csp[nt][h] += __shfl_xor_sync(0xffffffffu, csp[nt][h], o);
                        csn[nt][h] += __shfl_xor_sync(0xffffffffu, csn[nt][h], o);
                        cmnP[nt][h] = fminf(cmnP[nt][h], __shfl_xor_sync(0xffffffffu, cmnP[nt][h], o));
                        cmxN[nt][h] = fmaxf(cmxN[nt][h], __shfl_xor_sync(0xffffffffu, cmxN[nt][h], o));
                    }
                }
            if (r4 == 0) {
#pragma unroll
                for (int nt = 0; nt < 4; ++nt) {
                    const int gj = j0 + wn * 32 + nt * 8 + 2 * cq;
                    atomicAdd(&g_sp[gj], csp[nt][0]);
                    atomicAdd(&g_sn[gj], csn[nt][0]);
                    atomicMin(&g_minpos[gj], fenc(cmnP[nt][0]));
                    atomicMax(&g_maxneg[gj], fenc(cmxN[nt][0]));
                    atomicAdd(&g_sp[gj + 1], csp[nt][1]);
                    atomicAdd(&g_sn[gj + 1], csn[nt][1]);
                    atomicMin(&g_minpos[gj + 1], fenc(cmnP[nt][1]));
                    atomicMax(&g_maxneg[gj + 1], fenc(cmxN[nt][1]));
                }
            }
        }
#pragma unroll
        for (int o = 16; o > 0; o >>= 1) {
            gmx = fmaxf(gmx, __shfl_xor_sync(0xffffffffu, gmx, o));
            gmn = fminf(gmn, __shfl_xor_sync(0xffffffffu, gmn, o));
        }
        if (lane == 0) { sredA[warp] = gmx; sredB[warp] = gmn; }
        __syncthreads();
        if (tid == 0) {
            float a = sredA[0], b = sredB[0];
#pragma unroll
            for (int w = 1; w < 8; ++w) { a = fmaxf(a, sredA[w]); b = fminf(b, sredB[w]); }
            atomicMax(&g_gmaxpos, fenc(a));
            atomicMin(&g_gminneg, fenc(b));
        }
    }
    gsync(2 * FB_GRID);

    // ---- phase C: per-row check ----
    {
        const float gmaxP = fdec(g_gmaxpos);
        const float gminN = fdec(g_gminneg);
        for (int r = blockIdx.x * 256 + tid; r < B_SZ; r += FB_GRID * 256) {
            const float minpos = fdec(g_minpos[r]);
            const float maxneg = fdec(g_maxneg[r]);
            const bool okP = (gmaxP - MARGIN < maxneg);
            const bool okN = (gminN + MARGIN > minpos);
            if (okP && okN) {
                float loss = 0.f;
                float sp = g_sp[r], sn = g_sn[r];
                if (sp > 0.f && sn > 0.f) {
                    const float E1 = 2.718281828459045f;
                    const float EINV = 0.36787944117144233f;
                    loss = 0.5f * log1pf(E1 * sp) + 0.5f * log1pf(EINV * sn);
                }
                g_rowloss[r] = loss;
            } else {
                g_rowloss[r] = 0.f;
                int idx = atomicAdd(&g_nfix, 1);
                g_fixlist[idx] = r;
            }
        }
    }
    gsync(3 * FB_GRID);

    // ---- phase D: exact fixup for flagged rows ----
    {
        float* fr = reinterpret_cast<float*>(dsm);            // D_SZ floats
        float* redp = fr + D_SZ;                               // 256
        float* redn = redp + 256;                              // 256
        const int n = g_nfix;
        for (int w = blockIdx.x; w < n; w += FB_GRID) {
            const int r = g_fixlist[w];
            for (int k = tid; k < D_SZ; k += 256)
                fr[k] = __bfloat162float(g_fbf[(size_t)r * D_SZ + k]);
            __syncthreads();
            const float inv = 1.0f / g_end_norm;
            const float minpos = fdec(g_minpos[r]);
            const float maxneg = fdec(g_maxneg[r]);
            const int lr = labels[r];
            const float ONE_EPS = 1.0f - 1e-5f;
            float sp = 0.f, sn = 0.f;
            for (int j = tid; j < B_SZ; j += 256) {
                const __nv_bfloat162* fj =
                    reinterpret_cast<const __nv_bfloat162*>(g_fbf + (size_t)j * D_SZ);
                float d = 0.f;
                for (int k = 0; k < D_SZ / 2; ++k) {
                    float2 v = __bfloat1622float2(fj[k]);
                    d = fmaf(fr[2 * k], v.x, d);
                    d = fmaf(fr[2 * k + 1], v.y, d);
                }
                float s = d * inv;
                if (labels[j] == lr) {
                    if (s < ONE_EPS && (s - MARGIN < maxneg)) sp += __expf(-2.f * (s - 0.5f));
                } else if (s + MARGIN > minpos) {
                    sn += __expf(2.f * (s - 0.5f));
                }
            }
            redp[tid] = sp;
            redn[tid] = sn;
            __syncthreads();
            for (int o = 128; o > 0; o >>= 1) {
                if (tid < o) { redp[tid] += redp[tid + o]; redn[tid] += redn[tid + o]; }
                __syncthreads();
            }
            if (tid == 0) {
                float loss = 0.f;
                if (redp[0] > 0.f && redn[0] > 0.f)
                    loss = 0.5f * log1pf(redp[0]) + 0.5f * log1pf(redn[0]);
                g_rowloss[r] = loss;
            }
            __syncthreads();
        }
    }
    gsync(4 * FB_GRID);

    // ---- phase E: final reduction (block 0) + barrier reset ----
    if (blockIdx.x == 0) {
        float* red = reinterpret_cast<float*>(dsm);
        float s = 0.f;
        for (int i = tid; i < B_SZ; i += 256) s += g_rowloss[i];
        red[tid] = s;
        __syncthreads();
        for (int o = 128; o > 0; o >>= 1) {
            if (tid < o) red[tid] += red[tid + o];
            __syncthreads();
        }
        if (tid == 0) { out[0] = red[0] * (1.0f / B_SZ); g_fbar = 0; }
    }
}

// ================= launch =================
extern "C" void kernel_launch(void* const* d_in, const int* in_sizes, int n_in,
                              void* d_out, int out_size) {
    const float* feats = (const float*)d_in[0];
    const int* labels = (const int*)d_in[1];
    (void)in_sizes; (void)n_in; (void)out_size;

    static int once = 0;
    if (!once) {
        cudaFuncSetAttribute(k_fallback, cudaFuncAttributeMaxDynamicSharedMemorySize, SMEM_BYTES);
        once = 1;
    }

    k_prep<<<256, 256>>>(feats, labels);
    k_cent<<<104, 256>>>(feats);
    k_row<<<512, 256>>>(feats, labels, (float*)d_out);
    k_fallback<<<FB_GRID, 256, SMEM_BYTES>>>(feats, labels, (float*)d_out);
}

// round 12
// speedup vs baseline: 14.8246x; 1.2000x over previous
#include <cuda_runtime.h>
#include <cuda_bf16.h>
#include <cstdint>
#include <cstddef>

#define B_SZ 8192
#define D_SZ 512
#define MARGIN 0.1f

#define BM 128
#define BN 128
#define BK 32
#define PADW 20
#define NBLK 64
#define NTRI 2080
#define FB_GRID 148

#define SM_A(s)  ((s) * 5120)
#define SM_B(s)  ((s) * 5120 + 2560)
#define SMEM_BYTES 61440

// ---------------- device scratch ----------------
static __device__ __nv_bfloat16 g_fbf[B_SZ * D_SZ];   // bf16 feats (fallback only)
static __device__ float    g_sp[B_SZ];
static __device__ float    g_sn[B_SZ];
static __device__ unsigned g_minpos[B_SZ];
static __device__ unsigned g_maxneg[B_SZ];
static __device__ unsigned g_gmaxpos;
static __device__ unsigned g_gminneg;
static __device__ float    g_end_norm;
static __device__ float    g_invE;
static __device__ float    g_rowloss[B_SZ];
static __device__ int      g_fixlist[B_SZ];
static __device__ int      g_nfix;
// fast-path state
static __device__ float    g_C[512];
static __device__ float    g_cent[100 * 512];
static __device__ int      g_perm[B_SZ];
static __device__ int      g_off[101];
static __device__ int      g_cntg[100];
static __device__ int      g_cnth[100];               // histogram; consumed+reset per replay
static __device__ unsigned g_offa[100];
static __device__ unsigned g_maxn;                    // atomicMax, idempotent across replays
static __device__ float    g_esum;                    // reset after consumption
static __device__ float    g_loss;                    // reset in phase V
static __device__ int      g_fast;
static __device__ int      g_zero;
static __device__ unsigned g_fbarA;                   // k_fast barrier; reset by k_fallback
static __device__ unsigned g_fbarB;                   // k_fallback barrier; reset by k_fast

__device__ __forceinline__ unsigned fenc(float f) {
    unsigned u = __float_as_uint(f);
    return (u & 0x80000000u) ? ~u : (u | 0x80000000u);
}
__device__ __forceinline__ float fdec(unsigned u) {
    return (u & 0x80000000u) ? __uint_as_float(u ^ 0x80000000u) : __uint_as_float(~u);
}

__device__ __forceinline__ void gsyncA(unsigned target) {
    __syncthreads();
    if (threadIdx.x == 0) {
        __threadfence();
        atomicAdd(&g_fbarA, 1u);
        while (*(volatile unsigned*)&g_fbarA < target) { }
    }
    __syncthreads();
    __threadfence();
}

// ================= k_fast: whole fast path in one persistent kernel =================
__global__ void __launch_bounds__(512, 1) k_fast(const float* __restrict__ feats,
                                                 const int* __restrict__ labels,
                                                 float* __restrict__ out) {
    const int b = blockIdx.x, t = threadIdx.x;
    const int warp = t >> 5, lane = t & 31;
    __shared__ float eW[16], mW[16];
    __shared__ float Cs[512];
    __shared__ int sperm2[56], slab2[56];

    // ---- phase A: resets, zero cent/C, norms + histogram ----
    if (b == 0 && t == 0) g_fbarB = 0;   // k_fallback finished last replay (stream order)
    for (int i = b * 512 + t; i < 100 * 512; i += FB_GRID * 512) g_cent[i] = 0.f;
    if (b == 1) g_C[t] = 0.f;

    {
        const float4* f4 = reinterpret_cast<const float4*>(feats);
        const int gw = b * 16 + warp;     // 0..2367
        float esum = 0.f, mmax = 0.f;
        for (int row = gw; row < B_SZ; row += FB_GRID * 16) {
            float rsq = 0.f;
#pragma unroll
            for (int it = 0; it < 4; ++it) {
                float4 v = f4[(size_t)row * 128 + it * 32 + lane];
                rsq += v.x * v.x + v.y * v.y + v.z * v.z + v.w * v.w;
            }
#pragma unroll
            for (int o = 16; o > 0; o >>= 1) rsq += __shfl_xor_sync(0xffffffffu, rsq, o);
            if (lane == 0) { esum += rsq; atomicAdd(&g_cnth[labels[row]], 1); }
            mmax = fmaxf(mmax, rsq);
        }
        if (lane == 0) { eW[warp] = esum; mW[warp] = mmax; }
        __syncthreads();
        if (t == 0) {
            float E = 0.f, m = 0.f;
#pragma unroll
            for (int w = 0; w < 16; ++w) { E += eW[w]; m = fmaxf(m, mW[w]); }
            atomicAdd(&g_esum, E);
            atomicMax(&g_maxn, fenc(m));
        }
    }
    gsyncA(1 * FB_GRID);

    // ---- phase V: block 0 computes flags/prefix/offsets ----
    if (b == 0) {
        __shared__ int cnt[100], off[101];
        if (t < 100) { cnt[t] = g_cnth[t]; g_cnth[t] = 0; }
        __syncthreads();
        if (t == 0) {
            int acc = 0, mxc = 0;
            for (int l = 0; l < 100; ++l) { off[l] = acc; acc += cnt[l]; mxc = max(mxc, cnt[l]); }
            off[100] = acc;
            float E = g_esum;
            g_esum = 0.f;
            float M2 = __uint_as_float(g_maxn & 0x7fffffffu);
            float Mp = (E > 0.f) ? M2 / E : 1.f;            // rigorous |sim| bound
            int zero = (mxc == B_SZ) ? 1 : 0;
            int fast = (E > 0.f) && (2.f * Mp < MARGIN * 0.9f) &&
                       (2.1f * (float)B_SZ * Mp * Mp < 1e-3f) && !zero;
            g_zero = zero;
            g_fast = fast ? 1 : 0;
            g_end_norm = E;
            g_invE = (E > 0.f) ? 1.f / E : 0.f;
            g_loss = 0.f;
            g_nfix = 0;
            g_gmaxpos = 0x007FFFFFu;
            g_gminneg = 0xFF800000u;
        }
        __syncthreads();
        if (t < 100) { g_cntg[t] = cnt[t]; g_off[t] = off[t]; g_offa[t] = (unsigned)off[t]; }
        if (t == 100) g_off[100] = B_SZ;
        __syncthreads();
        if (!g_fast && !g_zero) {   // init fallback accumulators
            for (int i = t; i < B_SZ; i += 512) {
                g_sp[i] = 0.f; g_sn[i] = 0.f;
                g_minpos[i] = 0xFF800000u;
                g_maxneg[i] = 0x007FFFFFu;
            }
        }
    }
    gsyncA(2 * FB_GRID);

    const int fast = g_fast, zero = g_zero;
    if (!fast && !zero) return;   // fallback kernel takes over; g_fbarA reset there

    // ---- phase P: parallel perm build ----
    for (int i = b * 512 + t; i < B_SZ; i += FB_GRID * 512) {
        unsigned p = atomicAdd(&g_offa[labels[i]], 1u);
        g_perm[p] = i;
    }
    gsyncA(3 * FB_GRID);

    // ---- phase B: centroid + C accumulation via perm chunks ----
    {
        const int start = b * 56;
        int n = B_SZ - start;
        if (n > 56) n = 56;
        if (n < 0) n = 0;
        if (t < n) { int r = g_perm[start + t]; sperm2[t] = r; slab2[t] = labels[r]; }
        __syncthreads();
        if (fast && n > 0) {
            int cl = -1;
            float ax = 0.f, cx = 0.f;
#pragma unroll 8
            for (int k = 0; k < n; ++k) {
                int row = sperm2[k];
                int l = slab2[k];
                float v = feats[(size_t)row * 512 + t];
                if (l != cl) {
                    if (cl >= 0) atomicAdd(&g_cent[cl * 512 + t], ax);
                    cl = l; ax = 0.f;
                }
                ax += v; cx += v;
            }
            if (cl >= 0) atomicAdd(&g_cent[cl * 512 + t], ax);
            atomicAdd(&g_C[t], cx);
        }
    }
    gsyncA(4 * FB_GRID);

    // ---- phase C: per-row analytic loss (L2-warm feats) ----
    Cs[t] = g_C[t];
    __syncthreads();
    if (fast) {
        const float4* f4 = reinterpret_cast<const float4*>(feats);
        const float4* c4 = reinterpret_cast<const float4*>(g_cent);
        const float4* C4 = reinterpret_cast<const float4*>(Cs);
        const float invE = g_invE;
        const float E1 = 2.718281828459045f;
        const float EINV = 0.36787944117144233f;
        const int gw = b * 16 + warp;
        float wl = 0.f;
        for (int row = gw; row < B_SZ; row += FB_GRID * 16) {
            const int lab = labels[row];
            float dp = 0.f, da = 0.f;
#pragma unroll
            for (int it = 0; it < 4; ++it) {
                float4 a = f4[(size_t)row * 128 + it * 32 + lane];
                float4 bb = c4[(size_t)lab * 128 + it * 32 + lane];
                float4 cc = C4[it * 32 + lane];
                dp = fmaf(a.x, bb.x, fmaf(a.y, bb.y, fmaf(a.z, bb.z, fmaf(a.w, bb.w, dp))));
                da = fmaf(a.x, cc.x, fmaf(a.y, cc.y, fmaf(a.z, cc.z, fmaf(a.w, cc.w, da))));
            }
#pragma unroll
            for (int o = 16; o > 0; o >>= 1) {
                dp += __shfl_xor_sync(0xffffffffu, dp, o);
                da += __shfl_xor_sync(0xffffffffu, da, o);
            }
            if (lane == 0) {
                float n = (float)g_cntg[lab];
                float sp = n - 2.f * dp * invE;
                float sn = ((float)B_SZ - n) + 2.f * (da - dp) * invE;
                wl += 0.5f * log1pf(E1 * sp) + 0.5f * log1pf(EINV * sn);
            }
        }
        if (lane == 0) eW[warp] = wl;
        __syncthreads();
        if (t == 0) {
            float s = 0.f;
#pragma unroll
            for (int w = 0; w < 16; ++w) s += eW[w];
            atomicAdd(&g_loss, s);
        }
    }
    // (zero case: g_loss stays 0)

    // ---- final barrier: others arrive+exit, block 0 waits and writes ----
    __syncthreads();
    __threadfence();
    if (t == 0) {
        atomicAdd(&g_fbarA, 1u);
        if (b == 0) {
            while (*(volatile unsigned*)&g_fbarA < 5u * FB_GRID) { }
            __threadfence();
            out[0] = (*(volatile float*)&g_loss) * (1.0f / B_SZ);
        }
    }
}

// ================= fallback: conv + GEMM + check + fixup + final in ONE kernel =================
__device__ __forceinline__ void mma16816(float* d, const uint32_t* a, const uint32_t* b) {
    asm volatile(
        "mma.sync.aligned.m16n8k16.row.col.f32.bf16.bf16.f32 "
        "{%0,%1,%2,%3}, {%4,%5,%6,%7}, {%8,%9}, {%0,%1,%2,%3};\n"
        : "+f"(d[0]), "+f"(d[1]), "+f"(d[2]), "+f"(d[3])
        : "r"(a[0]), "r"(a[1]), "r"(a[2]), "r"(a[3]), "r"(b[0]), "r"(b[1]));
}
__device__ __forceinline__ void ldsm4(uint32_t* d, uint32_t saddr) {
    asm volatile("ldmatrix.sync.aligned.m8n8.x4.shared.b16 {%0,%1,%2,%3}, [%4];"
                 : "=r"(d[0]), "=r"(d[1]), "=r"(d[2]), "=r"(d[3]) : "r"(saddr));
}
__device__ __forceinline__ void cpa16(uint32_t saddr, const void* g) {
    asm volatile("cp.async.cg.shared.global [%0], [%1], 16;\n" :: "r"(saddr), "l"(g));
}
__device__ __forceinline__ void load_chunk(uint32_t sb, int stage, int kbase,
                                           int i0, int j0, int tid) {
    const int r = tid >> 2, q = tid & 3;
#pragma unroll
    for (int h = 0; h < 2; ++h) {
        int rr = r + h * 64;
        cpa16(sb + (SM_A(stage) + rr * PADW + q * 4) * 4,
              g_fbf + (size_t)(i0 + rr) * D_SZ + kbase + q * 8);
        cpa16(sb + (SM_B(stage) + rr * PADW + q * 4) * 4,
              g_fbf + (size_t)(j0 + rr) * D_SZ + kbase + q * 8);
    }
    asm volatile("cp.async.commit_group;\n" ::: "memory");
}
__device__ __forceinline__ void gsyncB(unsigned target) {
    __syncthreads();
    if (threadIdx.x == 0) {
        __threadfence();
        atomicAdd(&g_fbarB, 1u);
        while (*(volatile unsigned*)&g_fbarB < target) { }
    }
    __syncthreads();
    __threadfence();
}
#define PROC(SRAW, LI, LJ, SP, SN, MN, MX, NT, H)                              \
    {                                                                          \
        float s_ = (SRAW) * inv;                                               \
        float s2_ = s_ * s_;                                                   \
        float even_ = fmaf(s2_, 2.f, 1.f);                                     \
        float odd_ = s_ * fmaf(s2_, 1.33333333f, 2.f);                         \
        if ((LI) == (LJ)) {                                                    \
            if (s_ < ONE_EPS) {                                                \
                float evp_ = even_ - odd_;                                     \
                SP += evp_; MN = fminf(MN, s_); gmx = fmaxf(gmx, s_);          \
                csp[NT][H] += evp_; cmnP[NT][H] = fminf(cmnP[NT][H], s_);      \
            }                                                                  \
        } else {                                                               \
            float evn_ = even_ + odd_;                                         \
            SN += evn_; MX = fmaxf(MX, s_); gmn = fminf(gmn, s_);              \
            csn[NT][H] += evn_; cmxN[NT][H] = fmaxf(cmxN[NT][H], s_);          \
        }                                                                      \
    }

__global__ void __launch_bounds__(256, 2) k_fallback(const float* __restrict__ feats,
                                                     const int* __restrict__ labels,
                                                     float* __restrict__ out) {
    // reset k_fast's barrier for next replay (k_fast fully done — stream order)
    if (blockIdx.x == 0 && threadIdx.x == 0) g_fbarA = 0;
    if (g_fast | g_zero) return;
    extern __shared__ uint32_t dsm[];
    const uint32_t sb = (uint32_t)__cvta_generic_to_shared(dsm);
    __shared__ int slabi[BM];
    __shared__ int slabj[BN];
    __shared__ float sredA[8], sredB[8];

    const int tid = threadIdx.x, lane = tid & 31, warp = tid >> 5;

    // ---- phase A: fp32 -> bf16 convert ----
    {
        const int n4 = B_SZ * D_SZ / 4;
        const float4* f4 = reinterpret_cast<const float4*>(feats);
        for (int i = blockIdx.x * 256 + tid; i < n4; i += FB_GRID * 256) {
            float4 v = f4[i];
            __nv_bfloat162 lo = __floats2bfloat162_rn(v.x, v.y);
            __nv_bfloat162 hi = __floats2bfloat162_rn(v.z, v.w);
            uint2 o;
            o.x = *reinterpret_cast<unsigned*>(&lo);
            o.y = *reinterpret_cast<unsigned*>(&hi);
            reinterpret_cast<uint2*>(g_fbf)[i] = o;
        }
    }
    gsyncB(1 * FB_GRID);

    // ---- phase B: triangular HMMA GEMM + epilogue stats ----
    const int wm = warp >> 2, wn = warp & 3;
    const int r4 = lane >> 2, cq = lane & 3;
    const int arow = wm * 64 + (lane & 15);
    const int akw  = (lane >> 4) * 4;
    const int awoff = arow * PADW + akw;
    const int brow = wn * 32 + (lane & 7) + ((lane >= 16) ? 8 : 0);
    const int bkw  = ((lane >> 3) & 1) * 4;
    const int bwoff = brow * PADW + bkw;

    for (int kb = blockIdx.x; kb < NTRI; kb += FB_GRID) {
        __syncthreads();
        int bi = (int)(64.5f - sqrtf(64.5f * 64.5f - 2.0f * (float)kb));
        if (bi < 0) bi = 0;
        if (bi > 63) bi = 63;
        while (bi > 0 && bi * NBLK - bi * (bi - 1) / 2 > kb) --bi;
        while ((bi + 1) * NBLK - (bi + 1) * bi / 2 <= kb) ++bi;
        const int bj = bi + (kb - (bi * NBLK - bi * (bi - 1) / 2));
        const int i0 = bi * BM, j0 = bj * BN;
        const bool offdiag = (bi != bj);

        if (tid < BM) slabi[tid] = labels[i0 + tid];
        else if (tid < BM + BN) slabj[tid - BM] = labels[j0 + tid - BM];

        float acc[4][4][4];
#pragma unroll
        for (int mt = 0; mt < 4; ++mt)
#pragma unroll
            for (int nt = 0; nt < 4; ++nt)
#pragma unroll
                for (int e = 0; e < 4; ++e) acc[mt][nt][e] = 0.f;

        const int NK = D_SZ / BK;
        load_chunk(sb, 0, 0, i0, j0, tid);
        load_chunk(sb, 1, BK, i0, j0, tid);

        for (int kt = 0; kt < NK; ++kt) {
            const int s = kt % 3;
            if (kt + 1 < NK) asm volatile("cp.async.wait_group 1;\n" ::: "memory");
            else             asm volatile("cp.async.wait_group 0;\n" ::: "memory");
            __syncthreads();
            if (kt + 2 < NK) load_chunk(sb, (kt + 2) % 3, (kt + 2) * BK, i0, j0, tid);
#pragma unroll
            for (int ks = 0; ks < 2; ++ks) {
                const int ko = ks * 8;
                uint32_t a[4][4], b[2][4];
#pragma unroll
                for (int mt = 0; mt < 4; ++mt)
                    ldsm4(a[mt], sb + (SM_A(s) + awoff + mt * 16 * PADW + ko) * 4);
#pragma unroll
                for (int p = 0; p < 2; ++p)
                    ldsm4(b[p], sb + (SM_B(s) + bwoff + p * 16 * PADW + ko) * 4);
#pragma unroll
                for (int mt = 0; mt < 4; ++mt)
#pragma unroll
                    for (int nt = 0; nt < 4; ++nt) {
                        uint32_t bb[2] = {b[nt >> 1][(nt & 1) * 2], b[nt >> 1][(nt & 1) * 2 + 1]};
                        mma16816(acc[mt][nt], a[mt], bb);
                    }
            }
        }

        const float inv = 1.0f / g_end_norm;
        const float ONE_EPS = 1.0f - 1e-5f;
        const float INF = __int_as_float(0x7f800000);
        float csp[4][2], csn[4][2], cmnP[4][2], cmxN[4][2];
#pragma unroll
        for (int nt = 0; nt < 4; ++nt)
#pragma unroll
            for (int h = 0; h < 2; ++h) {
                csp[nt][h] = 0.f; csn[nt][h] = 0.f;
                cmnP[nt][h] = INF; cmxN[nt][h] = -INF;
            }
        float gmx = -INF, gmn = INF;

#pragma unroll
        for (int mt = 0; mt < 4; ++mt) {
            const int lr0 = mt * 16 + r4, lr1 = lr0 + 8;
            const int li0 = slabi[wm * 64 + lr0], li1 = slabi[wm * 64 + lr1];
            const int gi0 = i0 + wm * 64 + lr0, gi1 = i0 + wm * 64 + lr1;
            float sp0 = 0.f, sn0 = 0.f, mn0 = INF, mx0 = -INF;
            float sp1 = 0.f, sn1 = 0.f, mn1 = INF, mx1 = -INF;
#pragma unroll
            for (int nt = 0; nt < 4; ++nt) {
                const int lc = nt * 8 + 2 * cq;
                const int lj0 = slabj[wn * 32 + lc], lj1 = slabj[wn * 32 + lc + 1];
                PROC(acc[mt][nt][0], li0, lj0, sp0, sn0, mn0, mx0, nt, 0);
                PROC(acc[mt][nt][1], li0, lj1, sp0, sn0, mn0, mx0, nt, 1);
                PROC(acc[mt][nt][2], li1, lj0, sp1, sn1, mn1, mx1, nt, 0);
                PROC(acc[mt][nt][3], li1, lj1, sp1, sn1, mn1, mx1, nt, 1);
            }
#pragma unroll
            for (int o = 1; o < 4; o <<= 1) {
                sp0 += __shfl_xor_sync(0xffffffffu, sp0, o);
                sn0 += __shfl_xor_sync(0xffffffffu, sn0, o);
                mn0 = fminf(mn0, __shfl_xor_sync(0xffffffffu, mn0, o));
                mx0 = fmaxf(mx0, __shfl_xor_sync(0xffffffffu, mx0, o));
                sp1 += __shfl_xor_sync(0xffffffffu, sp1, o);
                sn1 += __shfl_xor_sync(0xffffffffu, sn1, o);
                mn1 = fminf(mn1, __shfl_xor_sync(0xffffffffu, mn1, o));
                mx1 = fmaxf(mx1, __shfl_xor_sync(0xffffffffu, mx1, o));
            }
            if (cq == 0) {
                atomicAdd(&g_sp[gi0], sp0);
                atomicAdd(&g_sn[gi0], sn0);
                atomicMin(&g_minpos[gi0], fenc(mn0));
                atomicMax(&g_maxneg[gi0], fenc(mx0));
                atomicAdd(&g_sp[gi1], sp1);
                atomicAdd(&g_sn[gi1], sn1);
                atomicMin(&g_minpos[gi1], fenc(mn1));
                atomicMax(&g_maxneg[gi1], fenc(mx1));
            }
        }
        if (offdiag) {
#pragma unroll
            for (int nt = 0; nt < 4; ++nt)
#pragma unroll
                for (int h = 0; h < 2; ++h) {
#pragma unroll
                    for (int o = 4; o < 32; o <<= 1) {
                        csp[nt][h] += __shfl_xor_sync(0xffffffffu, csp[nt][h], o);
                        csn[nt][h] += __shfl_xor_sync(0xffffffffu, csn[nt][h], o);
                        cmnP[nt][h] = fminf(cmnP[nt][h], __shfl_xor_sync(0xffffffffu, cmnP[nt][h], o));
                        cmxN[nt][h] = fmaxf(cmxN[nt][h], __shfl_xor_sync(0xffffffffu, cmxN[nt][h], o));
                    }
                }
            if (r4 == 0) {
#pragma unroll
                for (int nt = 0; nt < 4; ++nt) {
                    const int gj = j0 + wn * 32 + nt * 8 + 2 * cq;
                    atomicAdd(&g_sp[gj], csp[nt][0]);
                    atomicAdd(&g_sn[gj], csn[nt][0]);
                    atomicMin(&g_minpos[gj], fenc(cmnP[nt][0]));
                    atomicMax(&g_maxneg[gj], fenc(cmxN[nt][0]));
                    atomicAdd(&g_sp[gj + 1], csp[nt][1]);
                    atomicAdd(&g_sn[gj + 1], csn[nt][1]);
                    atomicMin(&g_minpos[gj + 1], fenc(cmnP[nt][1]));
                    atomicMax(&g_maxneg[gj + 1], fenc(cmxN[nt][1]));
                }
            }
        }
#pragma unroll
        for (int o = 16; o > 0; o >>= 1) {
            gmx = fmaxf(gmx, __shfl_xor_sync(0xffffffffu, gmx, o));
            gmn = fminf(gmn, __shfl_xor_sync(0xffffffffu, gmn, o));
        }
        if (lane == 0) { sredA[warp] = gmx; sredB[warp] = gmn; }
        __syncthreads();
        if (tid == 0) {
            float a = sredA[0], b = sredB[0];
#pragma unroll
            for (int w = 1; w < 8; ++w) { a = fmaxf(a, sredA[w]); b = fminf(b, sredB[w]); }
            atomicMax(&g_gmaxpos, fenc(a));
            atomicMin(&g_gminneg, fenc(b));
        }
    }
    gsyncB(2 * FB_GRID);

    // ---- phase C: per-row check ----
    {
        const float gmaxP = fdec(g_gmaxpos);
        const float gminN = fdec(g_gminneg);
        for (int r = blockIdx.x * 256 + tid; r < B_SZ; r += FB_GRID * 256) {
            const float minpos = fdec(g_minpos[r]);
            const float maxneg = fdec(g_maxneg[r]);
            const bool okP = (gmaxP - MARGIN < maxneg);
            const bool okN = (gminN + MARGIN > minpos);
            if (okP && okN) {
                float loss = 0.f;
                float sp = g_sp[r], sn = g_sn[r];
                if (sp > 0.f && sn > 0.f) {
                    const float E1 = 2.718281828459045f;
                    const float EINV = 0.36787944117144233f;
                    loss = 0.5f * log1pf(E1 * sp) + 0.5f * log1pf(EINV * sn);
                }
                g_rowloss[r] = loss;
            } else {
                g_rowloss[r] = 0.f;
                int idx = atomicAdd(&g_nfix, 1);
                g_fixlist[idx] = r;
            }
        }
    }
    gsyncB(3 * FB_GRID);

    // ---- phase D: exact fixup for flagged rows ----
    {
        float* fr = reinterpret_cast<float*>(dsm);
        float* redp = fr + D_SZ;
        float* redn = redp + 256;
        const int n = g_nfix;
        for (int w = blockIdx.x; w < n; w += FB_GRID) {
            const int r = g_fixlist[w];
            for (int k = tid; k < D_SZ; k += 256)
                fr[k] = __bfloat162float(g_fbf[(size_t)r * D_SZ + k]);
            __syncthreads();
            const float inv = 1.0f / g_end_norm;
            const float minpos = fdec(g_minpos[r]);
            const float maxneg = fdec(g_maxneg[r]);
            const int lr = labels[r];
            const float ONE_EPS = 1.0f - 1e-5f;
            float sp = 0.f, sn = 0.f;
            for (int j = tid; j < B_SZ; j += 256) {
                const __nv_bfloat162* fj =
                    reinterpret_cast<const __nv_bfloat162*>(g_fbf + (size_t)j * D_SZ);
                float d = 0.f;
                for (int k = 0; k < D_SZ / 2; ++k) {
                    float2 v = __bfloat1622float2(fj[k]);
                    d = fmaf(fr[2 * k], v.x, d);
                    d = fmaf(fr[2 * k + 1], v.y, d);
                }
                float s = d * inv;
                if (labels[j] == lr) {
                    if (s < ONE_EPS && (s - MARGIN < maxneg)) sp += __expf(-2.f * (s - 0.5f));
                } else if (s + MARGIN > minpos) {
                    sn += __expf(2.f * (s - 0.5f));
                }
            }
            redp[tid] = sp;
            redn[tid] = sn;
            __syncthreads();
            for (int o = 128; o > 0; o >>= 1) {
                if (tid < o) { redp[tid] += redp[tid + o]; redn[tid] += redn[tid + o]; }
                __syncthreads();
            }
            if (tid == 0) {
                float loss = 0.f;
                if (redp[0] > 0.f && redn[0] > 0.f)
                    loss = 0.5f * log1pf(redp[0]) + 0.5f * log1pf(redn[0]);
                g_rowloss[r] = loss;
            }
            __syncthreads();
        }
    }
    gsyncB(4 * FB_GRID);

    // ---- phase E: final reduction (block 0); g_fbarB reset by next k_fast ----
    if (blockIdx.x == 0) {
        float* red = reinterpret_cast<float*>(dsm);
        float s = 0.f;
        for (int i = tid; i < B_SZ; i += 256) s += g_rowloss[i];
        red[tid] = s;
        __syncthreads();
        for (int o = 128; o > 0; o >>= 1) {
            if (tid < o) red[tid] += red[tid + o];
            __syncthreads();
        }
        if (tid == 0) out[0] = red[0] * (1.0f / B_SZ);
    }
}

// ================= launch =================
extern "C" void kernel_launch(void* const* d_in, const int* in_sizes, int n_in,
                              void* d_out, int out_size) {
    const float* feats = (const float*)d_in[0];
    const int* labels = (const int*)d_in[1];
    (void)in_sizes; (void)n_in; (void)out_size;

    static int once = 0;
    if (!once) {
        cudaFuncSetAttribute(k_fallback, cudaFuncAttributeMaxDynamicSharedMemorySize, SMEM_BYTES);
        once = 1;
    }

    k_fast<<<FB_GRID, 512>>>(feats, labels, (float*)d_out);
    k_fallback<<<FB_GRID, 256, SMEM_BYTES>>>(feats, labels, (float*)d_out);
}

// round 14
// speedup vs baseline: 14.9469x; 1.0083x over previous
#include <cuda_runtime.h>
#include <cuda_bf16.h>
#include <cstdint>
#include <cstddef>

#define B_SZ 8192
#define D_SZ 512
#define MARGIN 0.1f

#define BM 128
#define BN 128
#define BK 32
#define PADW 20
#define NBLK 64
#define NTRI 2080
#define FGRID 296        // k_fast: 2 CTAs/SM
#define FB_GRID 148      // k_fallback: 1 CTA/SM (61KB smem)
#define CHUNK 28         // ceil(8192/296)

#define SM_A(s)  ((s) * 5120)
#define SM_B(s)  ((s) * 5120 + 2560)
#define SMEM_BYTES 61440

// ---------------- device scratch ----------------
static __device__ __nv_bfloat16 g_fbf[B_SZ * D_SZ];   // bf16 feats (fallback only)
static __device__ float    g_sp[B_SZ];
static __device__ float    g_sn[B_SZ];
static __device__ unsigned g_minpos[B_SZ];
static __device__ unsigned g_maxneg[B_SZ];
static __device__ unsigned g_gmaxpos;
static __device__ unsigned g_gminneg;
static __device__ float    g_end_norm;
static __device__ float    g_invE;
static __device__ float    g_rowloss[B_SZ];
static __device__ int      g_fixlist[B_SZ];
static __device__ int      g_nfix;
// fast-path state
static __device__ float    g_C[512];
static __device__ float    g_cent[100 * 512];
static __device__ int      g_perm[B_SZ];
static __device__ int      g_cntg[100];
static __device__ int      g_cnth[100];               // histogram; reset by k_fallback prologue
static __device__ unsigned g_offa[100];               // per-class rank ctr; reset by k_fallback
static __device__ unsigned g_maxn;                    // atomicMax, idempotent across replays
static __device__ float    g_esum;                    // consumed+reset in VP
static __device__ float    g_loss;                    // reset in VP
static __device__ int      g_fast;
static __device__ int      g_zero;
static __device__ unsigned g_fbarA;                   // k_fast barrier; reset by k_fallback
static __device__ unsigned g_fbarB;                   // k_fallback barrier; reset by k_fast

__device__ __forceinline__ unsigned fenc(float f) {
    unsigned u = __float_as_uint(f);
    return (u & 0x80000000u) ? ~u : (u | 0x80000000u);
}
__device__ __forceinline__ float fdec(unsigned u) {
    return (u & 0x80000000u) ? __uint_as_float(u ^ 0x80000000u) : __uint_as_float(~u);
}

__device__ __forceinline__ void gsyncA(unsigned target) {
    __syncthreads();
    if (threadIdx.x == 0) {
        __threadfence();
        atomicAdd(&g_fbarA, 1u);
        while (*(volatile unsigned*)&g_fbarA < target) { }
    }
    __syncthreads();
    __threadfence();
}

// ================= k_fast: whole fast path, one persistent kernel, 2 CTAs/SM =================
__global__ void __launch_bounds__(512, 2) k_fast(const float* __restrict__ feats,
                                                 const int* __restrict__ labels,
                                                 float* __restrict__ out) {
    const int b = blockIdx.x, t = threadIdx.x;
    const int warp = t >> 5, lane = t & 31;
    __shared__ float eW[16], mW[16];
    __shared__ float Cs[512];
    __shared__ int sperm2[CHUNK], slab2[CHUNK];
    __shared__ int cnt[100], soff[101];

    // ---- phase A: resets, zero cent/C, norms + histogram ----
    if (b == 0 && t == 0) g_fbarB = 0;   // k_fallback of last replay done (stream order)
    if (b == 2) g_C[t] = 0.f;
    for (int i = b * 512 + t; i < 100 * 512; i += FGRID * 512) g_cent[i] = 0.f;

    {
        const float4* f4 = reinterpret_cast<const float4*>(feats);
        const int gw = b * 16 + warp;     // 0..4735
        float esum = 0.f, mmax = 0.f;
        for (int row = gw; row < B_SZ; row += FGRID * 16) {
            float rsq = 0.f;
#pragma unroll
            for (int it = 0; it < 4; ++it) {
                float4 v = f4[(size_t)row * 128 + it * 32 + lane];
                rsq += v.x * v.x + v.y * v.y + v.z * v.z + v.w * v.w;
            }
#pragma unroll
            for (int o = 16; o > 0; o >>= 1) rsq += __shfl_xor_sync(0xffffffffu, rsq, o);
            if (lane == 0) { esum += rsq; atomicAdd(&g_cnth[labels[row]], 1); }
            mmax = fmaxf(mmax, rsq);
        }
        if (lane == 0) { eW[warp] = esum; mW[warp] = mmax; }
        __syncthreads();
        if (t == 0) {
            float E = 0.f, m = 0.f;
#pragma unroll
            for (int w = 0; w < 16; ++w) { E += eW[w]; m = fmaxf(m, mW[w]); }
            atomicAdd(&g_esum, E);
            atomicMax(&g_maxn, fenc(m));
        }
    }
    gsyncA(1 * FGRID);

    // ---- phase VP: every block computes local prefix; block 0 sets flags; all build perm ----
    if (t < 100) cnt[t] = g_cnth[t];
    __syncthreads();
    if (t == 0) {
        int acc = 0;
        for (int l = 0; l < 100; ++l) { soff[l] = acc; acc += cnt[l]; }
        soff[100] = acc;
    }
    __syncthreads();
    if (b == 0) {
        if (t == 0) {
            int mxc = 0;
            for (int l = 0; l < 100; ++l) mxc = max(mxc, cnt[l]);
            float E = g_esum;
            g_esum = 0.f;
            float M2 = __uint_as_float(g_maxn & 0x7fffffffu);
            float Mp = (E > 0.f) ? M2 / E : 1.f;            // rigorous |sim| bound
            int zero = (mxc == B_SZ) ? 1 : 0;
            int fast = (E > 0.f) && (2.f * Mp < MARGIN * 0.9f) &&
                       (2.1f * (float)B_SZ * Mp * Mp < 1e-3f) && !zero;
            g_zero = zero;
            g_fast = fast ? 1 : 0;
            g_end_norm = E;
            g_invE = (E > 0.f) ? 1.f / E : 0.f;
            g_loss = 0.f;
            g_nfix = 0;
            g_gmaxpos = 0x007FFFFFu;
            g_gminneg = 0xFF800000u;
        }
        __syncthreads();
        if (t < 100) g_cntg[t] = cnt[t];
        if (!g_fast && !g_zero) {   // init fallback accumulators
            for (int i = t; i < B_SZ; i += 512) {
                g_sp[i] = 0.f; g_sn[i] = 0.f;
                g_minpos[i] = 0xFF800000u;
                g_maxneg[i] = 0x007FFFFFu;
            }
        }
    }
    // perm build (all blocks; position = local prefix + global per-class rank)
    for (int i = b * 512 + t; i < B_SZ; i += FGRID * 512) {
        int l = labels[i];
        unsigned r = atomicAdd(&g_offa[l], 1u);
        g_perm[soff[l] + r] = i;
    }
    gsyncA(2 * FGRID);

    const int fast = g_fast, zero = g_zero;
    if (!fast && !zero) return;   // fallback takes over; it resets g_fbarA/g_cnth/g_offa

    // ---- phase B: centroid + C accumulation via perm chunks ----
    {
        const int start = b * CHUNK;
        int n = B_SZ - start;
        if (n > CHUNK) n = CHUNK;
        if (n < 0) n = 0;
        if (t < n) { int r = g_perm[start + t]; sperm2[t] = r; slab2[t] = labels[r]; }
        __syncthreads();
        if (fast && n > 0) {
            int cl = -1;
            float ax = 0.f, cx = 0.f;
#pragma unroll 4
            for (int k = 0; k < n; ++k) {
                int row = sperm2[k];
                int l = slab2[k];
                float v = feats[(size_t)row * 512 + t];
                if (l != cl) {
                    if (cl >= 0) atomicAdd(&g_cent[cl * 512 + t], ax);
                    cl = l; ax = 0.f;
                }
                ax += v; cx += v;
            }
            if (cl >= 0) atomicAdd(&g_cent[cl * 512 + t], ax);
            atomicAdd(&g_C[t], cx);
        }
    }
    gsyncA(3 * FGRID);

    // ---- phase C: per-row analytic loss (L2-warm feats) ----
    Cs[t] = g_C[t];
    __syncthreads();
    if (fast) {
        const float4* f4 = reinterpret_cast<const float4*>(feats);
        const float4* c4 = reinterpret_cast<const float4*>(g_cent);
        const float4* C4 = reinterpret_cast<const float4*>(Cs);
        const float invE = g_invE;
        const float E1 = 2.718281828459045f;
        const float EINV = 0.36787944117144233f;
        const int gw = b * 16 + warp;
        float wl = 0.f;
        for (int row = gw; row < B_SZ; row += FGRID * 16) {
            const int lab = labels[row];
            float dp = 0.f, da = 0.f;
#pragma unroll
            for (int it = 0; it < 4; ++it) {
                float4 a = f4[(size_t)row * 128 + it * 32 + lane];
                float4 bb = c4[(size_t)lab * 128 + it * 32 + lane];
                float4 cc = C4[it * 32 + lane];
                dp = fmaf(a.x, bb.x, fmaf(a.y, bb.y, fmaf(a.z, bb.z, fmaf(a.w, bb.w, dp))));
                da = fmaf(a.x, cc.x, fmaf(a.y, cc.y, fmaf(a.z, cc.z, fmaf(a.w, cc.w, da))));
            }
#pragma unroll
            for (int o = 16; o > 0; o >>= 1) {
                dp += __shfl_xor_sync(0xffffffffu, dp, o);
                da += __shfl_xor_sync(0xffffffffu, da, o);
            }
            if (lane == 0) {
                float n = (float)g_cntg[lab];
                float sp = n - 2.f * dp * invE;
                float sn = ((float)B_SZ - n) + 2.f * (da - dp) * invE;
                wl += 0.5f * log1pf(E1 * sp) + 0.5f * log1pf(EINV * sn);
            }
        }
        if (lane == 0) eW[warp] = wl;
        __syncthreads();
        if (t == 0) {
            float s = 0.f;
#pragma unroll
            for (int w = 0; w < 16; ++w) s += eW[w];
            atomicAdd(&g_loss, s);
        }
    }
    // (zero case: g_loss stays 0)

    // ---- final barrier: others arrive+exit, block 0 waits and writes ----
    __syncthreads();
    __threadfence();
    if (t == 0) {
        atomicAdd(&g_fbarA, 1u);
        if (b == 0) {
            while (*(volatile unsigned*)&g_fbarA < 4u * FGRID) { }
            __threadfence();
            out[0] = (*(volatile float*)&g_loss) * (1.0f / B_SZ);
        }
    }
}

// ================= fallback: conv + GEMM + check + fixup + final in ONE kernel =================
__device__ __forceinline__ void mma16816(float* d, const uint32_t* a, const uint32_t* b) {
    asm volatile(
        "mma.sync.aligned.m16n8k16.row.col.f32.bf16.bf16.f32 "
        "{%0,%1,%2,%3}, {%4,%5,%6,%7}, {%8,%9}, {%0,%1,%2,%3};\n"
        : "+f"(d[0]), "+f"(d[1]), "+f"(d[2]), "+f"(d[3])
        : "r"(a[0]), "r"(a[1]), "r"(a[2]), "r"(a[3]), "r"(b[0]), "r"(b[1]));
}
__device__ __forceinline__ void ldsm4(uint32_t* d, uint32_t saddr) {
    asm volatile("ldmatrix.sync.aligned.m8n8.x4.shared.b16 {%0,%1,%2,%3}, [%4];"
                 : "=r"(d[0]), "=r"(d[1]), "=r"(d[2]), "=r"(d[3]) : "r"(saddr));
}
__device__ __forceinline__ void cpa16(uint32_t saddr, const void* g) {
    asm volatile("cp.async.cg.shared.global [%0], [%1], 16;\n" :: "r"(saddr), "l"(g));
}
__device__ __forceinline__ void load_chunk(uint32_t sb, int stage, int kbase,
                                           int i0, int j0, int tid) {
    const int r = tid >> 2, q = tid & 3;
#pragma unroll
    for (int h = 0; h < 2; ++h) {
        int rr = r + h * 64;
        cpa16(sb + (SM_A(stage) + rr * PADW + q * 4) * 4,
              g_fbf + (size_t)(i0 + rr) * D_SZ + kbase + q * 8);
        cpa16(sb + (SM_B(stage) + rr * PADW + q * 4) * 4,
              g_fbf + (size_t)(j0 + rr) * D_SZ + kbase + q * 8);
    }
    asm volatile("cp.async.commit_group;\n" ::: "memory");
}
__device__ __forceinline__ void gsyncB(unsigned target) {
    __syncthreads();
    if (threadIdx.x == 0) {
        __threadfence();
        atomicAdd(&g_fbarB, 1u);
        while (*(volatile unsigned*)&g_fbarB < target) { }
    }
    __syncthreads();
    __threadfence();
}
#define PROC(SRAW, LI, LJ, SP, SN, MN, MX, NT, H)                              \
    {                                                                          \
        float s_ = (SRAW) * inv;                                               \
        float s2_ = s_ * s_;                                                   \
        float even_ = fmaf(s2_, 2.f, 1.f);                                     \
        float odd_ = s_ * fmaf(s2_, 1.33333333f, 2.f);                         \
        if ((LI) == (LJ)) {                                                    \
            if (s_ < ONE_EPS) {                                                \
                float evp_ = even_ - odd_;                                     \
                SP += evp_; MN = fminf(MN, s_); gmx = fmaxf(gmx, s_);          \
                csp[NT][H] += evp_; cmnP[NT][H] = fminf(cmnP[NT][H], s_);      \
            }                                                                  \
        } else {                                                               \
            float evn_ = even_ + odd_;                                         \
            SN += evn_; MX = fmaxf(MX, s_); gmn = fminf(gmn, s_);              \
            csn[NT][H] += evn_; cmxN[NT][H] = fmaxf(cmxN[NT][H], s_);          \
        }                                                                      \
    }

__global__ void __launch_bounds__(256, 2) k_fallback(const float* __restrict__ feats,
                                                     const int* __restrict__ labels,
                                                     float* __restrict__ out) {
    // prologue: reset next-replay state for k_fast (k_fast fully done — stream order)
    if (blockIdx.x == 0) {
        if (threadIdx.x == 0) g_fbarA = 0;
        if (threadIdx.x < 100) { g_cnth[threadIdx.x] = 0; g_offa[threadIdx.x] = 0u; }
    }
    if (g_fast | g_zero) return;
    extern __shared__ uint32_t dsm[];
    const uint32_t sb = (uint32_t)__cvta_generic_to_shared(dsm);
    __shared__ int slabi[BM];
    __shared__ int slabj[BN];
    __shared__ float sredA[8], sredB[8];

    const int tid = threadIdx.x, lane = tid & 31, warp = tid >> 5;

    // ---- phase A: fp32 -> bf16 convert ----
    {
        const int n4 = B_SZ * D_SZ / 4;
        const float4* f4 = reinterpret_cast<const float4*>(feats);
        for (int i = blockIdx.x * 256 + tid; i < n4; i += FB_GRID * 256) {
            float4 v = f4[i];
            __nv_bfloat162 lo = __floats2bfloat162_rn(v.x, v.y);
            __nv_bfloat162 hi = __floats2bfloat162_rn(v.z, v.w);
            uint2 o;
            o.x = *reinterpret_cast<unsigned*>(&lo);
            o.y = *reinterpret_cast<unsigned*>(&hi);
            reinterpret_cast<uint2*>(g_fbf)[i] = o;
        }
    }
    gsyncB(1 * FB_GRID);

    // ---- phase B: triangular HMMA GEMM + epilogue stats ----
    const int wm = warp >> 2, wn = warp & 3;
    const int r4 = lane >> 2, cq = lane & 3;
    const int arow = wm * 64 + (lane & 15);
    const int akw  = (lane >> 4) * 4;
    const int awoff = arow * PADW + akw;
    const int brow = wn * 32 + (lane & 7) + ((lane >= 16) ? 8 : 0);
    const int bkw  = ((lane >> 3) & 1) * 4;
    const int bwoff = brow * PADW + bkw;

    for (int kb = blockIdx.x; kb < NTRI; kb += FB_GRID) {
        __syncthreads();
        int bi = (int)(64.5f - sqrtf(64.5f * 64.5f - 2.0f * (float)kb));
        if (bi < 0) bi = 0;
        if (bi > 63) bi = 63;
        while (bi > 0 && bi * NBLK - bi * (bi - 1) / 2 > kb) --bi;
        while ((bi + 1) * NBLK - (bi + 1) * bi / 2 <= kb) ++bi;
        const int bj = bi + (kb - (bi * NBLK - bi * (bi - 1) / 2));
        const int i0 = bi * BM, j0 = bj * BN;
        const bool offdiag = (bi != bj);

        if (tid < BM) slabi[tid] = labels[i0 + tid];
        else if (tid < BM + BN) slabj[tid - BM] = labels[j0 + tid - BM];

        float acc[4][4][4];
#pragma unroll
        for (int mt = 0; mt < 4; ++mt)
#pragma unroll
            for (int nt = 0; nt < 4; ++nt)
#pragma unroll
                for (int e = 0; e < 4; ++e) acc[mt][nt][e] = 0.f;

        const int NK = D_SZ / BK;
        load_chunk(sb, 0, 0, i0, j0, tid);
        load_chunk(sb, 1, BK, i0, j0, tid);

        for (int kt = 0; kt < NK; ++kt) {
            const int s = kt % 3;
            if (kt + 1 < NK) asm volatile("cp.async.wait_group 1;\n" ::: "memory");
            else             asm volatile("cp.async.wait_group 0;\n" ::: "memory");
            __syncthreads();
            if (kt + 2 < NK) load_chunk(sb, (kt + 2) % 3, (kt + 2) * BK, i0, j0, tid);
#pragma unroll
            for (int ks = 0; ks < 2; ++ks) {
                const int ko = ks * 8;
                uint32_t a[4][4], b[2][4];
#pragma unroll
                for (int mt = 0; mt < 4; ++mt)
                    ldsm4(a[mt], sb + (SM_A(s) + awoff + mt * 16 * PADW + ko) * 4);
#pragma unroll
                for (int p = 0; p < 2; ++p)
                    ldsm4(b[p], sb + (SM_B(s) + bwoff + p * 16 * PADW + ko) * 4);
#pragma unroll
                for (int mt = 0; mt < 4; ++mt)
#pragma unroll
                    for (int nt = 0; nt < 4; ++nt) {
                        uint32_t bb[2] = {b[nt >> 1][(nt & 1) * 2], b[nt >> 1][(nt & 1) * 2 + 1]};
                        mma16816(acc[mt][nt], a[mt], bb);
                    }
            }
        }

        const float inv = 1.0f / g_end_norm;
        const float ONE_EPS = 1.0f - 1e-5f;
        const float INF = __int_as_float(0x7f800000);
        float csp[4][2], csn[4][2], cmnP[4][2], cmxN[4][2];
#pragma unroll
        for (int nt = 0; nt < 4; ++nt)
#pragma unroll
            for (int h = 0; h < 2; ++h) {
                csp[nt][h] = 0.f; csn[nt][h] = 0.f;
                cmnP[nt][h] = INF; cmxN[nt][h] = -INF;
            }
        float gmx = -INF, gmn = INF;

#pragma unroll
        for (int mt = 0; mt < 4; ++mt) {
            const int lr0 = mt * 16 + r4, lr1 = lr0 + 8;
            const int li0 = slabi[wm * 64 + lr0], li1 = slabi[wm * 64 + lr1];
            const int gi0 = i0 + wm * 64 + lr0, gi1 = i0 + wm * 64 + lr1;
            float sp0 = 0.f, sn0 = 0.f, mn0 = INF, mx0 = -INF;
            float sp1 = 0.f, sn1 = 0.f, mn1 = INF, mx1 = -INF;
#pragma unroll
            for (int nt = 0; nt < 4; ++nt) {
                const int lc = nt * 8 + 2 * cq;
                const int lj0 = slabj[wn * 32 + lc], lj1 = slabj[wn * 32 + lc + 1];
                PROC(acc[mt][nt][0], li0, lj0, sp0, sn0, mn0, mx0, nt, 0);
                PROC(acc[mt][nt][1], li0, lj1, sp0, sn0, mn0, mx0, nt, 1);
                PROC(acc[mt][nt][2], li1, lj0, sp1, sn1, mn1, mx1, nt, 0);
                PROC(acc[mt][nt][3], li1, lj1, sp1, sn1, mn1, mx1, nt, 1);
            }
#pragma unroll
            for (int o = 1; o < 4; o <<= 1) {
                sp0 += __shfl_xor_sync(0xffffffffu, sp0, o);
                sn0 += __shfl_xor_sync(0xffffffffu, sn0, o);
                mn0 = fminf(mn0, __shfl_xor_sync(0xffffffffu, mn0, o));
                mx0 = fmaxf(mx0, __shfl_xor_sync(0xffffffffu, mx0, o));
                sp1 += __shfl_xor_sync(0xffffffffu, sp1, o);
                sn1 += __shfl_xor_sync(0xffffffffu, sn1, o);
                mn1 = fminf(mn1, __shfl_xor_sync(0xffffffffu, mn1, o));
                mx1 = fmaxf(mx1, __shfl_xor_sync(0xffffffffu, mx1, o));
            }
            if (cq == 0) {
                atomicAdd(&g_sp[gi0], sp0);
                atomicAdd(&g_sn[gi0], sn0);
                atomicMin(&g_minpos[gi0], fenc(mn0));
                atomicMax(&g_maxneg[gi0], fenc(mx0));
                atomicAdd(&g_sp[gi1], sp1);
                atomicAdd(&g_sn[gi1], sn1);
                atomicMin(&g_minpos[gi1], fenc(mn1));
                atomicMax(&g_maxneg[gi1], fenc(mx1));
            }
        }
        if (offdiag) {
#pragma unroll
            for (int nt = 0; nt < 4; ++nt)
#pragma unroll
                for (int h = 0; h < 2; ++h) {
#pragma unroll
                    for (int o = 4; o < 32; o <<= 1) {
                        csp[nt][h] += __shfl_xor_sync(0xffffffffu, csp[nt][h], o);
                        csn[nt][h] += __shfl_xor_sync(0xffffffffu, csn[nt][h], o);
                        cmnP[nt][h] = fminf(cmnP[nt][h], __shfl_xor_sync(0xffffffffu, cmnP[nt][h], o));
                        cmxN[nt][h] = fmaxf(cmxN[nt][h], __shfl_xor_sync(0xffffffffu, cmxN[nt][h], o));
                    }
                }
            if (r4 == 0) {
#pragma unroll
                for (int nt = 0; nt < 4; ++nt) {
                    const int gj = j0 + wn * 32 + nt * 8 + 2 * cq;
                    atomicAdd(&g_sp[gj], csp[nt][0]);
                    atomicAdd(&g_sn[gj], csn[nt][0]);
                    atomicMin(&g_minpos[gj], fenc(cmnP[nt][0]));
                    atomicMax(&g_maxneg[gj], fenc(cmxN[nt][0]));
                    atomicAdd(&g_sp[gj + 1], csp[nt][1]);
                    atomicAdd(&g_sn[gj + 1], csn[nt][1]);
                    atomicMin(&g_minpos[gj + 1], fenc(cmnP[nt][1]));
                    atomicMax(&g_maxneg[gj + 1], fenc(cmxN[nt][1]));
                }
            }
        }
#pragma unroll
        for (int o = 16; o > 0; o >>= 1) {
            gmx = fmaxf(gmx, __shfl_xor_sync(0xffffffffu, gmx, o));
            gmn = fminf(gmn, __shfl_xor_sync(0xffffffffu, gmn, o));
        }
        if (lane == 0) { sredA[warp] = gmx; sredB[warp] = gmn; }
        __syncthreads();
        if (tid == 0) {
            float a = sredA[0], b = sredB[0];
#pragma unroll
            for (int w = 1; w < 8; ++w) { a = fmaxf(a, sredA[w]); b = fminf(b, sredB[w]); }
            atomicMax(&g_gmaxpos, fenc(a));
            atomicMin(&g_gminneg, fenc(b));
        }
    }
    gsyncB(2 * FB_GRID);

    // ---- phase C: per-row check ----
    {
        const float gmaxP = fdec(g_gmaxpos);
        const float gminN = fdec(g_gminneg);
        for (int r = blockIdx.x * 256 + tid; r < B_SZ; r += FB_GRID * 256) {
            const float minpos = fdec(g_minpos[r]);
            const float maxneg = fdec(g_maxneg[r]);
            const bool okP = (gmaxP - MARGIN < maxneg);
            const bool okN = (gminN + MARGIN > minpos);
            if (okP && okN) {
                float loss = 0.f;
                float sp = g_sp[r], sn = g_sn[r];
                if (sp > 0.f && sn > 0.f) {
                    const float E1 = 2.718281828459045f;
                    const float EINV = 0.36787944117144233f;
                    loss = 0.5f * log1pf(E1 * sp) + 0.5f * log1pf(EINV * sn);
                }
                g_rowloss[r] = loss;
            } else {
                g_rowloss[r] = 0.f;
                int idx = atomicAdd(&g_nfix, 1);
                g_fixlist[idx] = r;
            }
        }
    }
    gsyncB(3 * FB_GRID);

    // ---- phase D: exact fixup for flagged rows ----
    {
        float* fr = reinterpret_cast<float*>(dsm);
        float* redp = fr + D_SZ;
        float* redn = redp + 256;
        const int n = g_nfix;
        for (int w = blockIdx.x; w < n; w += FB_GRID) {
            const int r = g_fixlist[w];
            for (int k = tid; k < D_SZ; k += 256)
                fr[k] = __bfloat162float(g_fbf[(size_t)r * D_SZ + k]);
            __syncthreads();
            const float inv = 1.0f / g_end_norm;
            const float minpos = fdec(g_minpos[r]);
            const float maxneg = fdec(g_maxneg[r]);
            const int lr = labels[r];
            const float ONE_EPS = 1.0f - 1e-5f;
            float sp = 0.f, sn = 0.f;
            for (int j = tid; j < B_SZ; j += 256) {
                const __nv_bfloat162* fj =
                    reinterpret_cast<const __nv_bfloat162*>(g_fbf + (size_t)j * D_SZ);
                float d = 0.f;
                for (int k = 0; k < D_SZ / 2; ++k) {
                    float2 v = __bfloat1622float2(fj[k]);
                    d = fmaf(fr[2 * k], v.x, d);
                    d = fmaf(fr[2 * k + 1], v.y, d);
                }
                float s = d * inv;
                if (labels[j] == lr) {
                    if (s < ONE_EPS && (s - MARGIN < maxneg)) sp += __expf(-2.f * (s - 0.5f));
                } else if (s + MARGIN > minpos) {
                    sn += __expf(2.f * (s - 0.5f));
                }
            }
            redp[tid] = sp;
            redn[tid] = sn;
            __syncthreads();
            for (int o = 128; o > 0; o >>= 1) {
                if (tid < o) { redp[tid] += redp[tid + o]; redn[tid] += redn[tid + o]; }
                __syncthreads();
            }
            if (tid == 0) {
                float loss = 0.f;
                if (redp[0] > 0.f && redn[0] > 0.f)
                    loss = 0.5f * log1pf(redp[0]) + 0.5f * log1pf(redn[0]);
                g_rowloss[r] = loss;
            }
            __syncthreads();
        }
    }
    gsyncB(4 * FB_GRID);

    // ---- phase E: final reduction (block 0); g_fbarB reset by next k_fast ----
    if (blockIdx.x == 0) {
        float* red = reinterpret_cast<float*>(dsm);
        float s = 0.f;
        for (int i = tid; i < B_SZ; i += 256) s += g_rowloss[i];
        red[tid] = s;
        __syncthreads();
        for (int o = 128; o > 0; o >>= 1) {
            if (tid < o) red[tid] += red[tid + o];
            __syncthreads();
        }
        if (tid == 0) out[0] = red[0] * (1.0f / B_SZ);
    }
}

// ================= launch =================
extern "C" void kernel_launch(void* const* d_in, const int* in_sizes, int n_in,
                              void* d_out, int out_size) {
    const float* feats = (const float*)d_in[0];
    const int* labels = (const int*)d_in[1];
    (void)in_sizes; (void)n_in; (void)out_size;

    static int once = 0;
    if (!once) {
        cudaFuncSetAttribute(k_fallback, cudaFuncAttributeMaxDynamicSharedMemorySize, SMEM_BYTES);
        cudaFuncSetAttribute(k_fast, cudaFuncAttributePreferredSharedMemoryCarveout,
                             cudaSharedmemCarveoutMaxShared);
        cudaFuncSetAttribute(k_fallback, cudaFuncAttributePreferredSharedMemoryCarveout,
                             cudaSharedmemCarveoutMaxShared);
        once = 1;
    }

    k_fast<<<FGRID, 512>>>(feats, labels, (float*)d_out);
    k_fallback<<<FB_GRID, 256, SMEM_BYTES>>>(feats, labels, (float*)d_out);
}

// round 16
// speedup vs baseline: 14.9646x; 1.0012x over previous
#include <cuda_runtime.h>
#include <cuda_bf16.h>
#include <cstdint>
#include <cstddef>

#define B_SZ 8192
#define D_SZ 512
#define MARGIN 0.1f

#define BM 128
#define BN 128
#define BK 32
#define PADW 20
#define NBLK 64
#define NTRI 2080
#define GRID 148
#define CHUNK 56         // ceil(8192/148)

#define SM_A(s)  ((s) * 5120)
#define SM_B(s)  ((s) * 5120 + 2560)
#define SMEM_BYTES 61440

// ---------------- device scratch ----------------
static __device__ __nv_bfloat16 g_fbf[B_SZ * D_SZ];   // bf16 feats (fallback only)
static __device__ float    g_sp[B_SZ];
static __device__ float    g_sn[B_SZ];
static __device__ unsigned g_minpos[B_SZ];
static __device__ unsigned g_maxneg[B_SZ];
static __device__ unsigned g_gmaxpos;
static __device__ unsigned g_gminneg;
static __device__ float    g_end_norm;
static __device__ float    g_invE;
static __device__ float    g_rowloss[B_SZ];
static __device__ int      g_fixlist[B_SZ];
static __device__ int      g_nfix;
// fast-path state
static __device__ float    g_C[512];
static __device__ float    g_cent[100 * 512];
static __device__ int      g_perm[B_SZ];
static __device__ int      g_cntg[100];
static __device__ int      g_cnth[100];               // histogram; self-reset after VP
static __device__ unsigned g_offa[100];               // per-class rank; self-reset after VP
static __device__ unsigned g_maxn;                    // atomicMax, idempotent across replays
static __device__ float    g_esum;                    // consumed+reset in VP
static __device__ float    g_loss;                    // reset in VP
static __device__ int      g_fast;
static __device__ int      g_zero;
static __device__ unsigned g_fbar;                    // grid barrier; reset by block 0 at end

__device__ __forceinline__ unsigned fenc(float f) {
    unsigned u = __float_as_uint(f);
    return (u & 0x80000000u) ? ~u : (u | 0x80000000u);
}
__device__ __forceinline__ float fdec(unsigned u) {
    return (u & 0x80000000u) ? __uint_as_float(u ^ 0x80000000u) : __uint_as_float(~u);
}

__device__ __forceinline__ void gsync(unsigned target) {
    __syncthreads();
    if (threadIdx.x == 0) {
        __threadfence();
        atomicAdd(&g_fbar, 1u);
        while (*(volatile unsigned*)&g_fbar < target) { }
    }
    __syncthreads();
    __threadfence();
}

__device__ __forceinline__ void mma16816(float* d, const uint32_t* a, const uint32_t* b) {
    asm volatile(
        "mma.sync.aligned.m16n8k16.row.col.f32.bf16.bf16.f32 "
        "{%0,%1,%2,%3}, {%4,%5,%6,%7}, {%8,%9}, {%0,%1,%2,%3};\n"
        : "+f"(d[0]), "+f"(d[1]), "+f"(d[2]), "+f"(d[3])
        : "r"(a[0]), "r"(a[1]), "r"(a[2]), "r"(a[3]), "r"(b[0]), "r"(b[1]));
}
__device__ __forceinline__ void ldsm4(uint32_t* d, uint32_t saddr) {
    asm volatile("ldmatrix.sync.aligned.m8n8.x4.shared.b16 {%0,%1,%2,%3}, [%4];"
                 : "=r"(d[0]), "=r"(d[1]), "=r"(d[2]), "=r"(d[3]) : "r"(saddr));
}
__device__ __forceinline__ void cpa16(uint32_t saddr, const void* g) {
    asm volatile("cp.async.cg.shared.global [%0], [%1], 16;\n" :: "r"(saddr), "l"(g));
}
__device__ __forceinline__ void load_chunk(uint32_t sb, int stage, int kbase,
                                           int i0, int j0, int tid) {
    const int r = tid >> 2, q = tid & 3;
#pragma unroll
    for (int h = 0; h < 2; ++h) {
        int rr = r + h * 64;
        cpa16(sb + (SM_A(stage) + rr * PADW + q * 4) * 4,
              g_fbf + (size_t)(i0 + rr) * D_SZ + kbase + q * 8);
        cpa16(sb + (SM_B(stage) + rr * PADW + q * 4) * 4,
              g_fbf + (size_t)(j0 + rr) * D_SZ + kbase + q * 8);
    }
    asm volatile("cp.async.commit_group;\n" ::: "memory");
}
#define PROC(SRAW, LI, LJ, SP, SN, MN, MX, NT, H)                              \
    {                                                                          \
        float s_ = (SRAW) * inv;                                               \
        float s2_ = s_ * s_;                                                   \
        float even_ = fmaf(s2_, 2.f, 1.f);                                     \
        float odd_ = s_ * fmaf(s2_, 1.33333333f, 2.f);                         \
        if ((LI) == (LJ)) {                                                    \
            if (s_ < ONE_EPS) {                                                \
                float evp_ = even_ - odd_;                                     \
                SP += evp_; MN = fminf(MN, s_); gmx = fmaxf(gmx, s_);          \
                csp[NT][H] += evp_; cmnP[NT][H] = fminf(cmnP[NT][H], s_);      \
            }                                                                  \
        } else {                                                               \
            float evn_ = even_ + odd_;                                         \
            SN += evn_; MX = fmaxf(MX, s_); gmn = fminf(gmn, s_);              \
            csn[NT][H] += evn_; cmxN[NT][H] = fmaxf(cmxN[NT][H], s_);          \
        }                                                                      \
    }

// ================= k_all: entire problem, one persistent kernel =================
__global__ void __launch_bounds__(512, 1) k_all(const float* __restrict__ feats,
                                                const int* __restrict__ labels,
                                                float* __restrict__ out) {
    extern __shared__ uint32_t dsm[];
    const uint32_t sb = (uint32_t)__cvta_generic_to_shared(dsm);
    const int b = blockIdx.x, t = threadIdx.x;
    const int warp = t >> 5, lane = t & 31;
    __shared__ float eW[16], mW[16];
    __shared__ float Cs[512];
    __shared__ int sperm2[CHUNK], slab2[CHUNK];
    __shared__ int cnt[100], soff[101];
    __shared__ int slabi[BM], slabj[BN];
    __shared__ float sredA[8], sredB[8];

    // ---- phase A: zero cent/C, norms + histogram ----
    if (b == 2) g_C[t] = 0.f;
    for (int i = b * 512 + t; i < 100 * 512; i += GRID * 512) g_cent[i] = 0.f;
    {
        const float4* f4 = reinterpret_cast<const float4*>(feats);
        const int gw = b * 16 + warp;     // 0..2367
        float esum = 0.f, mmax = 0.f;
        for (int row = gw; row < B_SZ; row += GRID * 16) {
            float rsq = 0.f;
#pragma unroll
            for (int it = 0; it < 4; ++it) {
                float4 v = f4[(size_t)row * 128 + it * 32 + lane];
                rsq += v.x * v.x + v.y * v.y + v.z * v.z + v.w * v.w;
            }
#pragma unroll
            for (int o = 16; o > 0; o >>= 1) rsq += __shfl_xor_sync(0xffffffffu, rsq, o);
            if (lane == 0) { esum += rsq; atomicAdd(&g_cnth[labels[row]], 1); }
            mmax = fmaxf(mmax, rsq);
        }
        if (lane == 0) { eW[warp] = esum; mW[warp] = mmax; }
        __syncthreads();
        if (t == 0) {
            float E = 0.f, m = 0.f;
#pragma unroll
            for (int w = 0; w < 16; ++w) { E += eW[w]; m = fmaxf(m, mW[w]); }
            atomicAdd(&g_esum, E);
            atomicMax(&g_maxn, fenc(m));
        }
    }
    gsync(1u * GRID);

    // ---- phase VP: local prefix everywhere; block 0 sets flags; all build perm ----
    if (t < 100) cnt[t] = g_cnth[t];
    __syncthreads();
    if (t == 0) {
        int acc = 0;
        for (int l = 0; l < 100; ++l) { soff[l] = acc; acc += cnt[l]; }
        soff[100] = acc;
    }
    __syncthreads();
    if (b == 0) {
        if (t == 0) {
            int mxc = 0;
            for (int l = 0; l < 100; ++l) mxc = max(mxc, cnt[l]);
            float E = g_esum;
            g_esum = 0.f;
            float M2 = __uint_as_float(g_maxn & 0x7fffffffu);
            float Mp = (E > 0.f) ? M2 / E : 1.f;            // rigorous |sim| bound
            int zero = (mxc == B_SZ) ? 1 : 0;
            int fast = (E > 0.f) && (2.f * Mp < MARGIN * 0.9f) &&
                       (2.1f * (float)B_SZ * Mp * Mp < 1e-3f) && !zero;
            g_zero = zero;
            g_fast = fast ? 1 : 0;
            g_end_norm = E;
            g_invE = (E > 0.f) ? 1.f / E : 0.f;
            g_loss = 0.f;
            g_nfix = 0;
            g_gmaxpos = 0x007FFFFFu;
            g_gminneg = 0xFF800000u;
        }
        __syncthreads();
        if (t < 100) g_cntg[t] = cnt[t];
        if (!g_fast && !g_zero) {   // init fallback accumulators
            for (int i = t; i < B_SZ; i += 512) {
                g_sp[i] = 0.f; g_sn[i] = 0.f;
                g_minpos[i] = 0xFF800000u;
                g_maxneg[i] = 0x007FFFFFu;
            }
        }
    }
    for (int i = b * 512 + t; i < B_SZ; i += GRID * 512) {
        int l = labels[i];
        unsigned r = atomicAdd(&g_offa[l], 1u);
        g_perm[soff[l] + r] = i;
    }
    gsync(2u * GRID);
    // self-reset consumed state for next replay (everyone is past reading them)
    if (b == 0 && t < 100) { g_cnth[t] = 0; g_offa[t] = 0u; }

    const int fast = g_fast, zero = g_zero;

    if (fast | zero) {
        // ================= FAST PATH =================
        // ---- phase B: centroid + C accumulation via perm chunks ----
        {
            const int start = b * CHUNK;
            int n = B_SZ - start;
            if (n > CHUNK) n = CHUNK;
            if (n < 0) n = 0;
            if (t < n) { int r = g_perm[start + t]; sperm2[t] = r; slab2[t] = labels[r]; }
            __syncthreads();
            if (fast && n > 0) {
                int cl = -1;
                float ax = 0.f, cx = 0.f;
#pragma unroll 4
                for (int k = 0; k < n; ++k) {
                    int row = sperm2[k];
                    int l = slab2[k];
                    float v = feats[(size_t)row * 512 + t];
                    if (l != cl) {
                        if (cl >= 0) atomicAdd(&g_cent[cl * 512 + t], ax);
                        cl = l; ax = 0.f;
                    }
                    ax += v; cx += v;
                }
                if (cl >= 0) atomicAdd(&g_cent[cl * 512 + t], ax);
                atomicAdd(&g_C[t], cx);
            }
        }
        gsync(3u * GRID);

        // ---- phase C: per-row analytic loss (L2-warm feats) ----
        Cs[t] = g_C[t];
        __syncthreads();
        if (fast) {
            const float4* f4 = reinterpret_cast<const float4*>(feats);
            const float4* c4 = reinterpret_cast<const float4*>(g_cent);
            const float4* C4 = reinterpret_cast<const float4*>(Cs);
            const float invE = g_invE;
            const float E1 = 2.718281828459045f;
            const float EINV = 0.36787944117144233f;
            const int gw = b * 16 + warp;
            float wl = 0.f;
            for (int row = gw; row < B_SZ; row += GRID * 16) {
                const int lab = labels[row];
                float dp = 0.f, da = 0.f;
#pragma unroll
                for (int it = 0; it < 4; ++it) {
                    float4 a = f4[(size_t)row * 128 + it * 32 + lane];
                    float4 bb = c4[(size_t)lab * 128 + it * 32 + lane];
                    float4 cc = C4[it * 32 + lane];
                    dp = fmaf(a.x, bb.x, fmaf(a.y, bb.y, fmaf(a.z, bb.z, fmaf(a.w, bb.w, dp))));
                    da = fmaf(a.x, cc.x, fmaf(a.y, cc.y, fmaf(a.z, cc.z, fmaf(a.w, cc.w, da))));
                }
#pragma unroll
                for (int o = 16; o > 0; o >>= 1) {
                    dp += __shfl_xor_sync(0xffffffffu, dp, o);
                    da += __shfl_xor_sync(0xffffffffu, da, o);
                }
                if (lane == 0) {
                    float n = (float)g_cntg[lab];
                    float sp = n - 2.f * dp * invE;
                    float sn = ((float)B_SZ - n) + 2.f * (da - dp) * invE;
                    wl += 0.5f * log1pf(E1 * sp) + 0.5f * log1pf(EINV * sn);
                }
            }
            if (lane == 0) eW[warp] = wl;
            __syncthreads();
            if (t == 0) {
                float s = 0.f;
#pragma unroll
                for (int w = 0; w < 16; ++w) s += eW[w];
                atomicAdd(&g_loss, s);
            }
        }
        // final barrier: others arrive+exit; block 0 waits, writes, resets
        __syncthreads();
        __threadfence();
        if (t == 0) {
            atomicAdd(&g_fbar, 1u);
            if (b == 0) {
                while (*(volatile unsigned*)&g_fbar < 4u * GRID) { }
                __threadfence();
                out[0] = (*(volatile float*)&g_loss) * (1.0f / B_SZ);
                g_fbar = 0u;
            }
        }
        return;
    }

    // ================= FALLBACK PATH (same resident blocks) =================
    // ---- phase F-A: fp32 -> bf16 convert ----
    {
        const int n4 = B_SZ * D_SZ / 4;
        const float4* f4 = reinterpret_cast<const float4*>(feats);
        for (int i = b * 512 + t; i < n4; i += GRID * 512) {
            float4 v = f4[i];
            __nv_bfloat162 lo = __floats2bfloat162_rn(v.x, v.y);
            __nv_bfloat162 hi = __floats2bfloat162_rn(v.z, v.w);
            uint2 o;
            o.x = *reinterpret_cast<unsigned*>(&lo);
            o.y = *reinterpret_cast<unsigned*>(&hi);
            reinterpret_cast<uint2*>(g_fbf)[i] = o;
        }
    }
    gsync(3u * GRID);

    // ---- phase F-B: triangular HMMA GEMM + epilogue stats (warps 0-7 compute) ----
    {
        const int wm = warp >> 2, wn = warp & 3;
        const int r4 = lane >> 2, cq = lane & 3;
        const int arow = wm * 64 + (lane & 15);
        const int akw  = (lane >> 4) * 4;
        const int awoff = arow * PADW + akw;
        const int brow = wn * 32 + (lane & 7) + ((lane >= 16) ? 8 : 0);
        const int bkw  = ((lane >> 3) & 1) * 4;
        const int bwoff = brow * PADW + bkw;
        const bool act = (t < 256);

        for (int kb = b; kb < NTRI; kb += GRID) {
            __syncthreads();
            int bi = (int)(64.5f - sqrtf(64.5f * 64.5f - 2.0f * (float)kb));
            if (bi < 0) bi = 0;
            if (bi > 63) bi = 63;
            while (bi > 0 && bi * NBLK - bi * (bi - 1) / 2 > kb) --bi;
            while ((bi + 1) * NBLK - (bi + 1) * bi / 2 <= kb) ++bi;
            const int bj = bi + (kb - (bi * NBLK - bi * (bi - 1) / 2));
            const int i0 = bi * BM, j0 = bj * BN;
            const bool offdiag = (bi != bj);

            if (t < BM) slabi[t] = labels[i0 + t];
            else if (t < BM + BN) slabj[t - BM] = labels[j0 + t - BM];

            float acc[4][4][4];
#pragma unroll
            for (int mt = 0; mt < 4; ++mt)
#pragma unroll
                for (int nt = 0; nt < 4; ++nt)
#pragma unroll
                    for (int e = 0; e < 4; ++e) acc[mt][nt][e] = 0.f;

            const int NK = D_SZ / BK;
            if (act) { load_chunk(sb, 0, 0, i0, j0, t); load_chunk(sb, 1, BK, i0, j0, t); }

            for (int kt = 0; kt < NK; ++kt) {
                const int s = kt % 3;
                if (act) {
                    if (kt + 1 < NK) asm volatile("cp.async.wait_group 1;\n" ::: "memory");
                    else             asm volatile("cp.async.wait_group 0;\n" ::: "memory");
                }
                __syncthreads();
                if (act && kt + 2 < NK) load_chunk(sb, (kt + 2) % 3, (kt + 2) * BK, i0, j0, t);
                if (act) {
#pragma unroll
                    for (int ks = 0; ks < 2; ++ks) {
                        const int ko = ks * 8;
                        uint32_t a[4][4], bb[2][4];
#pragma unroll
                        for (int mt = 0; mt < 4; ++mt)
                            ldsm4(a[mt], sb + (SM_A(s) + awoff + mt * 16 * PADW + ko) * 4);
#pragma unroll
                        for (int p = 0; p < 2; ++p)
                            ldsm4(bb[p], sb + (SM_B(s) + bwoff + p * 16 * PADW + ko) * 4);
#pragma unroll
                        for (int mt = 0; mt < 4; ++mt)
#pragma unroll
                            for (int nt = 0; nt < 4; ++nt) {
                                uint32_t b2[2] = {bb[nt >> 1][(nt & 1) * 2],
                                                  bb[nt >> 1][(nt & 1) * 2 + 1]};
                                mma16816(acc[mt][nt], a[mt], b2);
                            }
                    }
                }
            }

            const float inv = 1.0f / g_end_norm;
            const float ONE_EPS = 1.0f - 1e-5f;
            const float INF = __int_as_float(0x7f800000);
            if (act) {
                float csp[4][2], csn[4][2], cmnP[4][2], cmxN[4][2];
#pragma unroll
                for (int nt = 0; nt < 4; ++nt)
#pragma unroll
                    for (int h = 0; h < 2; ++h) {
                        csp[nt][h] = 0.f; csn[nt][h] = 0.f;
                        cmnP[nt][h] = INF; cmxN[nt][h] = -INF;
                    }
                float gmx = -INF, gmn = INF;

#pragma unroll
                for (int mt = 0; mt < 4; ++mt) {
                    const int lr0 = mt * 16 + r4, lr1 = lr0 + 8;
                    const int li0 = slabi[wm * 64 + lr0], li1 = slabi[wm * 64 + lr1];
                    const int gi0 = i0 + wm * 64 + lr0, gi1 = i0 + wm * 64 + lr1;
                    float sp0 = 0.f, sn0 = 0.f, mn0 = INF, mx0 = -INF;
                    float sp1 = 0.f, sn1 = 0.f, mn1 = INF, mx1 = -INF;
#pragma unroll
                    for (int nt = 0; nt < 4; ++nt) {
                        const int lc = nt * 8 + 2 * cq;
                        const int lj0 = slabj[wn * 32 + lc], lj1 = slabj[wn * 32 + lc + 1];
                        PROC(acc[mt][nt][0], li0, lj0, sp0, sn0, mn0, mx0, nt, 0);
                        PROC(acc[mt][nt][1], li0, lj1, sp0, sn0, mn0, mx0, nt, 1);
                        PROC(acc[mt][nt][2], li1, lj0, sp1, sn1, mn1, mx1, nt, 0);
                        PROC(acc[mt][nt][3], li1, lj1, sp1, sn1, mn1, mx1, nt, 1);
                    }
#pragma unroll
                    for (int o = 1; o < 4; o <<= 1) {
                        sp0 += __shfl_xor_sync(0xffffffffu, sp0, o);
                        sn0 += __shfl_xor_sync(0xffffffffu, sn0, o);
                        mn0 = fminf(mn0, __shfl_xor_sync(0xffffffffu, mn0, o));
                        mx0 = fmaxf(mx0, __shfl_xor_sync(0xffffffffu, mx0, o));
                        sp1 += __shfl_xor_sync(0xffffffffu, sp1, o);
                        sn1 += __shfl_xor_sync(0xffffffffu, sn1, o);
                        mn1 = fminf(mn1, __shfl_xor_sync(0xffffffffu, mn1, o));
                        mx1 = fmaxf(mx1, __shfl_xor_sync(0xffffffffu, mx1, o));
                    }
                    if (cq == 0) {
                        atomicAdd(&g_sp[gi0], sp0);
                        atomicAdd(&g_sn[gi0], sn0);
                        atomicMin(&g_minpos[gi0], fenc(mn0));
                        atomicMax(&g_maxneg[gi0], fenc(mx0));
                        atomicAdd(&g_sp[gi1], sp1);
                        atomicAdd(&g_sn[gi1], sn1);
                        atomicMin(&g_minpos[gi1], fenc(mn1));
                        atomicMax(&g_maxneg[gi1], fenc(mx1));
                    }
                }
                if (offdiag) {
#pragma unroll
                    for (int nt = 0; nt < 4; ++nt)
#pragma unroll
                        for (int h = 0; h < 2; ++h) {
#pragma unroll
                            for (int o = 4; o < 32; o <<= 1) {
                                csp[nt][h] += __shfl_xor_sync(0xffffffffu, csp[nt][h], o);
                                csn[nt][h] += __shfl_xor_sync(0xffffffffu, csn[nt][h], o);
                                cmnP[nt][h] = fminf(cmnP[nt][h],
                                                    __shfl_xor_sync(0xffffffffu, cmnP[nt][h], o));
                                cmxN[nt][h] = fmaxf(cmxN[nt][h],
                                                    __shfl_xor_sync(0xffffffffu, cmxN[nt][h], o));
                            }
                        }
                    if (r4 == 0) {
#pragma unroll
                        for (int nt = 0; nt < 4; ++nt) {
                            const int gj = j0 + wn * 32 + nt * 8 + 2 * cq;
                            atomicAdd(&g_sp[gj], csp[nt][0]);
                            atomicAdd(&g_sn[gj], csn[nt][0]);
                            atomicMin(&g_minpos[gj], fenc(cmnP[nt][0]));
                            atomicMax(&g_maxneg[gj], fenc(cmxN[nt][0]));
                            atomicAdd(&g_sp[gj + 1], csp[nt][1]);
                            atomicAdd(&g_sn[gj + 1], csn[nt][1]);
                            atomicMin(&g_minpos[gj + 1], fenc(cmnP[nt][1]));
                            atomicMax(&g_maxneg[gj + 1], fenc(cmxN[nt][1]));
                        }
                    }
                }
#pragma unroll
                for (int o = 16; o > 0; o >>= 1) {
                    gmx = fmaxf(gmx, __shfl_xor_sync(0xffffffffu, gmx, o));
                    gmn = fminf(gmn, __shfl_xor_sync(0xffffffffu, gmn, o));
                }
                if (lane == 0) { sredA[warp] = gmx; sredB[warp] = gmn; }
            }
            __syncthreads();
            if (t == 0) {
                float a = sredA[0], bb = sredB[0];
#pragma unroll
                for (int w = 1; w < 8; ++w) { a = fmaxf(a, sredA[w]); bb = fminf(bb, sredB[w]); }
                atomicMax(&g_gmaxpos, fenc(a));
                atomicMin(&g_gminneg, fenc(bb));
            }
        }
    }
    gsync(4u * GRID);

    // ---- phase F-C: per-row check ----
    {
        const float gmaxP = fdec(g_gmaxpos);
        const float gminN = fdec(g_gminneg);
        for (int r = b * 512 + t; r < B_SZ; r += GRID * 512) {
            const float minpos = fdec(g_minpos[r]);
            const float maxneg = fdec(g_maxneg[r]);
            const bool okP = (gmaxP - MARGIN < maxneg);
            const bool okN = (gminN + MARGIN > minpos);
            if (okP && okN) {
                float loss = 0.f;
                float sp = g_sp[r], sn = g_sn[r];
                if (sp > 0.f && sn > 0.f) {
                    const float E1 = 2.718281828459045f;
                    const float EINV = 0.36787944117144233f;
                    loss = 0.5f * log1pf(E1 * sp) + 0.5f * log1pf(EINV * sn);
                }
                g_rowloss[r] = loss;
            } else {
                g_rowloss[r] = 0.f;
                int idx = atomicAdd(&g_nfix, 1);
                g_fixlist[idx] = r;
            }
        }
    }
    gsync(5u * GRID);

    // ---- phase F-D: exact fixup for flagged rows ----
    {
        float* fr = reinterpret_cast<float*>(dsm);            // 512 floats
        float* redp = fr + D_SZ;                               // 512
        float* redn = redp + 512;                              // 512
        const int n = g_nfix;
        for (int w = b; w < n; w += GRID) {
            const int r = g_fixlist[w];
            if (t < D_SZ) fr[t] = __bfloat162float(g_fbf[(size_t)r * D_SZ + t]);
            __syncthreads();
            const float inv = 1.0f / g_end_norm;
            const float minpos = fdec(g_minpos[r]);
            const float maxneg = fdec(g_maxneg[r]);
            const int lr = labels[r];
            const float ONE_EPS = 1.0f - 1e-5f;
            float sp = 0.f, sn = 0.f;
            for (int j = t; j < B_SZ; j += 512) {
                const __nv_bfloat162* fj =
                    reinterpret_cast<const __nv_bfloat162*>(g_fbf + (size_t)j * D_SZ);
                float d = 0.f;
                for (int k = 0; k < D_SZ / 2; ++k) {
                    float2 v = __bfloat1622float2(fj[k]);
                    d = fmaf(fr[2 * k], v.x, d);
                    d = fmaf(fr[2 * k + 1], v.y, d);
                }
                float s = d * inv;
                if (labels[j] == lr) {
                    if (s < ONE_EPS && (s - MARGIN < maxneg)) sp += __expf(-2.f * (s - 0.5f));
                } else if (s + MARGIN > minpos) {
                    sn += __expf(2.f * (s - 0.5f));
                }
            }
            redp[t] = sp;
            redn[t] = sn;
            __syncthreads();
            for (int o = 256; o > 0; o >>= 1) {
                if (t < o) { redp[t] += redp[t + o]; redn[t] += redn[t + o]; }
                __syncthreads();
            }
            if (t == 0) {
                float loss = 0.f;
                if (redp[0] > 0.f && redn[0] > 0.f)
                    loss = 0.5f * log1pf(redp[0]) + 0.5f * log1pf(redn[0]);
                g_rowloss[r] = loss;
            }
            __syncthreads();
        }
    }
    gsync(6u * GRID);

    // ---- phase F-E: final reduction (block 0), then reset barrier ----
    if (b == 0) {
        float* red = reinterpret_cast<float*>(dsm);
        float s = 0.f;
        for (int i = t; i < B_SZ; i += 512) s += g_rowloss[i];
        red[t] = s;
        __syncthreads();
        for (int o = 256; o > 0; o >>= 1) {
            if (t < o) red[t] += red[t + o];
            __syncthreads();
        }
        if (t == 0) out[0] = red[0] * (1.0f / B_SZ);
    }
    __syncthreads();
    __threadfence();
    if (t == 0) {
        atomicAdd(&g_fbar, 1u);
        if (b == 0) {
            while (*(volatile unsigned*)&g_fbar < 7u * GRID) { }
            g_fbar = 0u;
        }
    }
}

// ================= launch =================
extern "C" void kernel_launch(void* const* d_in, const int* in_sizes, int n_in,
                              void* d_out, int out_size) {
    const float* feats = (const float*)d_in[0];
    const int* labels = (const int*)d_in[1];
    (void)in_sizes; (void)n_in; (void)out_size;

    static int once = 0;
    if (!once) {
        cudaFuncSetAttribute(k_all, cudaFuncAttributeMaxDynamicSharedMemorySize, SMEM_BYTES);
        once = 1;
    }

    k_all<<<GRID, 512, SMEM_BYTES>>>(feats, labels, (float*)d_out);
}

// round 17
// speedup vs baseline: 16.0240x; 1.0708x over previous
#include <cuda_runtime.h>
#include <cuda_bf16.h>
#include <cstdint>
#include <cstddef>

#define B_SZ 8192
#define D_SZ 512
#define MARGIN 0.1f

#define BM 128
#define BN 128
#define BK 32
#define PADW 20
#define NBLK 64
#define NTRI 2080
#define GRID 148
#define CHUNK 56         // ceil(8192/148)

#define SM_A(s)  ((s) * 5120)
#define SM_B(s)  ((s) * 5120 + 2560)
#define SMEM_BYTES 61440

// ---------------- device scratch ----------------
static __device__ __nv_bfloat16 g_fbf[B_SZ * D_SZ];   // bf16 feats (fallback only)
static __device__ float    g_sp[B_SZ];
static __device__ float    g_sn[B_SZ];
static __device__ unsigned g_minpos[B_SZ];
static __device__ unsigned g_maxneg[B_SZ];
static __device__ unsigned g_gmaxpos;
static __device__ unsigned g_gminneg;
static __device__ float    g_rowloss[B_SZ];
static __device__ int      g_fixlist[B_SZ];
static __device__ int      g_nfix;
// fast-path state
static __device__ float    g_C[512];
static __device__ float    g_cent[100 * 512];
static __device__ int      g_perm[B_SZ];
static __device__ unsigned g_offa[100];               // per-class rank; reset after bar1
static __device__ unsigned g_maxn;                    // atomicMax, idempotent across replays
static __device__ float    g_esum;                    // reset after bar2
static __device__ float    g_loss;                    // reset at final write
static __device__ unsigned g_fbar;                    // grid barrier; reset at final write

__device__ __forceinline__ unsigned fenc(float f) {
    unsigned u = __float_as_uint(f);
    return (u & 0x80000000u) ? ~u : (u | 0x80000000u);
}
__device__ __forceinline__ float fdec(unsigned u) {
    return (u & 0x80000000u) ? __uint_as_float(u ^ 0x80000000u) : __uint_as_float(~u);
}

__device__ __forceinline__ void gsync(unsigned target) {
    __syncthreads();
    if (threadIdx.x == 0) {
        __threadfence();
        atomicAdd(&g_fbar, 1u);
        while (*(volatile unsigned*)&g_fbar < target) { }
    }
    __syncthreads();
    __threadfence();
}

__device__ __forceinline__ void mma16816(float* d, const uint32_t* a, const uint32_t* b) {
    asm volatile(
        "mma.sync.aligned.m16n8k16.row.col.f32.bf16.bf16.f32 "
        "{%0,%1,%2,%3}, {%4,%5,%6,%7}, {%8,%9}, {%0,%1,%2,%3};\n"
        : "+f"(d[0]), "+f"(d[1]), "+f"(d[2]), "+f"(d[3])
        : "r"(a[0]), "r"(a[1]), "r"(a[2]), "r"(a[3]), "r"(b[0]), "r"(b[1]));
}
__device__ __forceinline__ void ldsm4(uint32_t* d, uint32_t saddr) {
    asm volatile("ldmatrix.sync.aligned.m8n8.x4.shared.b16 {%0,%1,%2,%3}, [%4];"
                 : "=r"(d[0]), "=r"(d[1]), "=r"(d[2]), "=r"(d[3]) : "r"(saddr));
}
__device__ __forceinline__ void cpa16(uint32_t saddr, const void* g) {
    asm volatile("cp.async.cg.shared.global [%0], [%1], 16;\n" :: "r"(saddr), "l"(g));
}
__device__ __forceinline__ void load_chunk(uint32_t sb, int stage, int kbase,
                                           int i0, int j0, int tid) {
    const int r = tid >> 2, q = tid & 3;
#pragma unroll
    for (int h = 0; h < 2; ++h) {
        int rr = r + h * 64;
        cpa16(sb + (SM_A(stage) + rr * PADW + q * 4) * 4,
              g_fbf + (size_t)(i0 + rr) * D_SZ + kbase + q * 8);
        cpa16(sb + (SM_B(stage) + rr * PADW + q * 4) * 4,
              g_fbf + (size_t)(j0 + rr) * D_SZ + kbase + q * 8);
    }
    asm volatile("cp.async.commit_group;\n" ::: "memory");
}
#define PROC(SRAW, LI, LJ, SP, SN, MN, MX, NT, H)                              \
    {                                                                          \
        float s_ = (SRAW) * inv;                                               \
        float s2_ = s_ * s_;                                                   \
        float even_ = fmaf(s2_, 2.f, 1.f);                                     \
        float odd_ = s_ * fmaf(s2_, 1.33333333f, 2.f);                         \
        if ((LI) == (LJ)) {                                                    \
            if (s_ < ONE_EPS) {                                                \
                float evp_ = even_ - odd_;                                     \
                SP += evp_; MN = fminf(MN, s_); gmx = fmaxf(gmx, s_);          \
                csp[NT][H] += evp_; cmnP[NT][H] = fminf(cmnP[NT][H], s_);      \
            }                                                                  \
        } else {                                                               \
            float evn_ = even_ + odd_;                                         \
            SN += evn_; MX = fmaxf(MX, s_); gmn = fminf(gmn, s_);              \
            csn[NT][H] += evn_; cmxN[NT][H] = fmaxf(cmxN[NT][H], s_);          \
        }                                                                      \
    }

// ================= k_all: entire problem, one persistent kernel, 3-barrier fast path =================
__global__ void __launch_bounds__(512, 1) k_all(const float* __restrict__ feats,
                                                const int* __restrict__ labels,
                                                float* __restrict__ out) {
    extern __shared__ uint32_t dsm[];
    const uint32_t sb = (uint32_t)__cvta_generic_to_shared(dsm);
    const int b = blockIdx.x, t = threadIdx.x;
    const int warp = t >> 5, lane = t & 31;
    __shared__ float eW[16], mW[16];
    __shared__ float Cs[512];
    __shared__ int sperm2[CHUNK], slab2[CHUNK];
    __shared__ int cnt[100], soff[101];
    __shared__ int mxcS;
    __shared__ int slabi[BM], slabj[BN];
    __shared__ float sredA[8], sredB[8];

    // ---- phase A: zero cent/C, LOCAL histogram+prefix, norms, perm build ----
    if (b == 2) g_C[t] = 0.f;
    for (int i = b * 512 + t; i < 100 * 512; i += GRID * 512) g_cent[i] = 0.f;

    if (t < 100) cnt[t] = 0;
    __syncthreads();
    for (int i = t; i < B_SZ; i += 512) atomicAdd(&cnt[labels[i]], 1);
    __syncthreads();
    if (t == 0) {
        int acc = 0, mx = 0;
        for (int l = 0; l < 100; ++l) { soff[l] = acc; acc += cnt[l]; mx = max(mx, cnt[l]); }
        soff[100] = acc;
        mxcS = mx;
    }
    __syncthreads();

    {   // norms + E + maxn (warp per row)
        const float4* f4 = reinterpret_cast<const float4*>(feats);
        const int gw = b * 16 + warp;     // 0..2367
        float esum = 0.f, mmax = 0.f;
        for (int row = gw; row < B_SZ; row += GRID * 16) {
            float rsq = 0.f;
#pragma unroll
            for (int it = 0; it < 4; ++it) {
                float4 v = f4[(size_t)row * 128 + it * 32 + lane];
                rsq += v.x * v.x + v.y * v.y + v.z * v.z + v.w * v.w;
            }
#pragma unroll
            for (int o = 16; o > 0; o >>= 1) rsq += __shfl_xor_sync(0xffffffffu, rsq, o);
            if (lane == 0) esum += rsq;
            mmax = fmaxf(mmax, rsq);
        }
        if (lane == 0) { eW[warp] = esum; mW[warp] = mmax; }
        __syncthreads();
        if (t == 0) {
            float E = 0.f, m = 0.f;
#pragma unroll
            for (int w = 0; w < 16; ++w) { E += eW[w]; m = fmaxf(m, mW[w]); }
            atomicAdd(&g_esum, E);
            atomicMax(&g_maxn, fenc(m));
        }
    }
    // perm build (position = local prefix + global per-class rank)
    for (int i = b * 512 + t; i < B_SZ; i += GRID * 512) {
        int l = labels[i];
        unsigned r = atomicAdd(&g_offa[l], 1u);
        g_perm[soff[l] + r] = i;
    }
    gsync(1u * GRID);

    // ---- every block computes flags locally (no serial step) ----
    const float E = g_esum;
    const float M2 = __uint_as_float(g_maxn & 0x7fffffffu);
    const float Mp = (E > 0.f) ? M2 / E : 1.f;            // rigorous |sim| bound
    const int zero = (mxcS == B_SZ) ? 1 : 0;
    const int fast = ((E > 0.f) && (2.f * Mp < MARGIN * 0.9f) &&
                      (2.1f * (float)B_SZ * Mp * Mp < 1e-3f) && !zero) ? 1 : 0;
    const float invE = (E > 0.f) ? 1.f / E : 0.f;
    if (b == 0 && t < 100) g_offa[t] = 0u;   // reset for next replay (all adds done)

    if (fast | zero) {
        // ================= FAST PATH =================
        // ---- phase B: centroid + C accumulation via perm chunks ----
        {
            const int start = b * CHUNK;
            int n = B_SZ - start;
            if (n > CHUNK) n = CHUNK;
            if (n < 0) n = 0;
            if (t < n) { int r = g_perm[start + t]; sperm2[t] = r; slab2[t] = labels[r]; }
            __syncthreads();
            if (fast && n > 0) {
                int cl = -1;
                float ax = 0.f, cx = 0.f;
#pragma unroll 4
                for (int k = 0; k < n; ++k) {
                    int row = sperm2[k];
                    int l = slab2[k];
                    float v = feats[(size_t)row * 512 + t];
                    if (l != cl) {
                        if (cl >= 0) atomicAdd(&g_cent[cl * 512 + t], ax);
                        cl = l; ax = 0.f;
                    }
                    ax += v; cx += v;
                }
                if (cl >= 0) atomicAdd(&g_cent[cl * 512 + t], ax);
                atomicAdd(&g_C[t], cx);
            }
        }
        gsync(2u * GRID);
        if (b == 0 && t == 0) g_esum = 0.f;   // everyone has consumed E

        // ---- phase C: per-row analytic loss (L2-warm feats, smem counts) ----
        Cs[t] = g_C[t];
        __syncthreads();
        if (fast) {
            const float4* f4 = reinterpret_cast<const float4*>(feats);
            const float4* c4 = reinterpret_cast<const float4*>(g_cent);
            const float4* C4 = reinterpret_cast<const float4*>(Cs);
            const float E1 = 2.718281828459045f;
            const float EINV = 0.36787944117144233f;
            const int gw = b * 16 + warp;
            float wl = 0.f;
            for (int row = gw; row < B_SZ; row += GRID * 16) {
                const int lab = labels[row];
                float dp = 0.f, da = 0.f;
#pragma unroll
                for (int it = 0; it < 4; ++it) {
                    float4 a = f4[(size_t)row * 128 + it * 32 + lane];
                    float4 bb = c4[(size_t)lab * 128 + it * 32 + lane];
                    float4 cc = C4[it * 32 + lane];
                    dp = fmaf(a.x, bb.x, fmaf(a.y, bb.y, fmaf(a.z, bb.z, fmaf(a.w, bb.w, dp))));
                    da = fmaf(a.x, cc.x, fmaf(a.y, cc.y, fmaf(a.z, cc.z, fmaf(a.w, cc.w, da))));
                }
#pragma unroll
                for (int o = 16; o > 0; o >>= 1) {
                    dp += __shfl_xor_sync(0xffffffffu, dp, o);
                    da += __shfl_xor_sync(0xffffffffu, da, o);
                }
                if (lane == 0) {
                    float n = (float)cnt[lab];
                    float sp = n - 2.f * dp * invE;
                    float sn = ((float)B_SZ - n) + 2.f * (da - dp) * invE;
                    wl += 0.5f * log1pf(E1 * sp) + 0.5f * log1pf(EINV * sn);
                }
            }
            if (lane == 0) eW[warp] = wl;
            __syncthreads();
            if (t == 0) {
                float s = 0.f;
#pragma unroll
                for (int w = 0; w < 16; ++w) s += eW[w];
                atomicAdd(&g_loss, s);
            }
        }
        // final barrier: others arrive+exit; block 0 waits, writes, resets
        __syncthreads();
        __threadfence();
        if (t == 0) {
            atomicAdd(&g_fbar, 1u);
            if (b == 0) {
                while (*(volatile unsigned*)&g_fbar < 3u * GRID) { }
                __threadfence();
                out[0] = (*(volatile float*)&g_loss) * (1.0f / B_SZ);
                g_loss = 0.f;
                g_fbar = 0u;
            }
        }
        return;
    }

    // ================= FALLBACK PATH (same resident blocks) =================
    // ---- phase F-A: fp32 -> bf16 convert + accumulator init ----
    if (b == 0 && t == 0) {
        g_esum = 0.f;
        g_nfix = 0;
        g_gmaxpos = 0x007FFFFFu;
        g_gminneg = 0xFF800000u;
    }
    for (int i = b * 512 + t; i < B_SZ; i += GRID * 512) {
        g_sp[i] = 0.f; g_sn[i] = 0.f;
        g_minpos[i] = 0xFF800000u;
        g_maxneg[i] = 0x007FFFFFu;
    }
    {
        const int n4 = B_SZ * D_SZ / 4;
        const float4* f4 = reinterpret_cast<const float4*>(feats);
        for (int i = b * 512 + t; i < n4; i += GRID * 512) {
            float4 v = f4[i];
            __nv_bfloat162 lo = __floats2bfloat162_rn(v.x, v.y);
            __nv_bfloat162 hi = __floats2bfloat162_rn(v.z, v.w);
            uint2 o;
            o.x = *reinterpret_cast<unsigned*>(&lo);
            o.y = *reinterpret_cast<unsigned*>(&hi);
            reinterpret_cast<uint2*>(g_fbf)[i] = o;
        }
    }
    gsync(2u * GRID);

    // ---- phase F-B: triangular HMMA GEMM + epilogue stats (warps 0-7 compute) ----
    {
        const int wm = warp >> 2, wn = warp & 3;
        const int r4 = lane >> 2, cq = lane & 3;
        const int arow = wm * 64 + (lane & 15);
        const int akw  = (lane >> 4) * 4;
        const int awoff = arow * PADW + akw;
        const int brow = wn * 32 + (lane & 7) + ((lane >= 16) ? 8 : 0);
        const int bkw  = ((lane >> 3) & 1) * 4;
        const int bwoff = brow * PADW + bkw;
        const bool act = (t < 256);

        for (int kb = b; kb < NTRI; kb += GRID) {
            __syncthreads();
            int bi = (int)(64.5f - sqrtf(64.5f * 64.5f - 2.0f * (float)kb));
            if (bi < 0) bi = 0;
            if (bi > 63) bi = 63;
            while (bi > 0 && bi * NBLK - bi * (bi - 1) / 2 > kb) --bi;
            while ((bi + 1) * NBLK - (bi + 1) * bi / 2 <= kb) ++bi;
            const int bj = bi + (kb - (bi * NBLK - bi * (bi - 1) / 2));
            const int i0 = bi * BM, j0 = bj * BN;
            const bool offdiag = (bi != bj);

            if (t < BM) slabi[t] = labels[i0 + t];
            else if (t < BM + BN) slabj[t - BM] = labels[j0 + t - BM];

            float acc[4][4][4];
#pragma unroll
            for (int mt = 0; mt < 4; ++mt)
#pragma unroll
                for (int nt = 0; nt < 4; ++nt)
#pragma unroll
                    for (int e = 0; e < 4; ++e) acc[mt][nt][e] = 0.f;

            const int NK = D_SZ / BK;
            if (act) { load_chunk(sb, 0, 0, i0, j0, t); load_chunk(sb, 1, BK, i0, j0, t); }

            for (int kt = 0; kt < NK; ++kt) {
                const int s = kt % 3;
                if (act) {
                    if (kt + 1 < NK) asm volatile("cp.async.wait_group 1;\n" ::: "memory");
                    else             asm volatile("cp.async.wait_group 0;\n" ::: "memory");
                }
                __syncthreads();
                if (act && kt + 2 < NK) load_chunk(sb, (kt + 2) % 3, (kt + 2) * BK, i0, j0, t);
                if (act) {
#pragma unroll
                    for (int ks = 0; ks < 2; ++ks) {
                        const int ko = ks * 8;
                        uint32_t a[4][4], bb[2][4];
#pragma unroll
                        for (int mt = 0; mt < 4; ++mt)
                            ldsm4(a[mt], sb + (SM_A(s) + awoff + mt * 16 * PADW + ko) * 4);
#pragma unroll
                        for (int p = 0; p < 2; ++p)
                            ldsm4(bb[p], sb + (SM_B(s) + bwoff + p * 16 * PADW + ko) * 4);
#pragma unroll
                        for (int mt = 0; mt < 4; ++mt)
#pragma unroll
                            for (int nt = 0; nt < 4; ++nt) {
                                uint32_t b2[2] = {bb[nt >> 1][(nt & 1) * 2],
                                                  bb[nt >> 1][(nt & 1) * 2 + 1]};
                                mma16816(acc[mt][nt], a[mt], b2);
                            }
                    }
                }
            }

            const float inv = invE;
            const float ONE_EPS = 1.0f - 1e-5f;
            const float INF = __int_as_float(0x7f800000);
            if (act) {
                float csp[4][2], csn[4][2], cmnP[4][2], cmxN[4][2];
#pragma unroll
                for (int nt = 0; nt < 4; ++nt)
#pragma unroll
                    for (int h = 0; h < 2; ++h) {
                        csp[nt][h] = 0.f; csn[nt][h] = 0.f;
                        cmnP[nt][h] = INF; cmxN[nt][h] = -INF;
                    }
                float gmx = -INF, gmn = INF;

#pragma unroll
                for (int mt = 0; mt < 4; ++mt) {
                    const int lr0 = mt * 16 + r4, lr1 = lr0 + 8;
                    const int li0 = slabi[wm * 64 + lr0], li1 = slabi[wm * 64 + lr1];
                    const int gi0 = i0 + wm * 64 + lr0, gi1 = i0 + wm * 64 + lr1;
                    float sp0 = 0.f, sn0 = 0.f, mn0 = INF, mx0 = -INF;
                    float sp1 = 0.f, sn1 = 0.f, mn1 = INF, mx1 = -INF;
#pragma unroll
                    for (int nt = 0; nt < 4; ++nt) {
                        const int lc = nt * 8 + 2 * cq;
                        const int lj0 = slabj[wn * 32 + lc], lj1 = slabj[wn * 32 + lc + 1];
                        PROC(acc[mt][nt][0], li0, lj0, sp0, sn0, mn0, mx0, nt, 0);
                        PROC(acc[mt][nt][1], li0, lj1, sp0, sn0, mn0, mx0, nt, 1);
                        PROC(acc[mt][nt][2], li1, lj0, sp1, sn1, mn1, mx1, nt, 0);
                        PROC(acc[mt][nt][3], li1, lj1, sp1, sn1, mn1, mx1, nt, 1);
                    }
#pragma unroll
                    for (int o = 1; o < 4; o <<= 1) {
                        sp0 += __shfl_xor_sync(0xffffffffu, sp0, o);
                        sn0 += __shfl_xor_sync(0xffffffffu, sn0, o);
                        mn0 = fminf(mn0, __shfl_xor_sync(0xffffffffu, mn0, o));
                        mx0 = fmaxf(mx0, __shfl_xor_sync(0xffffffffu, mx0, o));
                        sp1 += __shfl_xor_sync(0xffffffffu, sp1, o);
                        sn1 += __shfl_xor_sync(0xffffffffu, sn1, o);
                        mn1 = fminf(mn1, __shfl_xor_sync(0xffffffffu, mn1, o));
                        mx1 = fmaxf(mx1, __shfl_xor_sync(0xffffffffu, mx1, o));
                    }
                    if (cq == 0) {
                        atomicAdd(&g_sp[gi0], sp0);
                        atomicAdd(&g_sn[gi0], sn0);
                        atomicMin(&g_minpos[gi0], fenc(mn0));
                        atomicMax(&g_maxneg[gi0], fenc(mx0));
                        atomicAdd(&g_sp[gi1], sp1);
                        atomicAdd(&g_sn[gi1], sn1);
                        atomicMin(&g_minpos[gi1], fenc(mn1));
                        atomicMax(&g_maxneg[gi1], fenc(mx1));
                    }
                }
                if (offdiag) {
#pragma unroll
                    for (int nt = 0; nt < 4; ++nt)
#pragma unroll
                        for (int h = 0; h < 2; ++h) {
#pragma unroll
                            for (int o = 4; o < 32; o <<= 1) {
                                csp[nt][h] += __shfl_xor_sync(0xffffffffu, csp[nt][h], o);
                                csn[nt][h] += __shfl_xor_sync(0xffffffffu, csn[nt][h], o);
                                cmnP[nt][h] = fminf(cmnP[nt][h],
                                                    __shfl_xor_sync(0xffffffffu, cmnP[nt][h], o));
                                cmxN[nt][h] = fmaxf(cmxN[nt][h],
                                                    __shfl_xor_sync(0xffffffffu, cmxN[nt][h], o));
                            }
                        }
                    if (r4 == 0) {
#pragma unroll
                        for (int nt = 0; nt < 4; ++nt) {
                            const int gj = j0 + wn * 32 + nt * 8 + 2 * cq;
                            atomicAdd(&g_sp[gj], csp[nt][0]);
                            atomicAdd(&g_sn[gj], csn[nt][0]);
                            atomicMin(&g_minpos[gj], fenc(cmnP[nt][0]));
                            atomicMax(&g_maxneg[gj], fenc(cmxN[nt][0]));
                            atomicAdd(&g_sp[gj + 1], csp[nt][1]);
                            atomicAdd(&g_sn[gj + 1], csn[nt][1]);
                            atomicMin(&g_minpos[gj + 1], fenc(cmnP[nt][1]));
                            atomicMax(&g_maxneg[gj + 1], fenc(cmxN[nt][1]));
                        }
                    }
                }
#pragma unroll
                for (int o = 16; o > 0; o >>= 1) {
                    gmx = fmaxf(gmx, __shfl_xor_sync(0xffffffffu, gmx, o));
                    gmn = fminf(gmn, __shfl_xor_sync(0xffffffffu, gmn, o));
                }
                if (lane == 0) { sredA[warp] = gmx; sredB[warp] = gmn; }
            }
            __syncthreads();
            if (t == 0) {
                float a = sredA[0], bb = sredB[0];
#pragma unroll
                for (int w = 1; w < 8; ++w) { a = fmaxf(a, sredA[w]); bb = fminf(bb, sredB[w]); }
                atomicMax(&g_gmaxpos, fenc(a));
                atomicMin(&g_gminneg, fenc(bb));
            }
        }
    }
    gsync(3u * GRID);

    // ---- phase F-C: per-row check ----
    {
        const float gmaxP = fdec(g_gmaxpos);
        const float gminN = fdec(g_gminneg);
        for (int r = b * 512 + t; r < B_SZ; r += GRID * 512) {
            const float minpos = fdec(g_minpos[r]);
            const float maxneg = fdec(g_maxneg[r]);
            const bool okP = (gmaxP - MARGIN < maxneg);
            const bool okN = (gminN + MARGIN > minpos);
            if (okP && okN) {
                float loss = 0.f;
                float sp = g_sp[r], sn = g_sn[r];
                if (sp > 0.f && sn > 0.f) {
                    const float E1 = 2.718281828459045f;
                    const float EINV = 0.36787944117144233f;
                    loss = 0.5f * log1pf(E1 * sp) + 0.5f * log1pf(EINV * sn);
                }
                g_rowloss[r] = loss;
            } else {
                g_rowloss[r] = 0.f;
                int idx = atomicAdd(&g_nfix, 1);
                g_fixlist[idx] = r;
            }
        }
    }
    gsync(4u * GRID);

    // ---- phase F-D: exact fixup for flagged rows ----
    {
        float* fr = reinterpret_cast<float*>(dsm);            // 512 floats
        float* redp = fr + D_SZ;                               // 512
        float* redn = redp + 512;                              // 512
        const int n = g_nfix;
        for (int w = b; w < n; w += GRID) {
            const int r = g_fixlist[w];
            if (t < D_SZ) fr[t] = __bfloat162float(g_fbf[(size_t)r * D_SZ + t]);
            __syncthreads();
            const float inv = invE;
            const float minpos = fdec(g_minpos[r]);
            const float maxneg = fdec(g_maxneg[r]);
            const int lr = labels[r];
            const float ONE_EPS = 1.0f - 1e-5f;
            float sp = 0.f, sn = 0.f;
            for (int j = t; j < B_SZ; j += 512) {
                const __nv_bfloat162* fj =
                    reinterpret_cast<const __nv_bfloat162*>(g_fbf + (size_t)j * D_SZ);
                float d = 0.f;
                for (int k = 0; k < D_SZ / 2; ++k) {
                    float2 v = __bfloat1622float2(fj[k]);
                    d = fmaf(fr[2 * k], v.x, d);
                    d = fmaf(fr[2 * k + 1], v.y, d);
                }
                float s = d * inv;
                if (labels[j] == lr) {
                    if (s < ONE_EPS && (s - MARGIN < maxneg)) sp += __expf(-2.f * (s - 0.5f));
                } else if (s + MARGIN > minpos) {
                    sn += __expf(2.f * (s - 0.5f));
                }
            }
            redp[t] = sp;
            redn[t] = sn;
            __syncthreads();
            for (int o = 256; o > 0; o >>= 1) {
                if (t < o) { redp[t] += redp[t + o]; redn[t] += redn[t + o]; }
                __syncthreads();
            }
            if (t == 0) {
                float loss = 0.f;
                if (redp[0] > 0.f && redn[0] > 0.f)
                    loss = 0.5f * log1pf(redp[0]) + 0.5f * log1pf(redn[0]);
                g_rowloss[r] = loss;
            }
            __syncthreads();
        }
    }
    gsync(5u * GRID);

    // ---- phase F-E: final reduction (block 0), then reset barrier ----
    if (b == 0) {
        float* red = reinterpret_cast<float*>(dsm);
        float s = 0.f;
        for (int i = t; i < B_SZ; i += 512) s += g_rowloss[i];
        red[t] = s;
        __syncthreads();
        for (int o = 256; o > 0; o >>= 1) {
            if (t < o) red[t] += red[t + o];
            __syncthreads();
        }
        if (t == 0) out[0] = red[0] * (1.0f / B_SZ);
    }
    __syncthreads();
    __threadfence();
    if (t == 0) {
        atomicAdd(&g_fbar, 1u);
        if (b == 0) {
            while (*(volatile unsigned*)&g_fbar < 6u * GRID) { }
            g_fbar = 0u;
        }
    }
}

// ================= launch =================
extern "C" void kernel_launch(void* const* d_in, const int* in_sizes, int n_in,
                              void* d_out, int out_size) {
    const float* feats = (const float*)d_in[0];
    const int* labels = (const int*)d_in[1];
    (void)in_sizes; (void)n_in; (void)out_size;

    static int once = 0;
    if (!once) {
        cudaFuncSetAttribute(k_all, cudaFuncAttributeMaxDynamicSharedMemorySize, SMEM_BYTES);
        once = 1;
    }

    k_all<<<GRID, 512, SMEM_BYTES>>>(feats, labels, (float*)d_out);
}